// round 7
// baseline (speedup 1.0000x reference)
#include <cuda_runtime.h>
#include <cuda_fp16.h>
#include <cstdint>
#include <math.h>

#define NN 100000
#define EE 600000
#define GG 64
#define HH 128
#define STEPS 4
#define N2 (2 * NN)              // combined nodes
#define E2 (2 * EE)              // combined edges
#define NB2 391                  // ceil(N2/512)
#define TILE 32768               // fp16 128x128 tile bytes
#define MT 782                   // ceil(NN/128)
#define NT2 1563                 // ceil(N2/128)

// ---------------- scratch (device globals; allocation-free) ----------------
__device__ __align__(256) float  d_h   [(size_t)N2 * HH];   // node hidden fp32
__device__ __align__(256) __half d_ym0 [(size_t)N2 * HH];   // messages ping
__device__ __align__(256) __half d_ym1 [(size_t)N2 * HH];   // messages pong
// Pre-swizzled fp16 weight tiles, 32KB each:
//  t0..3 : W_s ; t4..6 : Whh r,z,n ; t7..9 : Wih r,z,n ; t10,11 : emb b,v
__device__ __align__(256) char  d_img[12 * TILE];
__device__ __align__(256) float d_pool[2 * GG * HH];
__device__ __align__(256) float d_cnt [2 * GG];
// CSR scratch (d_ecnt: zero at launch entry; re-zeroed by k_scan each run)
__device__ int d_ecnt[N2];
__device__ int d_ecur[N2];
__device__ int d_eoff[N2 + 1];
__device__ int d_eidx[E2];

// ---------------- helpers ---------------------------------------------------
__device__ __forceinline__ uint32_t smem_u32(const void* p) {
    uint32_t a;
    asm("{ .reg .u64 t; cvta.to.shared.u64 t, %1; cvt.u32.u64 %0, t; }" : "=r"(a) : "l"(p));
    return a;
}
__host__ __device__ __forceinline__ uint32_t swz(int row, int k) {
    return (uint32_t)(row * 256 + ((((k >> 3) ^ (row & 7)) << 4) | ((k & 7) << 1)));
}
__device__ __forceinline__ float tanh_ap(float x) {
    float y;
    asm("tanh.approx.f32 %0, %1;" : "=f"(y) : "f"(x));
    return y;
}
__device__ __forceinline__ float sigm(float x) {
    return fmaf(tanh_ap(x * 0.5f), 0.5f, 0.5f);
}

#define LDSM4(R0, R1, R2, R3, ADDR) \
    asm volatile("ldmatrix.sync.aligned.m8n8.x4.shared.b16 {%0,%1,%2,%3}, [%4];" \
                 : "=r"(R0), "=r"(R1), "=r"(R2), "=r"(R3) : "r"(ADDR))

#define MMA16816(D, A0, A1, A2, A3, B0, B1) \
    asm volatile("mma.sync.aligned.m16n8k16.row.col.f32.f16.f16.f32 " \
                 "{%0,%1,%2,%3}, {%4,%5,%6,%7}, {%8,%9}, {%0,%1,%2,%3};" \
                 : "+f"((D)[0]), "+f"((D)[1]), "+f"((D)[2]), "+f"((D)[3]) \
                 : "r"(A0), "r"(A1), "r"(A2), "r"(A3), "r"(B0), "r"(B1))

// cp.async a 32KB tile (all 256 threads), one commit group
__device__ __forceinline__ void cp_tile(uint32_t dst, const char* __restrict__ src, int tid) {
#pragma unroll
    for (int i = 0; i < 8; i++) {
        uint32_t d = dst + tid * 16 + i * 4096;
        const char* s = src + tid * 16 + i * 4096;
        asm volatile("cp.async.cg.shared.global [%0], [%1], 16;" :: "r"(d), "l"(s));
    }
    asm volatile("cp.async.commit_group;");
}
#define CP_WAIT(n) asm volatile("cp.async.wait_group %0;" :: "n"(n))

// one 128x128x128 fp16 MMA pass accumulating into acc
__device__ __forceinline__ void mma_pass(uint32_t sA, uint32_t sB,
                                         int arow, int akl, int brow, int bkl,
                                         float (&acc)[2][8][4])
{
#pragma unroll
    for (int ks = 0; ks < 8; ks++) {
        const int kk = ks * 16;
        uint32_t a0[4], a1[4];
        LDSM4(a0[0], a0[1], a0[2], a0[3], sA + swz(arow,      kk + akl));
        LDSM4(a1[0], a1[1], a1[2], a1[3], sA + swz(arow + 16, kk + akl));
#pragma unroll
        for (int nb = 0; nb < 4; nb++) {
            uint32_t bh[4];
            LDSM4(bh[0], bh[1], bh[2], bh[3], sB + swz(brow + nb * 16, kk + bkl));
            int j0 = nb * 2;
            MMA16816(acc[0][j0],     a0[0], a0[1], a0[2], a0[3], bh[0], bh[1]);
            MMA16816(acc[1][j0],     a1[0], a1[1], a1[2], a1[3], bh[0], bh[1]);
            MMA16816(acc[0][j0 + 1], a0[0], a0[1], a0[2], a0[3], bh[2], bh[3]);
            MMA16816(acc[1][j0 + 1], a1[0], a1[1], a1[2], a1[3], bh[2], bh[3]);
        }
    }
}

__device__ __forceinline__ void zero_acc(float (&acc)[2][8][4]) {
#pragma unroll
    for (int i = 0; i < 2; i++)
#pragma unroll
        for (int j = 0; j < 8; j++)
#pragma unroll
            for (int q = 0; q < 4; q++) acc[i][j][q] = 0.f;
}

// stage fp32 A[rows at row0.., Kin<=128] -> fp16 swizzled smem tile
__device__ __forceinline__ void stage_A(const float* __restrict__ A, int Kin, int Mlim,
                                        int row0, char* dst, int tid)
{
    int r = tid >> 1;
    int hf = tid & 1;
    int row = row0 + r;
    bool valid = row < Mlim;
    const float* ap = A + (size_t)row * Kin;
#pragma unroll
    for (int i = 0; i < 8; i++) {
        int k0 = hf * 64 + i * 8;
        float v[8];
        if (Kin == 128) {
            float4 f0 = valid ? *reinterpret_cast<const float4*>(ap + k0)
                              : make_float4(0.f, 0.f, 0.f, 0.f);
            float4 f1 = valid ? *reinterpret_cast<const float4*>(ap + k0 + 4)
                              : make_float4(0.f, 0.f, 0.f, 0.f);
            v[0] = f0.x; v[1] = f0.y; v[2] = f0.z; v[3] = f0.w;
            v[4] = f1.x; v[5] = f1.y; v[6] = f1.z; v[7] = f1.w;
        } else {
#pragma unroll
            for (int q = 0; q < 8; q++) {
                int k = k0 + q;
                v[q] = (valid && k < Kin) ? ap[k] : 0.f;
            }
        }
        uint32_t p[4];
#pragma unroll
        for (int q = 0; q < 4; q++) {
            __half2 h2 = __floats2half2_rn(v[2 * q], v[2 * q + 1]);
            p[q] = *reinterpret_cast<uint32_t*>(&h2);
        }
        *reinterpret_cast<uint4*>(dst + swz(r, k0)) = make_uint4(p[0], p[1], p[2], p[3]);
    }
}

__device__ __forceinline__ void acc_row(float4& s, const __half* __restrict__ p) {
    uint2 v = *reinterpret_cast<const uint2*>(p);
    float2 a = __half22float2(*reinterpret_cast<__half2*>(&v.x));
    float2 b = __half22float2(*reinterpret_cast<__half2*>(&v.y));
    s.x += a.x; s.y += a.y; s.z += b.x; s.w += b.y;
}

// ---------------- prep: fp16 weight tiles + zero pool/cnt -------------------
__global__ void vspn_prep(const float* __restrict__ ggc,   // [4,128,128]
                          const float* __restrict__ wih,   // [384,128]
                          const float* __restrict__ whh,   // [384,128]
                          const float* __restrict__ wembB, // [FB,128]
                          const float* __restrict__ wembV, // [FV,128]
                          int FB, int FV)
{
    int idx = blockIdx.x * blockDim.x + threadIdx.x;
    if (idx < 2 * GG * HH) d_pool[idx] = 0.f;
    if (idx < 2 * GG) d_cnt[idx] = 0.f;
    if (idx >= 12 * 16384) return;
    int t = idx / 16384;
    int e = idx % 16384;
    int n = e >> 7;
    int k = e & 127;
    float v = 0.f;
    if (t < 4) {
        v = ggc[(t * 128 + k) * 128 + n];
    } else if (t < 7) {
        int g = t - 4;
        v = whh[(size_t)(g * 128 + n) * 128 + k];
    } else if (t < 10) {
        int g = t - 7;
        v = wih[(size_t)(g * 128 + n) * 128 + k];
    } else if (t == 10) {
        v = (k < FB) ? wembB[(size_t)k * 128 + n] : 0.f;
    } else {
        v = (k < FV) ? wembV[(size_t)k * 128 + n] : 0.f;
    }
    *(__half*)(d_img + (size_t)t * TILE + swz(n, k)) = __float2half_rn(v);
}

// ---------------- CSR build (combined graph) --------------------------------
__global__ void k_hist(const int* __restrict__ eb, const int* __restrict__ ev) {
    int e = blockIdx.x * blockDim.x + threadIdx.x;
    if (e < EE)       atomicAdd(&d_ecnt[eb[EE + e]], 1);
    else if (e < E2)  atomicAdd(&d_ecnt[NN + ev[EE + (e - EE)]], 1);
}
// fused scan: per block computes its base by summing preceding counts,
// then intra-block scan; also resets d_ecnt to zero for next replay.
__global__ void k_scan() {
    __shared__ int sh[512];
    int t = threadIdx.x, bid = blockIdx.x;
    int i = bid * 512 + t;
    int base = 0;
    for (int j = t; j < bid * 512; j += 512) base += d_ecnt[j];
    sh[t] = base;
    __syncthreads();
    for (int s = 256; s > 0; s >>= 1) {
        if (t < s) sh[t] += sh[t + s];
        __syncthreads();
    }
    base = sh[0];
    __syncthreads();
    int v = (i < N2) ? d_ecnt[i] : 0;
    sh[t] = v;
    __syncthreads();
    for (int off = 1; off < 512; off <<= 1) {
        int x = (t >= off) ? sh[t - off] : 0;
        __syncthreads();
        sh[t] += x;
        __syncthreads();
    }
    if (i < N2) {
        int excl = base + sh[t] - v;
        d_eoff[i] = excl;
        d_ecur[i] = excl;
        if (i == N2 - 1) d_eoff[N2] = excl + v;
        d_ecnt[i] = 0;   // maintain zero-at-entry invariant
    }
}
__global__ void k_fill(const int* __restrict__ eb, const int* __restrict__ ev) {
    int e = blockIdx.x * blockDim.x + threadIdx.x;
    if (e >= E2) return;
    int src, dst;
    if (e < EE) { src = eb[e];             dst = eb[EE + e]; }
    else        { src = NN + ev[e - EE];   dst = NN + ev[EE + (e - EE)]; }
    int p = atomicAdd(&d_ecur[dst], 1);
    d_eidx[p] = src;
}

// ---------------- embed: h = relu(x@Wemb); ym0 = fp16(h@W0) -----------------
#define SM_EMB (3 * TILE)
__global__ void __launch_bounds__(256, 1)
vspn_emb(const float* __restrict__ x_b, const float* __restrict__ x_v,
         int FB, int FV,
         float* __restrict__ h, __half* __restrict__ ym)
{
    extern __shared__ char smem[];
    const int tid = threadIdx.x, lane = tid & 31, wid = tid >> 5;
    const int wr = wid & 3, wc = wid >> 2;
    const int arow = wr * 32 + (lane & 15), akl = (lane >> 4) << 3;
    const int brow = wc * 64 + ((lane >> 4) << 3) + (lane & 7), bkl = ((lane >> 3) & 1) << 3;
    const int rl0 = wr * 32 + (lane >> 2);
    const int cb  = wc * 64 + (lane & 3) * 2;

    const int gb = (blockIdx.x >= MT) ? 1 : 0;
    const int row0_local = (blockIdx.x - gb * MT) * 128;    // row in x
    const int node0 = gb * NN + row0_local;                 // global node
    const float* x = gb ? x_v : x_b;
    const int Kin  = gb ? FV : FB;
    const char* imgE = d_img + (size_t)(10 + gb) * TILE;
    const char* imgM = d_img;   // W_s step 0

    uint32_t sA = smem_u32(smem), sB0 = sA + TILE, sB1 = sA + 2 * TILE;
    cp_tile(sB0, imgE, tid);
    cp_tile(sB1, imgM, tid);
    stage_A(x, Kin, NN, row0_local, smem, tid);
    CP_WAIT(1);
    __syncthreads();

    float acc[2][8][4];
    zero_acc(acc);
    mma_pass(sA, sB0, arow, akl, brow, bkl, acc);
    __syncthreads();   // A consumed

    // h = relu(acc): write gmem + restage fp16 into A slot
#pragma unroll
    for (int i = 0; i < 2; i++)
#pragma unroll
        for (int rr = 0; rr < 2; rr++) {
            int rl = rl0 + i * 16 + rr * 8;
            bool valid = (row0_local + rl) < NN;
            int node = node0 + rl;
#pragma unroll
            for (int j = 0; j < 8; j++) {
                int c = cb + j * 8;
                float v0 = fmaxf(acc[i][j][rr * 2], 0.f);
                float v1 = fmaxf(acc[i][j][rr * 2 + 1], 0.f);
                if (valid)
                    *reinterpret_cast<float2*>(h + (size_t)node * 128 + c) = make_float2(v0, v1);
                __half2 h2 = __floats2half2_rn(v0, v1);
                *reinterpret_cast<uint32_t*>(smem + swz(rl, c)) = *reinterpret_cast<uint32_t*>(&h2);
            }
        }
    CP_WAIT(0);
    __syncthreads();
    zero_acc(acc);
    mma_pass(sA, sB1, arow, akl, brow, bkl, acc);
#pragma unroll
    for (int i = 0; i < 2; i++)
#pragma unroll
        for (int rr = 0; rr < 2; rr++) {
            int rl = rl0 + i * 16 + rr * 8;
            if (row0_local + rl >= NN) continue;
            int node = node0 + rl;
#pragma unroll
            for (int j = 0; j < 8; j++) {
                int c = cb + j * 8;
                __half2 h2 = __floats2half2_rn(acc[i][j][rr * 2], acc[i][j][rr * 2 + 1]);
                *reinterpret_cast<uint32_t*>(ym + (size_t)node * 128 + c) =
                    *reinterpret_cast<uint32_t*>(&h2);
            }
        }
}

// ---------- fused step: gather + GRU(h, agg) -> h ; ym_out = h@W_next -------
// ym_in and ym_out are DIFFERENT buffers (ping-pong) — avoids cross-CTA race.
// smem: sA(agg) | sAh(h) | B0 | B1 | B2 | B3  = 6 * 32KB = 192KB
#define SM_STEP (6 * TILE)
__global__ void __launch_bounds__(256, 1)
vspn_step(float* __restrict__ h, const __half* __restrict__ ym_in,
          __half* __restrict__ ym_out, int mstep,
          const float* __restrict__ bih, const float* __restrict__ bhh)
{
    extern __shared__ char smem[];
    const int tid = threadIdx.x, lane = tid & 31, wid = tid >> 5;
    const int wr = wid & 3, wc = wid >> 2;
    const int arow = wr * 32 + (lane & 15), akl = (lane >> 4) << 3;
    const int brow = wc * 64 + ((lane >> 4) << 3) + (lane & 7), bkl = ((lane >> 3) & 1) << 3;
    const int rl0 = wr * 32 + (lane >> 2);
    const int cb  = wc * 64 + (lane & 3) * 2;
    const int node0 = blockIdx.x * 128;

    uint32_t sA  = smem_u32(smem);
    uint32_t sAh = sA + TILE;
    uint32_t sB0 = sA + 2 * TILE;
    uint32_t sB1 = sA + 3 * TILE;
    uint32_t sB2 = sA + 4 * TILE;
    uint32_t sB3 = sA + 5 * TILE;

    cp_tile(sB0, d_img + 4 * TILE, tid);   // g0: Whh_r
    cp_tile(sB1, d_img + 7 * TILE, tid);   // g1: Wih_r
    cp_tile(sB2, d_img + 6 * TILE, tid);   // g2: Whh_n
    cp_tile(sB3, d_img + 9 * TILE, tid);   // g3: Wih_n

    stage_A(h, 128, N2, node0, smem + TILE, tid);

    // ---- in-CTA gather: sA[rl,:] = sum over CSR(node0+rl) of ym_in[src] ----
    {
        const int lane4 = lane * 4;
#pragma unroll 1
        for (int i = 0; i < 16; i++) {
            int rl = wid * 16 + i;
            int n = node0 + rl;
            float4 s0 = make_float4(0.f, 0.f, 0.f, 0.f), s1 = s0, s2 = s0, s3 = s0;
            if (n < N2) {
                int e0 = d_eoff[n], e1 = d_eoff[n + 1];
                int e = e0;
                for (; e + 4 <= e1; e += 4) {
                    int p0 = d_eidx[e], p1 = d_eidx[e + 1];
                    int p2 = d_eidx[e + 2], p3 = d_eidx[e + 3];
                    acc_row(s0, ym_in + (size_t)p0 * 128 + lane4);
                    acc_row(s1, ym_in + (size_t)p1 * 128 + lane4);
                    acc_row(s2, ym_in + (size_t)p2 * 128 + lane4);
                    acc_row(s3, ym_in + (size_t)p3 * 128 + lane4);
                }
                for (; e < e1; e++)
                    acc_row(s0, ym_in + (size_t)d_eidx[e] * 128 + lane4);
            }
            s0.x += s1.x + s2.x + s3.x;
            s0.y += s1.y + s2.y + s3.y;
            s0.z += s1.z + s2.z + s3.z;
            s0.w += s1.w + s2.w + s3.w;
            __half2 h0 = __floats2half2_rn(s0.x, s0.y);
            __half2 h1 = __floats2half2_rn(s0.z, s0.w);
            uint2 pk;
            pk.x = *reinterpret_cast<uint32_t*>(&h0);
            pk.y = *reinterpret_cast<uint32_t*>(&h1);
            *reinterpret_cast<uint2*>(smem + swz(rl, lane4)) = pk;
        }
    }

    float acc[2][8][4], rg[2][8][4], ng[2][8][4];

    // ---- P0: gh_r ----
    CP_WAIT(3);
    __syncthreads();
    zero_acc(acc);
    mma_pass(sAh, sB0, arow, akl, brow, bkl, acc);
    __syncthreads();
    cp_tile(sB0, d_img + 5 * TILE, tid);   // g4: Whh_z
    // ---- P1: + gi_r -> r ----
    CP_WAIT(3);
    __syncthreads();
    mma_pass(sA, sB1, arow, akl, brow, bkl, acc);
#pragma unroll
    for (int i = 0; i < 2; i++)
#pragma unroll
        for (int j = 0; j < 8; j++) {
            int c = cb + j * 8;
            float2 b1 = *reinterpret_cast<const float2*>(bih + c);
            float2 b2 = *reinterpret_cast<const float2*>(bhh + c);
#pragma unroll
            for (int rr = 0; rr < 2; rr++) {
                rg[i][j][rr * 2]     = sigm(acc[i][j][rr * 2]     + b1.x + b2.x);
                rg[i][j][rr * 2 + 1] = sigm(acc[i][j][rr * 2 + 1] + b1.y + b2.y);
            }
        }
    __syncthreads();
    cp_tile(sB1, d_img + 8 * TILE, tid);   // g5: Wih_z
    // ---- P2: gh_n ----
    CP_WAIT(3);
    __syncthreads();
    zero_acc(acc);
    mma_pass(sAh, sB2, arow, akl, brow, bkl, acc);
#pragma unroll
    for (int i = 0; i < 2; i++)
#pragma unroll
        for (int j = 0; j < 8; j++) {
            int c = cb + j * 8;
            float2 b1 = *reinterpret_cast<const float2*>(bih + 256 + c);
            float2 b2 = *reinterpret_cast<const float2*>(bhh + 256 + c);
#pragma unroll
            for (int rr = 0; rr < 2; rr++) {
                acc[i][j][rr * 2]     = rg[i][j][rr * 2]     * (acc[i][j][rr * 2]     + b2.x) + b1.x;
                acc[i][j][rr * 2 + 1] = rg[i][j][rr * 2 + 1] * (acc[i][j][rr * 2 + 1] + b2.y) + b1.y;
            }
        }
    __syncthreads();
    // g6: next-step message weights (dummy t0 when mstep<0 to keep counts uniform)
    cp_tile(sB2, d_img + (size_t)((mstep >= 0) ? mstep : 0) * TILE, tid);
    // ---- P3: + gi_n -> n ----
    CP_WAIT(3);
    __syncthreads();
    mma_pass(sA, sB3, arow, akl, brow, bkl, acc);
#pragma unroll
    for (int i = 0; i < 2; i++)
#pragma unroll
        for (int j = 0; j < 8; j++)
#pragma unroll
            for (int q = 0; q < 4; q++) ng[i][j][q] = tanh_ap(acc[i][j][q]);
    // ---- P4: gh_z ----
    CP_WAIT(2);
    __syncthreads();
    zero_acc(acc);
    mma_pass(sAh, sB0, arow, akl, brow, bkl, acc);
    // ---- P5: + gi_z -> z ; combine; restage h_new into sA ----
    CP_WAIT(1);
    __syncthreads();
    mma_pass(sA, sB1, arow, akl, brow, bkl, acc);
    __syncthreads();   // all warps done reading sA
#pragma unroll
    for (int i = 0; i < 2; i++)
#pragma unroll
        for (int rr = 0; rr < 2; rr++) {
            int rl = rl0 + i * 16 + rr * 8;
            int node = node0 + rl;
            bool valid = node < N2;
#pragma unroll
            for (int j = 0; j < 8; j++) {
                int c = cb + j * 8;
                float2 b1 = *reinterpret_cast<const float2*>(bih + 128 + c);
                float2 b2 = *reinterpret_cast<const float2*>(bhh + 128 + c);
                float z0 = sigm(acc[i][j][rr * 2]     + b1.x + b2.x);
                float z1 = sigm(acc[i][j][rr * 2 + 1] + b1.y + b2.y);
                float2 hp = valid ? *reinterpret_cast<const float2*>(h + (size_t)node * 128 + c)
                                  : make_float2(0.f, 0.f);
                float h0 = (1.f - z0) * ng[i][j][rr * 2]     + z0 * hp.x;
                float h1 = (1.f - z1) * ng[i][j][rr * 2 + 1] + z1 * hp.y;
                if (valid)
                    *reinterpret_cast<float2*>(h + (size_t)node * 128 + c) = make_float2(h0, h1);
                __half2 hh = __floats2half2_rn(h0, h1);
                *reinterpret_cast<uint32_t*>(smem + swz(rl, c)) = *reinterpret_cast<uint32_t*>(&hh);
            }
        }

    // ---- P6: ym_out = fp16(h_new @ W[mstep]) ----
    if (mstep >= 0) {
        CP_WAIT(0);
        __syncthreads();
        zero_acc(acc);
        mma_pass(sA, sB2, arow, akl, brow, bkl, acc);
#pragma unroll
        for (int i = 0; i < 2; i++)
#pragma unroll
            for (int rr = 0; rr < 2; rr++) {
                int node = node0 + rl0 + i * 16 + rr * 8;
                if (node >= N2) continue;
#pragma unroll
                for (int j = 0; j < 8; j++) {
                    int c = cb + j * 8;
                    __half2 h2 = __floats2half2_rn(acc[i][j][rr * 2], acc[i][j][rr * 2 + 1]);
                    *reinterpret_cast<uint32_t*>(ym_out + (size_t)node * 128 + c) =
                        *reinterpret_cast<uint32_t*>(&h2);
                }
            }
    }
}

// ---------------- pool: combined 128 pools over 200k nodes ------------------
__global__ void vspn_pool(const float* __restrict__ h,
                          const int* __restrict__ bat_b, const int* __restrict__ bat_v)
{
    __shared__ int sbh[128];
    int j  = threadIdx.x;
    int n0 = blockIdx.x * 128;
    int nend = min(n0 + 128, N2);
    int cn = nend - n0;
    {
        int n = n0 + j;
        if (n < N2) sbh[j] = (n < NN) ? bat_b[n] : (GG + bat_v[n - NN]);
    }
    __syncthreads();
    float sum = 0.f, rc = 0.f;
    int cur = sbh[0];
    for (int t = 0; t < cn; t++) {
        int b = sbh[t];
        if (b != cur) {
            atomicAdd(&d_pool[(size_t)cur * HH + j], sum);
            if (j == 0) atomicAdd(&d_cnt[cur], rc);
            sum = 0.f; rc = 0.f; cur = b;
        }
        sum += fmaxf(h[(size_t)(n0 + t) * HH + j], 0.f);
        rc += 1.f;
    }
    atomicAdd(&d_pool[(size_t)cur * HH + j], sum);
    if (j == 0) atomicAdd(&d_cnt[cur], rc);
}

// ---------------- head ------------------------------------------------------
__global__ void vspn_head(const float* __restrict__ W1, const float* __restrict__ b1,
                          const float* __restrict__ W2, const float* __restrict__ b2,
                          float* __restrict__ out)
{
    int g = blockIdx.x;
    int k = threadIdx.x;
    __shared__ float gsh[256];
    __shared__ float tsh[256];
    float cb = fmaxf(d_cnt[g], 1.f);
    float cv = fmaxf(d_cnt[GG + g], 1.f);
    if (k < HH) gsh[k] = d_pool[(size_t)g * HH + k] / cb;
    else        gsh[k] = d_pool[(size_t)(GG + g) * HH + (k - HH)] / cv;
    __syncthreads();
    float acc = b1[k];
    for (int j = 0; j < 256; j++) acc += gsh[j] * W1[j * 256 + k];
    float t = fmaxf(acc, 0.f);
    tsh[k] = t * W2[k];
    __syncthreads();
    for (int s = 128; s > 0; s >>= 1) {
        if (k < s) tsh[k] += tsh[k + s];
        __syncthreads();
    }
    if (k == 0) {
        float x = tsh[0] + b2[0];
        out[g] = fmaxf(x, 0.f) + log1pf(expf(-fabsf(x)));
    }
}

// ---------------- launch ----------------------------------------------------
extern "C" void kernel_launch(void* const* d_in, const int* in_sizes, int n_in,
                              void* d_out, int out_size)
{
    const float* x_b   = (const float*)d_in[0];
    const int*   ei_b  = (const int*)  d_in[1];
    const int*   bat_b = (const int*)  d_in[2];
    const float* x_v   = (const float*)d_in[3];
    const int*   ei_v  = (const int*)  d_in[4];
    const int*   bat_v = (const int*)  d_in[5];
    const float* Wemb_b= (const float*)d_in[6];
    const float* Wemb_v= (const float*)d_in[7];
    const float* ggc   = (const float*)d_in[8];
    const float* w_ih  = (const float*)d_in[9];
    const float* w_hh  = (const float*)d_in[10];
    const float* b_ih  = (const float*)d_in[11];
    const float* b_hh  = (const float*)d_in[12];
    const float* W1    = (const float*)d_in[13];
    const float* b1    = (const float*)d_in[14];
    const float* W2    = (const float*)d_in[15];
    const float* b2    = (const float*)d_in[16];
    float* out = (float*)d_out;

    const int FB = in_sizes[0] / NN;
    const int FV = in_sizes[3] / NN;

    float* p_h;
    __half *p_ym0, *p_ym1;
    cudaGetSymbolAddress((void**)&p_h,   d_h);
    cudaGetSymbolAddress((void**)&p_ym0, d_ym0);
    cudaGetSymbolAddress((void**)&p_ym1, d_ym1);

    cudaFuncSetAttribute(vspn_emb,  cudaFuncAttributeMaxDynamicSharedMemorySize, SM_EMB);
    cudaFuncSetAttribute(vspn_step, cudaFuncAttributeMaxDynamicSharedMemorySize, SM_STEP);

    // 0: weights + zero pool/cnt
    vspn_prep<<<(12 * 16384 + 255) / 256, 256>>>(ggc, w_ih, w_hh, Wemb_b, Wemb_v, FB, FV);
    // 1: embed both graphs (also produces step-0 messages into ym0)
    vspn_emb<<<2 * MT, 256, SM_EMB>>>(x_b, x_v, FB, FV, p_h, p_ym0);
    // 2-4: CSR build for combined graph (d_ecnt zero at entry; k_scan re-zeroes)
    k_hist<<<(E2 + 255) / 256, 256>>>(ei_b, ei_v);
    k_scan<<<NB2, 512>>>();
    k_fill<<<(E2 + 255) / 256, 256>>>(ei_b, ei_v);
    // 5-8: fused gather + GRU + next messages (ping-pong message buffers)
    for (int s = 0; s < STEPS; s++) {
        int mstep = (s < STEPS - 1) ? (s + 1) : -1;
        __half* ym_in  = (s & 1) ? p_ym1 : p_ym0;
        __half* ym_out = (s & 1) ? p_ym0 : p_ym1;
        vspn_step<<<NT2, 256, SM_STEP>>>(p_h, ym_in, ym_out, mstep, b_ih, b_hh);
    }
    // 9: mean-pool both graphs
    vspn_pool<<<NT2, 128>>>(p_h, bat_b, bat_v);
    // 10: head
    vspn_head<<<GG, 256>>>(W1, b1, W2, b2, out);
}

// round 8
// speedup vs baseline: 1.5471x; 1.5471x over previous
#include <cuda_runtime.h>
#include <cuda_fp16.h>
#include <cstdint>
#include <math.h>

#define NN 100000
#define EE 600000
#define GG 64
#define HH 128
#define STEPS 4
#define N2 (2 * NN)              // combined nodes
#define E2 (2 * EE)              // combined edges
#define NB2 391                  // ceil(N2/512)
#define TILE 32768               // fp16 128x128 tile bytes
#define MT 782                   // ceil(NN/128)
#define NT2 1563                 // ceil(N2/128)

// ---------------- scratch (device globals; allocation-free) ----------------
__device__ __align__(256) float  d_h  [(size_t)N2 * HH];   // node hidden fp32
__device__ __align__(256) __half d_ym [(size_t)N2 * HH];   // messages fp16
__device__ __align__(256) float  d_agg[(size_t)N2 * HH];   // gathered messages
// Pre-swizzled fp16 weight tiles, 32KB each:
//  t0..3 : W_s ; t4..6 : Whh r,z,n ; t7..9 : Wih r,z,n ; t10,11 : emb b,v
__device__ __align__(256) char  d_img[12 * TILE];
__device__ __align__(256) float d_pool[2 * GG * HH];
__device__ __align__(256) float d_cnt [2 * GG];
// CSR scratch (d_ecnt: zero at launch entry; re-zeroed by k_scan each run)
__device__ int d_ecnt[N2];
__device__ int d_ecur[N2];
__device__ int d_eoff[N2 + 1];
__device__ int d_eidx[E2];

// ---------------- helpers ---------------------------------------------------
__device__ __forceinline__ uint32_t smem_u32(const void* p) {
    uint32_t a;
    asm("{ .reg .u64 t; cvta.to.shared.u64 t, %1; cvt.u32.u64 %0, t; }" : "=r"(a) : "l"(p));
    return a;
}
__host__ __device__ __forceinline__ uint32_t swz(int row, int k) {
    return (uint32_t)(row * 256 + ((((k >> 3) ^ (row & 7)) << 4) | ((k & 7) << 1)));
}
__device__ __forceinline__ float tanh_ap(float x) {
    float y;
    asm("tanh.approx.f32 %0, %1;" : "=f"(y) : "f"(x));
    return y;
}
__device__ __forceinline__ float sigm(float x) {
    return fmaf(tanh_ap(x * 0.5f), 0.5f, 0.5f);
}

#define LDSM4(R0, R1, R2, R3, ADDR) \
    asm volatile("ldmatrix.sync.aligned.m8n8.x4.shared.b16 {%0,%1,%2,%3}, [%4];" \
                 : "=r"(R0), "=r"(R1), "=r"(R2), "=r"(R3) : "r"(ADDR))

#define MMA16816(D, A0, A1, A2, A3, B0, B1) \
    asm volatile("mma.sync.aligned.m16n8k16.row.col.f32.f16.f16.f32 " \
                 "{%0,%1,%2,%3}, {%4,%5,%6,%7}, {%8,%9}, {%0,%1,%2,%3};" \
                 : "+f"((D)[0]), "+f"((D)[1]), "+f"((D)[2]), "+f"((D)[3]) \
                 : "r"(A0), "r"(A1), "r"(A2), "r"(A3), "r"(B0), "r"(B1))

// cp.async a 32KB tile (all 256 threads), one commit group
__device__ __forceinline__ void cp_tile(uint32_t dst, const char* __restrict__ src, int tid) {
#pragma unroll
    for (int i = 0; i < 8; i++) {
        uint32_t d = dst + tid * 16 + i * 4096;
        const char* s = src + tid * 16 + i * 4096;
        asm volatile("cp.async.cg.shared.global [%0], [%1], 16;" :: "r"(d), "l"(s));
    }
    asm volatile("cp.async.commit_group;");
}
#define CP_WAIT(n) asm volatile("cp.async.wait_group %0;" :: "n"(n))

// one 128x128x128 fp16 MMA pass accumulating into acc
__device__ __forceinline__ void mma_pass(uint32_t sA, uint32_t sB,
                                         int arow, int akl, int brow, int bkl,
                                         float (&acc)[2][8][4])
{
#pragma unroll
    for (int ks = 0; ks < 8; ks++) {
        const int kk = ks * 16;
        uint32_t a0[4], a1[4];
        LDSM4(a0[0], a0[1], a0[2], a0[3], sA + swz(arow,      kk + akl));
        LDSM4(a1[0], a1[1], a1[2], a1[3], sA + swz(arow + 16, kk + akl));
#pragma unroll
        for (int nb = 0; nb < 4; nb++) {
            uint32_t bh[4];
            LDSM4(bh[0], bh[1], bh[2], bh[3], sB + swz(brow + nb * 16, kk + bkl));
            int j0 = nb * 2;
            MMA16816(acc[0][j0],     a0[0], a0[1], a0[2], a0[3], bh[0], bh[1]);
            MMA16816(acc[1][j0],     a1[0], a1[1], a1[2], a1[3], bh[0], bh[1]);
            MMA16816(acc[0][j0 + 1], a0[0], a0[1], a0[2], a0[3], bh[2], bh[3]);
            MMA16816(acc[1][j0 + 1], a1[0], a1[1], a1[2], a1[3], bh[2], bh[3]);
        }
    }
}

__device__ __forceinline__ void zero_acc(float (&acc)[2][8][4]) {
#pragma unroll
    for (int i = 0; i < 2; i++)
#pragma unroll
        for (int j = 0; j < 8; j++)
#pragma unroll
            for (int q = 0; q < 4; q++) acc[i][j][q] = 0.f;
}

// stage fp32 A[rows at row0.., Kin<=128] -> fp16 swizzled smem tile
__device__ __forceinline__ void stage_A(const float* __restrict__ A, int Kin, int Mlim,
                                        int row0, char* dst, int tid)
{
    int r = tid >> 1;
    int hf = tid & 1;
    int row = row0 + r;
    bool valid = row < Mlim;
    const float* ap = A + (size_t)row * Kin;
#pragma unroll
    for (int i = 0; i < 8; i++) {
        int k0 = hf * 64 + i * 8;
        float v[8];
        if (Kin == 128) {
            float4 f0 = valid ? *reinterpret_cast<const float4*>(ap + k0)
                              : make_float4(0.f, 0.f, 0.f, 0.f);
            float4 f1 = valid ? *reinterpret_cast<const float4*>(ap + k0 + 4)
                              : make_float4(0.f, 0.f, 0.f, 0.f);
            v[0] = f0.x; v[1] = f0.y; v[2] = f0.z; v[3] = f0.w;
            v[4] = f1.x; v[5] = f1.y; v[6] = f1.z; v[7] = f1.w;
        } else {
#pragma unroll
            for (int q = 0; q < 8; q++) {
                int k = k0 + q;
                v[q] = (valid && k < Kin) ? ap[k] : 0.f;
            }
        }
        uint32_t p[4];
#pragma unroll
        for (int q = 0; q < 4; q++) {
            __half2 h2 = __floats2half2_rn(v[2 * q], v[2 * q + 1]);
            p[q] = *reinterpret_cast<uint32_t*>(&h2);
        }
        *reinterpret_cast<uint4*>(dst + swz(r, k0)) = make_uint4(p[0], p[1], p[2], p[3]);
    }
}

__device__ __forceinline__ void acc_row(float4& s, const __half* __restrict__ p) {
    uint2 v = *reinterpret_cast<const uint2*>(p);
    float2 a = __half22float2(*reinterpret_cast<__half2*>(&v.x));
    float2 b = __half22float2(*reinterpret_cast<__half2*>(&v.y));
    s.x += a.x; s.y += a.y; s.z += b.x; s.w += b.y;
}

// ---------------- prep: fp16 weight tiles + zero pool/cnt -------------------
__global__ void vspn_prep(const float* __restrict__ ggc,   // [4,128,128]
                          const float* __restrict__ wih,   // [384,128]
                          const float* __restrict__ whh,   // [384,128]
                          const float* __restrict__ wembB, // [FB,128]
                          const float* __restrict__ wembV, // [FV,128]
                          int FB, int FV)
{
    int idx = blockIdx.x * blockDim.x + threadIdx.x;
    if (idx < 2 * GG * HH) d_pool[idx] = 0.f;
    if (idx < 2 * GG) d_cnt[idx] = 0.f;
    if (idx >= 12 * 16384) return;
    int t = idx / 16384;
    int e = idx % 16384;
    int n = e >> 7;
    int k = e & 127;
    float v = 0.f;
    if (t < 4) {
        v = ggc[(t * 128 + k) * 128 + n];
    } else if (t < 7) {
        int g = t - 4;
        v = whh[(size_t)(g * 128 + n) * 128 + k];
    } else if (t < 10) {
        int g = t - 7;
        v = wih[(size_t)(g * 128 + n) * 128 + k];
    } else if (t == 10) {
        v = (k < FB) ? wembB[(size_t)k * 128 + n] : 0.f;
    } else {
        v = (k < FV) ? wembV[(size_t)k * 128 + n] : 0.f;
    }
    *(__half*)(d_img + (size_t)t * TILE + swz(n, k)) = __float2half_rn(v);
}

// ---------------- CSR build (combined graph) --------------------------------
__global__ void k_hist(const int* __restrict__ eb, const int* __restrict__ ev) {
    int e = blockIdx.x * blockDim.x + threadIdx.x;
    if (e < EE)       atomicAdd(&d_ecnt[eb[EE + e]], 1);
    else if (e < E2)  atomicAdd(&d_ecnt[NN + ev[EE + (e - EE)]], 1);
}
// fused scan: per block computes its base by summing preceding counts,
// then intra-block scan; also resets d_ecnt to zero for next replay.
__global__ void k_scan() {
    __shared__ int sh[512];
    int t = threadIdx.x, bid = blockIdx.x;
    int i = bid * 512 + t;
    int base = 0;
    for (int j = t; j < bid * 512; j += 512) base += d_ecnt[j];
    sh[t] = base;
    __syncthreads();
    for (int s = 256; s > 0; s >>= 1) {
        if (t < s) sh[t] += sh[t + s];
        __syncthreads();
    }
    base = sh[0];
    __syncthreads();
    int v = (i < N2) ? d_ecnt[i] : 0;
    sh[t] = v;
    __syncthreads();
    for (int off = 1; off < 512; off <<= 1) {
        int x = (t >= off) ? sh[t - off] : 0;
        __syncthreads();
        sh[t] += x;
        __syncthreads();
    }
    if (i < N2) {
        int excl = base + sh[t] - v;
        d_eoff[i] = excl;
        d_ecur[i] = excl;
        if (i == N2 - 1) d_eoff[N2] = excl + v;
        d_ecnt[i] = 0;   // maintain zero-at-entry invariant
    }
}
__global__ void k_fill(const int* __restrict__ eb, const int* __restrict__ ev) {
    int e = blockIdx.x * blockDim.x + threadIdx.x;
    if (e >= E2) return;
    int src, dst;
    if (e < EE) { src = eb[e];             dst = eb[EE + e]; }
    else        { src = NN + ev[e - EE];   dst = NN + ev[EE + (e - EE)]; }
    int p = atomicAdd(&d_ecur[dst], 1);
    d_eidx[p] = src;
}

// ---------------- gather: agg[d] = sum_{e in CSR(d)} ym[src_e] --------------
__global__ void vspn_gather(const __half* __restrict__ ym,
                            float* __restrict__ agg)
{
    int w = (blockIdx.x * blockDim.x + threadIdx.x) >> 5;
    if (w >= N2) return;
    int lane = threadIdx.x & 31;
    int e0 = d_eoff[w], e1 = d_eoff[w + 1];
    int lane4 = lane * 4;
    float4 s0 = make_float4(0.f, 0.f, 0.f, 0.f), s1 = s0, s2 = s0, s3 = s0;
    int e = e0;
    for (; e + 4 <= e1; e += 4) {
        int p0 = d_eidx[e], p1 = d_eidx[e + 1];
        int p2 = d_eidx[e + 2], p3 = d_eidx[e + 3];
        acc_row(s0, ym + (size_t)p0 * 128 + lane4);
        acc_row(s1, ym + (size_t)p1 * 128 + lane4);
        acc_row(s2, ym + (size_t)p2 * 128 + lane4);
        acc_row(s3, ym + (size_t)p3 * 128 + lane4);
    }
    for (; e < e1; e++)
        acc_row(s0, ym + (size_t)d_eidx[e] * 128 + lane4);
    s0.x += s1.x + s2.x + s3.x;
    s0.y += s1.y + s2.y + s3.y;
    s0.z += s1.z + s2.z + s3.z;
    s0.w += s1.w + s2.w + s3.w;
    *reinterpret_cast<float4*>(agg + (size_t)w * 128 + lane4) = s0;
}

// ---------------- embed: h = relu(x@Wemb); ym = fp16(h@W0) ------------------
#define SM_EMB (3 * TILE)
__global__ void __launch_bounds__(256, 1)
vspn_emb(const float* __restrict__ x_b, const float* __restrict__ x_v,
         int FB, int FV,
         float* __restrict__ h, __half* __restrict__ ym)
{
    extern __shared__ char smem[];
    const int tid = threadIdx.x, lane = tid & 31, wid = tid >> 5;
    const int wr = wid & 3, wc = wid >> 2;
    const int arow = wr * 32 + (lane & 15), akl = (lane >> 4) << 3;
    const int brow = wc * 64 + ((lane >> 4) << 3) + (lane & 7), bkl = ((lane >> 3) & 1) << 3;
    const int rl0 = wr * 32 + (lane >> 2);
    const int cb  = wc * 64 + (lane & 3) * 2;

    const int gb = (blockIdx.x >= MT) ? 1 : 0;
    const int row0_local = (blockIdx.x - gb * MT) * 128;    // row in x
    const int node0 = gb * NN + row0_local;                 // global node
    const float* x = gb ? x_v : x_b;
    const int Kin  = gb ? FV : FB;
    const char* imgE = d_img + (size_t)(10 + gb) * TILE;
    const char* imgM = d_img;   // W_s step 0

    uint32_t sA = smem_u32(smem), sB0 = sA + TILE, sB1 = sA + 2 * TILE;
    cp_tile(sB0, imgE, tid);
    cp_tile(sB1, imgM, tid);
    stage_A(x, Kin, NN, row0_local, smem, tid);
    CP_WAIT(1);
    __syncthreads();

    float acc[2][8][4];
    zero_acc(acc);
    mma_pass(sA, sB0, arow, akl, brow, bkl, acc);
    __syncthreads();   // A consumed

    // h = relu(acc): write gmem + restage fp16 into A slot
#pragma unroll
    for (int i = 0; i < 2; i++)
#pragma unroll
        for (int rr = 0; rr < 2; rr++) {
            int rl = rl0 + i * 16 + rr * 8;
            bool valid = (row0_local + rl) < NN;
            int node = node0 + rl;
#pragma unroll
            for (int j = 0; j < 8; j++) {
                int c = cb + j * 8;
                float v0 = fmaxf(acc[i][j][rr * 2], 0.f);
                float v1 = fmaxf(acc[i][j][rr * 2 + 1], 0.f);
                if (valid)
                    *reinterpret_cast<float2*>(h + (size_t)node * 128 + c) = make_float2(v0, v1);
                __half2 h2 = __floats2half2_rn(v0, v1);
                *reinterpret_cast<uint32_t*>(smem + swz(rl, c)) = *reinterpret_cast<uint32_t*>(&h2);
            }
        }
    CP_WAIT(0);
    __syncthreads();
    zero_acc(acc);
    mma_pass(sA, sB1, arow, akl, brow, bkl, acc);
#pragma unroll
    for (int i = 0; i < 2; i++)
#pragma unroll
        for (int rr = 0; rr < 2; rr++) {
            int rl = rl0 + i * 16 + rr * 8;
            if (row0_local + rl >= NN) continue;
            int node = node0 + rl;
#pragma unroll
            for (int j = 0; j < 8; j++) {
                int c = cb + j * 8;
                __half2 h2 = __floats2half2_rn(acc[i][j][rr * 2], acc[i][j][rr * 2 + 1]);
                *reinterpret_cast<uint32_t*>(ym + (size_t)node * 128 + c) =
                    *reinterpret_cast<uint32_t*>(&h2);
            }
        }
}

// ---------------- fused step: GRU(h, agg) -> h ; ym = fp16(h@W_next) --------
// R5-proven structure: 4 smem tiles (128KB), 2 B-buffers, no in-CTA gather.
#define SM_STEP (4 * TILE)   // A_agg | A_h | B0 | B1
__global__ void __launch_bounds__(256, 1)
vspn_step(const float* __restrict__ agg, float* __restrict__ h,
          int mstep,
          const float* __restrict__ bih, const float* __restrict__ bhh,
          __half* __restrict__ ym)
{
    extern __shared__ char smem[];
    const int tid = threadIdx.x, lane = tid & 31, wid = tid >> 5;
    const int wr = wid & 3, wc = wid >> 2;
    const int arow = wr * 32 + (lane & 15), akl = (lane >> 4) << 3;
    const int brow = wc * 64 + ((lane >> 4) << 3) + (lane & 7), bkl = ((lane >> 3) & 1) << 3;
    const int rl0 = wr * 32 + (lane >> 2);
    const int cb  = wc * 64 + (lane & 3) * 2;
    const int node0 = blockIdx.x * 128;

    uint32_t sA  = smem_u32(smem);
    uint32_t sAh = sA + TILE;
    uint32_t sB0 = sA + 2 * TILE;
    uint32_t sB1 = sA + 3 * TILE;

    cp_tile(sB0, d_img + 4 * TILE, tid);   // Whh_r
    cp_tile(sB1, d_img + 7 * TILE, tid);   // Wih_r
    stage_A(agg, 128, N2, node0, smem, tid);
    stage_A(h,   128, N2, node0, smem + TILE, tid);

    float acc[2][8][4], rg[2][8][4], ng[2][8][4];

    // ---- P0: gh_r ----
    CP_WAIT(1);
    __syncthreads();
    zero_acc(acc);
    mma_pass(sAh, sB0, arow, akl, brow, bkl, acc);
    __syncthreads();
    cp_tile(sB0, d_img + 6 * TILE, tid);   // Whh_n
    // ---- P1: + gi_r -> r ----
    CP_WAIT(1);
    __syncthreads();
    mma_pass(sA, sB1, arow, akl, brow, bkl, acc);
#pragma unroll
    for (int i = 0; i < 2; i++)
#pragma unroll
        for (int j = 0; j < 8; j++) {
            int c = cb + j * 8;
            float2 b1 = *reinterpret_cast<const float2*>(bih + c);
            float2 b2 = *reinterpret_cast<const float2*>(bhh + c);
#pragma unroll
            for (int rr = 0; rr < 2; rr++) {
                rg[i][j][rr * 2]     = sigm(acc[i][j][rr * 2]     + b1.x + b2.x);
                rg[i][j][rr * 2 + 1] = sigm(acc[i][j][rr * 2 + 1] + b1.y + b2.y);
            }
        }
    __syncthreads();
    cp_tile(sB1, d_img + 9 * TILE, tid);   // Wih_n
    // ---- P2: gh_n ----
    CP_WAIT(1);
    __syncthreads();
    zero_acc(acc);
    mma_pass(sAh, sB0, arow, akl, brow, bkl, acc);
#pragma unroll
    for (int i = 0; i < 2; i++)
#pragma unroll
        for (int j = 0; j < 8; j++) {
            int c = cb + j * 8;
            float2 b1 = *reinterpret_cast<const float2*>(bih + 256 + c);
            float2 b2 = *reinterpret_cast<const float2*>(bhh + 256 + c);
#pragma unroll
            for (int rr = 0; rr < 2; rr++) {
                acc[i][j][rr * 2]     = rg[i][j][rr * 2]     * (acc[i][j][rr * 2]     + b2.x) + b1.x;
                acc[i][j][rr * 2 + 1] = rg[i][j][rr * 2 + 1] * (acc[i][j][rr * 2 + 1] + b2.y) + b1.y;
            }
        }
    __syncthreads();
    cp_tile(sB0, d_img + 5 * TILE, tid);   // Whh_z
    // ---- P3: + gi_n -> n ----
    CP_WAIT(1);
    __syncthreads();
    mma_pass(sA, sB1, arow, akl, brow, bkl, acc);
#pragma unroll
    for (int i = 0; i < 2; i++)
#pragma unroll
        for (int j = 0; j < 8; j++)
#pragma unroll
            for (int q = 0; q < 4; q++) ng[i][j][q] = tanh_ap(acc[i][j][q]);
    __syncthreads();
    cp_tile(sB1, d_img + 8 * TILE, tid);   // Wih_z
    // ---- P4: gh_z ----
    CP_WAIT(1);
    __syncthreads();
    zero_acc(acc);
    mma_pass(sAh, sB0, arow, akl, brow, bkl, acc);
    __syncthreads();
    if (mstep >= 0) cp_tile(sB0, d_img + (size_t)mstep * TILE, tid);   // W_m
    // ---- P5: + gi_z -> z ; combine; restage h_new into sA ----
    if (mstep >= 0) { CP_WAIT(1); } else { CP_WAIT(0); }
    __syncthreads();
    mma_pass(sA, sB1, arow, akl, brow, bkl, acc);
    __syncthreads();   // all warps done reading sA
#pragma unroll
    for (int i = 0; i < 2; i++)
#pragma unroll
        for (int rr = 0; rr < 2; rr++) {
            int rl = rl0 + i * 16 + rr * 8;
            int node = node0 + rl;
            bool valid = node < N2;
#pragma unroll
            for (int j = 0; j < 8; j++) {
                int c = cb + j * 8;
                float2 b1 = *reinterpret_cast<const float2*>(bih + 128 + c);
                float2 b2 = *reinterpret_cast<const float2*>(bhh + 128 + c);
                float z0 = sigm(acc[i][j][rr * 2]     + b1.x + b2.x);
                float z1 = sigm(acc[i][j][rr * 2 + 1] + b1.y + b2.y);
                float2 hp = valid ? *reinterpret_cast<const float2*>(h + (size_t)node * 128 + c)
                                  : make_float2(0.f, 0.f);
                float h0 = (1.f - z0) * ng[i][j][rr * 2]     + z0 * hp.x;
                float h1 = (1.f - z1) * ng[i][j][rr * 2 + 1] + z1 * hp.y;
                if (valid)
                    *reinterpret_cast<float2*>(h + (size_t)node * 128 + c) = make_float2(h0, h1);
                __half2 hh = __floats2half2_rn(h0, h1);
                *reinterpret_cast<uint32_t*>(smem + swz(rl, c)) = *reinterpret_cast<uint32_t*>(&hh);
            }
        }

    // ---- P6: ym = fp16(h_new @ W[mstep]) ----
    if (mstep >= 0) {
        CP_WAIT(0);
        __syncthreads();
        zero_acc(acc);
        mma_pass(sA, sB0, arow, akl, brow, bkl, acc);
#pragma unroll
        for (int i = 0; i < 2; i++)
#pragma unroll
            for (int rr = 0; rr < 2; rr++) {
                int node = node0 + rl0 + i * 16 + rr * 8;
                if (node >= N2) continue;
#pragma unroll
                for (int j = 0; j < 8; j++) {
                    int c = cb + j * 8;
                    __half2 h2 = __floats2half2_rn(acc[i][j][rr * 2], acc[i][j][rr * 2 + 1]);
                    *reinterpret_cast<uint32_t*>(ym + (size_t)node * 128 + c) =
                        *reinterpret_cast<uint32_t*>(&h2);
                }
            }
    }
}

// ---------------- pool: combined 128 pools over 200k nodes ------------------
__global__ void vspn_pool(const float* __restrict__ h,
                          const int* __restrict__ bat_b, const int* __restrict__ bat_v)
{
    __shared__ int sbh[128];
    int j  = threadIdx.x;
    int n0 = blockIdx.x * 128;
    int nend = min(n0 + 128, N2);
    int cn = nend - n0;
    {
        int n = n0 + j;
        if (n < N2) sbh[j] = (n < NN) ? bat_b[n] : (GG + bat_v[n - NN]);
    }
    __syncthreads();
    float sum = 0.f, rc = 0.f;
    int cur = sbh[0];
    for (int t = 0; t < cn; t++) {
        int b = sbh[t];
        if (b != cur) {
            atomicAdd(&d_pool[(size_t)cur * HH + j], sum);
            if (j == 0) atomicAdd(&d_cnt[cur], rc);
            sum = 0.f; rc = 0.f; cur = b;
        }
        sum += fmaxf(h[(size_t)(n0 + t) * HH + j], 0.f);
        rc += 1.f;
    }
    atomicAdd(&d_pool[(size_t)cur * HH + j], sum);
    if (j == 0) atomicAdd(&d_cnt[cur], rc);
}

// ---------------- head ------------------------------------------------------
__global__ void vspn_head(const float* __restrict__ W1, const float* __restrict__ b1,
                          const float* __restrict__ W2, const float* __restrict__ b2,
                          float* __restrict__ out)
{
    int g = blockIdx.x;
    int k = threadIdx.x;
    __shared__ float gsh[256];
    __shared__ float tsh[256];
    float cb = fmaxf(d_cnt[g], 1.f);
    float cv = fmaxf(d_cnt[GG + g], 1.f);
    if (k < HH) gsh[k] = d_pool[(size_t)g * HH + k] / cb;
    else        gsh[k] = d_pool[(size_t)(GG + g) * HH + (k - HH)] / cv;
    __syncthreads();
    float acc = b1[k];
    for (int j = 0; j < 256; j++) acc += gsh[j] * W1[j * 256 + k];
    float t = fmaxf(acc, 0.f);
    tsh[k] = t * W2[k];
    __syncthreads();
    for (int s = 128; s > 0; s >>= 1) {
        if (k < s) tsh[k] += tsh[k + s];
        __syncthreads();
    }
    if (k == 0) {
        float x = tsh[0] + b2[0];
        out[g] = fmaxf(x, 0.f) + log1pf(expf(-fabsf(x)));
    }
}

// ---------------- launch ----------------------------------------------------
extern "C" void kernel_launch(void* const* d_in, const int* in_sizes, int n_in,
                              void* d_out, int out_size)
{
    const float* x_b   = (const float*)d_in[0];
    const int*   ei_b  = (const int*)  d_in[1];
    const int*   bat_b = (const int*)  d_in[2];
    const float* x_v   = (const float*)d_in[3];
    const int*   ei_v  = (const int*)  d_in[4];
    const int*   bat_v = (const int*)  d_in[5];
    const float* Wemb_b= (const float*)d_in[6];
    const float* Wemb_v= (const float*)d_in[7];
    const float* ggc   = (const float*)d_in[8];
    const float* w_ih  = (const float*)d_in[9];
    const float* w_hh  = (const float*)d_in[10];
    const float* b_ih  = (const float*)d_in[11];
    const float* b_hh  = (const float*)d_in[12];
    const float* W1    = (const float*)d_in[13];
    const float* b1    = (const float*)d_in[14];
    const float* W2    = (const float*)d_in[15];
    const float* b2    = (const float*)d_in[16];
    float* out = (float*)d_out;

    const int FB = in_sizes[0] / NN;
    const int FV = in_sizes[3] / NN;

    float *p_h, *p_agg;
    __half* p_ym;
    cudaGetSymbolAddress((void**)&p_h,   d_h);
    cudaGetSymbolAddress((void**)&p_ym,  d_ym);
    cudaGetSymbolAddress((void**)&p_agg, d_agg);

    cudaFuncSetAttribute(vspn_emb,  cudaFuncAttributeMaxDynamicSharedMemorySize, SM_EMB);
    cudaFuncSetAttribute(vspn_step, cudaFuncAttributeMaxDynamicSharedMemorySize, SM_STEP);

    // 0: weights + zero pool/cnt
    vspn_prep<<<(12 * 16384 + 255) / 256, 256>>>(ggc, w_ih, w_hh, Wemb_b, Wemb_v, FB, FV);
    // 1: embed both graphs (also produces step-0 messages)
    vspn_emb<<<2 * MT, 256, SM_EMB>>>(x_b, x_v, FB, FV, p_h, p_ym);
    // 2-4: CSR build for combined graph (d_ecnt zero at entry; k_scan re-zeroes)
    k_hist<<<(E2 + 255) / 256, 256>>>(ei_b, ei_v);
    k_scan<<<NB2, 512>>>();
    k_fill<<<(E2 + 255) / 256, 256>>>(ei_b, ei_v);
    // 5-12: gather (standalone, high-occupancy) + fused GRU step
    for (int s = 0; s < STEPS; s++) {
        vspn_gather<<<(N2 + 7) / 8, 256>>>(p_ym, p_agg);
        int mstep = (s < STEPS - 1) ? (s + 1) : -1;
        vspn_step<<<NT2, 256, SM_STEP>>>(p_agg, p_h, mstep, b_ih, b_hh, p_ym);
    }
    // 13: mean-pool both graphs
    vspn_pool<<<NT2, 128>>>(p_h, bat_b, bat_v);
    // 14: head
    vspn_head<<<GG, 256>>>(W1, b1, W2, b2, out);
}

// round 11
// speedup vs baseline: 4.9790x; 3.2182x over previous
#include <cuda_runtime.h>
#include <cuda_fp16.h>
#include <cstdint>
#include <math.h>

#define NN 100000
#define EE 600000
#define GG 64
#define HH 128
#define STEPS 4
#define NB_SCAN 196   // ceil(NN/512)
#define TILE 32768    // fp16 128x128 tile bytes
#define MT 782        // ceil(NN/128)
#define NPAD (MT * 128)   // 100096

// ---------------- scratch (device globals; allocation-free) ----------------
__device__ __align__(256) float  d_h  [(size_t)NN * HH];     // node hidden fp32
__device__ __align__(256) __half d_ym [(size_t)NN * HH];     // messages fp16
__device__ __align__(256) __half d_agg[(size_t)MT * 16384];  // gathered msgs, swizzled tiles
// Pre-swizzled fp16 weight tiles, 32KB each:
//  t0..3 : W_s ; t4..6 : Whh r,z,n ; t7..9 : Wih r,z,n ; t10,11 : emb b,v
__device__ __align__(256) char  d_img[12 * TILE];
__device__ __align__(256) float d_pool[2 * GG * HH];
__device__ __align__(256) float d_cnt [2 * GG];
// CSR scratch
__device__ int d_ecnt[NN];
__device__ int d_ecur[NN];
__device__ int d_eoff[NN + 1];
__device__ int d_eidx[EE];
__device__ int d_bsum[256];
__device__ int d_boff[256];

// ---------------- helpers ---------------------------------------------------
__device__ __forceinline__ uint32_t smem_u32(const void* p) {
    uint32_t a;
    asm("{ .reg .u64 t; cvta.to.shared.u64 t, %1; cvt.u32.u64 %0, t; }" : "=r"(a) : "l"(p));
    return a;
}
__host__ __device__ __forceinline__ uint32_t swz(int row, int k) {
    return (uint32_t)(row * 256 + ((((k >> 3) ^ (row & 7)) << 4) | ((k & 7) << 1)));
}
__device__ __forceinline__ float tanh_ap(float x) {
    float y;
    asm("tanh.approx.f32 %0, %1;" : "=f"(y) : "f"(x));
    return y;
}
__device__ __forceinline__ float sigm(float x) {
    return fmaf(tanh_ap(x * 0.5f), 0.5f, 0.5f);
}

#define LDSM4(R0, R1, R2, R3, ADDR) \
    asm volatile("ldmatrix.sync.aligned.m8n8.x4.shared.b16 {%0,%1,%2,%3}, [%4];" \
                 : "=r"(R0), "=r"(R1), "=r"(R2), "=r"(R3) : "r"(ADDR))

#define MMA16816(D, A0, A1, A2, A3, B0, B1) \
    asm volatile("mma.sync.aligned.m16n8k16.row.col.f32.f16.f16.f32 " \
                 "{%0,%1,%2,%3}, {%4,%5,%6,%7}, {%8,%9}, {%0,%1,%2,%3};" \
                 : "+f"((D)[0]), "+f"((D)[1]), "+f"((D)[2]), "+f"((D)[3]) \
                 : "r"(A0), "r"(A1), "r"(A2), "r"(A3), "r"(B0), "r"(B1))

// cp.async a 32KB tile (all 256 threads), one commit group
__device__ __forceinline__ void cp_tile(uint32_t dst, const char* __restrict__ src, int tid) {
#pragma unroll
    for (int i = 0; i < 8; i++) {
        uint32_t d = dst + tid * 16 + i * 4096;
        const char* s = src + tid * 16 + i * 4096;
        asm volatile("cp.async.cg.shared.global [%0], [%1], 16;" :: "r"(d), "l"(s));
    }
    asm volatile("cp.async.commit_group;");
}
#define CP_WAIT(n) asm volatile("cp.async.wait_group %0;" :: "n"(n))

// one 128x128x128 fp16 MMA pass accumulating into acc
__device__ __forceinline__ void mma_pass(uint32_t sA, uint32_t sB,
                                         int arow, int akl, int brow, int bkl,
                                         float (&acc)[2][8][4])
{
#pragma unroll
    for (int ks = 0; ks < 8; ks++) {
        const int kk = ks * 16;
        uint32_t a0[4], a1[4];
        LDSM4(a0[0], a0[1], a0[2], a0[3], sA + swz(arow,      kk + akl));
        LDSM4(a1[0], a1[1], a1[2], a1[3], sA + swz(arow + 16, kk + akl));
#pragma unroll
        for (int nb = 0; nb < 4; nb++) {
            uint32_t bh[4];
            LDSM4(bh[0], bh[1], bh[2], bh[3], sB + swz(brow + nb * 16, kk + bkl));
            int j0 = nb * 2;
            MMA16816(acc[0][j0],     a0[0], a0[1], a0[2], a0[3], bh[0], bh[1]);
            MMA16816(acc[1][j0],     a1[0], a1[1], a1[2], a1[3], bh[0], bh[1]);
            MMA16816(acc[0][j0 + 1], a0[0], a0[1], a0[2], a0[3], bh[2], bh[3]);
            MMA16816(acc[1][j0 + 1], a1[0], a1[1], a1[2], a1[3], bh[2], bh[3]);
        }
    }
}

__device__ __forceinline__ void zero_acc(float (&acc)[2][8][4]) {
#pragma unroll
    for (int i = 0; i < 2; i++)
#pragma unroll
        for (int j = 0; j < 8; j++)
#pragma unroll
            for (int q = 0; q < 4; q++) acc[i][j][q] = 0.f;
}

// stage fp32 A[rows at row0.., Kin<=128] -> fp16 swizzled smem tile
__device__ __forceinline__ void stage_A(const float* __restrict__ A, int Kin, int Mlim,
                                        int row0, char* dst, int tid)
{
    int r = tid >> 1;
    int hf = tid & 1;
    int row = row0 + r;
    bool valid = row < Mlim;
    const float* ap = A + (size_t)row * Kin;
#pragma unroll
    for (int i = 0; i < 8; i++) {
        int k0 = hf * 64 + i * 8;
        float v[8];
        if (Kin == 128) {
            float4 f0 = valid ? *reinterpret_cast<const float4*>(ap + k0)
                              : make_float4(0.f, 0.f, 0.f, 0.f);
            float4 f1 = valid ? *reinterpret_cast<const float4*>(ap + k0 + 4)
                              : make_float4(0.f, 0.f, 0.f, 0.f);
            v[0] = f0.x; v[1] = f0.y; v[2] = f0.z; v[3] = f0.w;
            v[4] = f1.x; v[5] = f1.y; v[6] = f1.z; v[7] = f1.w;
        } else {
#pragma unroll
            for (int q = 0; q < 8; q++) {
                int k = k0 + q;
                v[q] = (valid && k < Kin) ? ap[k] : 0.f;
            }
        }
        uint32_t p[4];
#pragma unroll
        for (int q = 0; q < 4; q++) {
            __half2 h2 = __floats2half2_rn(v[2 * q], v[2 * q + 1]);
            p[q] = *reinterpret_cast<uint32_t*>(&h2);
        }
        *reinterpret_cast<uint4*>(dst + swz(r, k0)) = make_uint4(p[0], p[1], p[2], p[3]);
    }
}

__device__ __forceinline__ void acc_row(float4& s, const __half* __restrict__ p) {
    uint2 v = *reinterpret_cast<const uint2*>(p);
    float2 a = __half22float2(*reinterpret_cast<__half2*>(&v.x));
    float2 b = __half22float2(*reinterpret_cast<__half2*>(&v.y));
    s.x += a.x; s.y += a.y; s.z += b.x; s.w += b.y;
}

// ---------------- prep: fp16 weight tiles + zero pool/cnt -------------------
__global__ void vspn_prep(const float* __restrict__ ggc,   // [4,128,128]
                          const float* __restrict__ wih,   // [384,128]
                          const float* __restrict__ whh,   // [384,128]
                          const float* __restrict__ wembB, // [FB,128]
                          const float* __restrict__ wembV, // [FV,128]
                          int FB, int FV)
{
    int idx = blockIdx.x * blockDim.x + threadIdx.x;
    if (idx < 2 * GG * HH) d_pool[idx] = 0.f;
    if (idx < 2 * GG) d_cnt[idx] = 0.f;
    if (idx >= 12 * 16384) return;
    int t = idx / 16384;
    int e = idx % 16384;
    int n = e >> 7;
    int k = e & 127;
    float v = 0.f;
    if (t < 4) {
        v = ggc[(t * 128 + k) * 128 + n];
    } else if (t < 7) {
        int g = t - 4;
        v = whh[(size_t)(g * 128 + n) * 128 + k];
    } else if (t < 10) {
        int g = t - 7;
        v = wih[(size_t)(g * 128 + n) * 128 + k];
    } else if (t == 10) {
        v = (k < FB) ? wembB[(size_t)k * 128 + n] : 0.f;
    } else {
        v = (k < FV) ? wembV[(size_t)k * 128 + n] : 0.f;
    }
    *(__half*)(d_img + (size_t)t * TILE + swz(n, k)) = __float2half_rn(v);
}

// ---------------- CSR build (per graph; race-free multi-kernel chain) -------
__global__ void k_hist(const int* __restrict__ ei) {
    int e = blockIdx.x * blockDim.x + threadIdx.x;
    if (e < EE) atomicAdd(&d_ecnt[ei[EE + e]], 1);
}
__global__ void k_blocksum() {
    __shared__ int sh[512];
    int i = blockIdx.x * 512 + threadIdx.x;
    sh[threadIdx.x] = (i < NN) ? d_ecnt[i] : 0;
    __syncthreads();
    for (int s = 256; s > 0; s >>= 1) {
        if (threadIdx.x < s) sh[threadIdx.x] += sh[threadIdx.x + s];
        __syncthreads();
    }
    if (threadIdx.x == 0) d_bsum[blockIdx.x] = sh[0];
}
__global__ void k_scanbsum() {
    __shared__ int sh[256];
    int t = threadIdx.x;
    int v = (t < NB_SCAN) ? d_bsum[t] : 0;
    sh[t] = v;
    __syncthreads();
    for (int off = 1; off < 256; off <<= 1) {
        int x = (t >= off) ? sh[t - off] : 0;
        __syncthreads();
        sh[t] += x;
        __syncthreads();
    }
    if (t < NB_SCAN) d_boff[t] = sh[t] - v;   // exclusive
}
__global__ void k_scanfinal() {
    __shared__ int sh[512];
    int t = threadIdx.x;
    int i = blockIdx.x * 512 + t;
    int v = (i < NN) ? d_ecnt[i] : 0;
    sh[t] = v;
    __syncthreads();
    for (int off = 1; off < 512; off <<= 1) {
        int x = (t >= off) ? sh[t - off] : 0;
        __syncthreads();
        sh[t] += x;
        __syncthreads();
    }
    if (i < NN) {
        int excl = d_boff[blockIdx.x] + sh[t] - v;
        d_eoff[i] = excl;
        d_ecur[i] = excl;
        if (i == NN - 1) d_eoff[NN] = excl + v;
    }
}
__global__ void k_fill(const int* __restrict__ ei) {
    int e = blockIdx.x * blockDim.x + threadIdx.x;
    if (e >= EE) return;
    int p = atomicAdd(&d_ecur[ei[EE + e]], 1);
    d_eidx[p] = ei[e];
}

// -------- gather: agg tile[row] = fp16(sum CSR ym rows), swizzled layout ----
__global__ void vspn_gather(const __half* __restrict__ ym,
                            __half* __restrict__ agg)
{
    int w = (blockIdx.x * blockDim.x + threadIdx.x) >> 5;   // padded node index
    if (w >= NPAD) return;
    int lane = threadIdx.x & 31;
    int lane4 = lane * 4;
    float4 s0 = make_float4(0.f, 0.f, 0.f, 0.f), s1 = s0, s2 = s0, s3 = s0;
    if (w < NN) {
        int e0 = d_eoff[w], e1 = d_eoff[w + 1];
        int e = e0;
        for (; e + 4 <= e1; e += 4) {
            int p0 = d_eidx[e], p1 = d_eidx[e + 1];
            int p2 = d_eidx[e + 2], p3 = d_eidx[e + 3];
            acc_row(s0, ym + (size_t)p0 * 128 + lane4);
            acc_row(s1, ym + (size_t)p1 * 128 + lane4);
            acc_row(s2, ym + (size_t)p2 * 128 + lane4);
            acc_row(s3, ym + (size_t)p3 * 128 + lane4);
        }
        for (; e < e1; e++)
            acc_row(s0, ym + (size_t)d_eidx[e] * 128 + lane4);
    }
    s0.x += s1.x + s2.x + s3.x;
    s0.y += s1.y + s2.y + s3.y;
    s0.z += s1.z + s2.z + s3.z;
    s0.w += s1.w + s2.w + s3.w;
    __half2 h0 = __floats2half2_rn(s0.x, s0.y);
    __half2 h1 = __floats2half2_rn(s0.z, s0.w);
    uint2 pk;
    pk.x = *reinterpret_cast<uint32_t*>(&h0);
    pk.y = *reinterpret_cast<uint32_t*>(&h1);
    char* dst = reinterpret_cast<char*>(agg) + (size_t)(w >> 7) * TILE + swz(w & 127, lane4);
    *reinterpret_cast<uint2*>(dst) = pk;
}

// ---------------- embed: h = relu(x@Wemb); ym = fp16(h@W0) ------------------
#define SM_EMB (3 * TILE)
__global__ void __launch_bounds__(256, 1)
vspn_emb(const float* __restrict__ x, int Kin,
         const char* __restrict__ imgE, const char* __restrict__ imgM,
         float* __restrict__ h, __half* __restrict__ ym, int M)
{
    extern __shared__ char smem[];
    const int tid = threadIdx.x, lane = tid & 31, wid = tid >> 5;
    const int wr = wid & 3, wc = wid >> 2;
    const int arow = wr * 32 + (lane & 15), akl = (lane >> 4) << 3;
    const int brow = wc * 64 + ((lane >> 4) << 3) + (lane & 7), bkl = ((lane >> 3) & 1) << 3;
    const int rl0 = wr * 32 + (lane >> 2);
    const int cb  = wc * 64 + (lane & 3) * 2;
    const int node0 = blockIdx.x * 128;

    uint32_t sA = smem_u32(smem), sB0 = sA + TILE, sB1 = sA + 2 * TILE;
    cp_tile(sB0, imgE, tid);
    cp_tile(sB1, imgM, tid);
    stage_A(x, Kin, M, node0, smem, tid);
    CP_WAIT(1);
    __syncthreads();

    float acc[2][8][4];
    zero_acc(acc);
    mma_pass(sA, sB0, arow, akl, brow, bkl, acc);
    __syncthreads();   // A consumed

    // h = relu(acc): write gmem + restage fp16 into A slot
#pragma unroll
    for (int i = 0; i < 2; i++)
#pragma unroll
        for (int rr = 0; rr < 2; rr++) {
            int rl = rl0 + i * 16 + rr * 8;
            int node = node0 + rl;
            bool valid = node < M;
#pragma unroll
            for (int j = 0; j < 8; j++) {
                int c = cb + j * 8;
                float v0 = fmaxf(acc[i][j][rr * 2], 0.f);
                float v1 = fmaxf(acc[i][j][rr * 2 + 1], 0.f);
                if (valid)
                    *reinterpret_cast<float2*>(h + (size_t)node * 128 + c) = make_float2(v0, v1);
                __half2 h2 = __floats2half2_rn(v0, v1);
                *reinterpret_cast<uint32_t*>(smem + swz(rl, c)) = *reinterpret_cast<uint32_t*>(&h2);
            }
        }
    CP_WAIT(0);
    __syncthreads();
    zero_acc(acc);
    mma_pass(sA, sB1, arow, akl, brow, bkl, acc);
#pragma unroll
    for (int i = 0; i < 2; i++)
#pragma unroll
        for (int rr = 0; rr < 2; rr++) {
            int node = node0 + rl0 + i * 16 + rr * 8;
            if (node >= M) continue;
#pragma unroll
            for (int j = 0; j < 8; j++) {
                int c = cb + j * 8;
                __half2 h2 = __floats2half2_rn(acc[i][j][rr * 2], acc[i][j][rr * 2 + 1]);
                *reinterpret_cast<uint32_t*>(ym + (size_t)node * 128 + c) =
                    *reinterpret_cast<uint32_t*>(&h2);
            }
        }
}

// ---------------- fused step: GRU(h, agg) -> h ; ym = fp16(h@W_next) --------
// agg arrives pre-swizzled fp16 → cp.async straight into sA.
#define SM_STEP (4 * TILE)   // sA(agg) | sAh(h) | B0 | B1
__global__ void __launch_bounds__(256, 1)
vspn_step(const __half* __restrict__ agg, float* __restrict__ h,
          int mstep,
          const float* __restrict__ bih, const float* __restrict__ bhh,
          __half* __restrict__ ym)
{
    extern __shared__ char smem[];
    const int tid = threadIdx.x, lane = tid & 31, wid = tid >> 5;
    const int wr = wid & 3, wc = wid >> 2;
    const int arow = wr * 32 + (lane & 15), akl = (lane >> 4) << 3;
    const int brow = wc * 64 + ((lane >> 4) << 3) + (lane & 7), bkl = ((lane >> 3) & 1) << 3;
    const int rl0 = wr * 32 + (lane >> 2);
    const int cb  = wc * 64 + (lane & 3) * 2;
    const int node0 = blockIdx.x * 128;

    uint32_t sA  = smem_u32(smem);
    uint32_t sAh = sA + TILE;
    uint32_t sB0 = sA + 2 * TILE;
    uint32_t sB1 = sA + 3 * TILE;

    cp_tile(sB0, d_img + 4 * TILE, tid);                                     // g1: Whh_r
    cp_tile(sB1, d_img + 7 * TILE, tid);                                     // g2: Wih_r
    cp_tile(sA, reinterpret_cast<const char*>(agg) + (size_t)blockIdx.x * TILE, tid); // g3: agg
    stage_A(h, 128, NN, node0, smem + TILE, tid);

    float acc[2][8][4], rg[2][8][4], ng[2][8][4];

    // ---- P0: gh_r (needs g1) ----
    CP_WAIT(2);
    __syncthreads();
    zero_acc(acc);
    mma_pass(sAh, sB0, arow, akl, brow, bkl, acc);
    __syncthreads();
    cp_tile(sB0, d_img + 6 * TILE, tid);   // g4: Whh_n
    // ---- P1: + gi_r -> r (needs g2, g3) ----
    CP_WAIT(1);
    __syncthreads();
    mma_pass(sA, sB1, arow, akl, brow, bkl, acc);
#pragma unroll
    for (int i = 0; i < 2; i++)
#pragma unroll
        for (int j = 0; j < 8; j++) {
            int c = cb + j * 8;
            float2 b1 = *reinterpret_cast<const float2*>(bih + c);
            float2 b2 = *reinterpret_cast<const float2*>(bhh + c);
#pragma unroll
            for (int rr = 0; rr < 2; rr++) {
                rg[i][j][rr * 2]     = sigm(acc[i][j][rr * 2]     + b1.x + b2.x);
                rg[i][j][rr * 2 + 1] = sigm(acc[i][j][rr * 2 + 1] + b1.y + b2.y);
            }
        }
    __syncthreads();
    cp_tile(sB1, d_img + 9 * TILE, tid);   // g5: Wih_n
    // ---- P2: gh_n (needs g4) ----
    CP_WAIT(1);
    __syncthreads();
    zero_acc(acc);
    mma_pass(sAh, sB0, arow, akl, brow, bkl, acc);
#pragma unroll
    for (int i = 0; i < 2; i++)
#pragma unroll
        for (int j = 0; j < 8; j++) {
            int c = cb + j * 8;
            float2 b1 = *reinterpret_cast<const float2*>(bih + 256 + c);
            float2 b2 = *reinterpret_cast<const float2*>(bhh + 256 + c);
#pragma unroll
            for (int rr = 0; rr < 2; rr++) {
                acc[i][j][rr * 2]     = rg[i][j][rr * 2]     * (acc[i][j][rr * 2]     + b2.x) + b1.x;
                acc[i][j][rr * 2 + 1] = rg[i][j][rr * 2 + 1] * (acc[i][j][rr * 2 + 1] + b2.y) + b1.y;
            }
        }
    __syncthreads();
    cp_tile(sB0, d_img + 5 * TILE, tid);   // g6: Whh_z
    // ---- P3: + gi_n -> n (needs g5) ----
    CP_WAIT(1);
    __syncthreads();
    mma_pass(sA, sB1, arow, akl, brow, bkl, acc);
#pragma unroll
    for (int i = 0; i < 2; i++)
#pragma unroll
        for (int j = 0; j < 8; j++)
#pragma unroll
            for (int q = 0; q < 4; q++) ng[i][j][q] = tanh_ap(acc[i][j][q]);
    __syncthreads();
    cp_tile(sB1, d_img + 8 * TILE, tid);   // g7: Wih_z
    // ---- P4: gh_z (needs g6) ----
    CP_WAIT(1);
    __syncthreads();
    zero_acc(acc);
    mma_pass(sAh, sB0, arow, akl, brow, bkl, acc);
    __syncthreads();
    if (mstep >= 0) cp_tile(sB0, d_img + (size_t)mstep * TILE, tid);   // g8: W_m
    // ---- P5: + gi_z -> z ; combine; restage h_new into sA (needs g7) ----
    if (mstep >= 0) { CP_WAIT(1); } else { CP_WAIT(0); }
    __syncthreads();
    mma_pass(sA, sB1, arow, akl, brow, bkl, acc);
    __syncthreads();   // all warps done reading sA
#pragma unroll
    for (int i = 0; i < 2; i++)
#pragma unroll
        for (int rr = 0; rr < 2; rr++) {
            int rl = rl0 + i * 16 + rr * 8;
            int node = node0 + rl;
            bool valid = node < NN;
#pragma unroll
            for (int j = 0; j < 8; j++) {
                int c = cb + j * 8;
                float2 b1 = *reinterpret_cast<const float2*>(bih + 128 + c);
                float2 b2 = *reinterpret_cast<const float2*>(bhh + 128 + c);
                float z0 = sigm(acc[i][j][rr * 2]     + b1.x + b2.x);
                float z1 = sigm(acc[i][j][rr * 2 + 1] + b1.y + b2.y);
                float2 hp = valid ? *reinterpret_cast<const float2*>(h + (size_t)node * 128 + c)
                                  : make_float2(0.f, 0.f);
                float h0 = (1.f - z0) * ng[i][j][rr * 2]     + z0 * hp.x;
                float h1 = (1.f - z1) * ng[i][j][rr * 2 + 1] + z1 * hp.y;
                if (valid)
                    *reinterpret_cast<float2*>(h + (size_t)node * 128 + c) = make_float2(h0, h1);
                __half2 hh = __floats2half2_rn(h0, h1);
                *reinterpret_cast<uint32_t*>(smem + swz(rl, c)) = *reinterpret_cast<uint32_t*>(&hh);
            }
        }

    // ---- P6: ym = fp16(h_new @ W[mstep]) (needs g8) ----
    if (mstep >= 0) {
        CP_WAIT(0);
        __syncthreads();
        zero_acc(acc);
        mma_pass(sA, sB0, arow, akl, brow, bkl, acc);
#pragma unroll
        for (int i = 0; i < 2; i++)
#pragma unroll
            for (int rr = 0; rr < 2; rr++) {
                int node = node0 + rl0 + i * 16 + rr * 8;
                if (node >= NN) continue;
#pragma unroll
                for (int j = 0; j < 8; j++) {
                    int c = cb + j * 8;
                    __half2 h2 = __floats2half2_rn(acc[i][j][rr * 2], acc[i][j][rr * 2 + 1]);
                    *reinterpret_cast<uint32_t*>(ym + (size_t)node * 128 + c) =
                        *reinterpret_cast<uint32_t*>(&h2);
                }
            }
    }
}

// ---------------- pool: pool[b] += relu(h[n]), cnt[b] += 1 ------------------
__global__ void vspn_pool(const float* __restrict__ h, const int* __restrict__ batch,
                          float* __restrict__ pool, float* __restrict__ cnt, int Nn)
{
    __shared__ int sbh[128];
    int j  = threadIdx.x;
    int n0 = blockIdx.x * 128;
    int nend = min(n0 + 128, Nn);
    int cn = nend - n0;
    if (n0 + j < Nn) sbh[j] = batch[n0 + j];
    __syncthreads();
    float sum = 0.f, rc = 0.f;
    int cur = sbh[0];
    for (int t = 0; t < cn; t++) {
        int b = sbh[t];
        if (b != cur) {
            atomicAdd(&pool[(size_t)cur * HH + j], sum);
            if (j == 0) atomicAdd(&cnt[cur], rc);
            sum = 0.f; rc = 0.f; cur = b;
        }
        sum += fmaxf(h[(size_t)(n0 + t) * HH + j], 0.f);
        rc += 1.f;
    }
    atomicAdd(&pool[(size_t)cur * HH + j], sum);
    if (j == 0) atomicAdd(&cnt[cur], rc);
}

// ---------------- head ------------------------------------------------------
__global__ void vspn_head(const float* __restrict__ W1, const float* __restrict__ b1,
                          const float* __restrict__ W2, const float* __restrict__ b2,
                          float* __restrict__ out)
{
    int g = blockIdx.x;
    int k = threadIdx.x;
    __shared__ float gsh[256];
    __shared__ float tsh[256];
    float cb = fmaxf(d_cnt[g], 1.f);
    float cv = fmaxf(d_cnt[GG + g], 1.f);
    if (k < HH) gsh[k] = d_pool[(size_t)g * HH + k] / cb;
    else        gsh[k] = d_pool[(size_t)(GG + g) * HH + (k - HH)] / cv;
    __syncthreads();
    float acc = b1[k];
    for (int j = 0; j < 256; j++) acc += gsh[j] * W1[j * 256 + k];
    float t = fmaxf(acc, 0.f);
    tsh[k] = t * W2[k];
    __syncthreads();
    for (int s = 128; s > 0; s >>= 1) {
        if (k < s) tsh[k] += tsh[k + s];
        __syncthreads();
    }
    if (k == 0) {
        float x = tsh[0] + b2[0];
        out[g] = fmaxf(x, 0.f) + log1pf(expf(-fabsf(x)));
    }
}

// ---------------- launch ----------------------------------------------------
extern "C" void kernel_launch(void* const* d_in, const int* in_sizes, int n_in,
                              void* d_out, int out_size)
{
    const float* x_b   = (const float*)d_in[0];
    const int*   ei_b  = (const int*)  d_in[1];
    const int*   bat_b = (const int*)  d_in[2];
    const float* x_v   = (const float*)d_in[3];
    const int*   ei_v  = (const int*)  d_in[4];
    const int*   bat_v = (const int*)  d_in[5];
    const float* Wemb_b= (const float*)d_in[6];
    const float* Wemb_v= (const float*)d_in[7];
    const float* ggc   = (const float*)d_in[8];
    const float* w_ih  = (const float*)d_in[9];
    const float* w_hh  = (const float*)d_in[10];
    const float* b_ih  = (const float*)d_in[11];
    const float* b_hh  = (const float*)d_in[12];
    const float* W1    = (const float*)d_in[13];
    const float* b1    = (const float*)d_in[14];
    const float* W2    = (const float*)d_in[15];
    const float* b2    = (const float*)d_in[16];
    float* out = (float*)d_out;

    const int FB = in_sizes[0] / NN;
    const int FV = in_sizes[3] / NN;

    float *p_h, *p_pool, *p_cnt;
    __half *p_ym, *p_agg;
    char* p_img;
    int* p_ecnt;
    cudaGetSymbolAddress((void**)&p_h,    d_h);
    cudaGetSymbolAddress((void**)&p_ym,   d_ym);
    cudaGetSymbolAddress((void**)&p_agg,  d_agg);
    cudaGetSymbolAddress((void**)&p_img,  d_img);
    cudaGetSymbolAddress((void**)&p_ecnt, d_ecnt);
    cudaGetSymbolAddress((void**)&p_pool, d_pool);
    cudaGetSymbolAddress((void**)&p_cnt,  d_cnt);

    cudaFuncSetAttribute(vspn_emb,  cudaFuncAttributeMaxDynamicSharedMemorySize, SM_EMB);
    cudaFuncSetAttribute(vspn_step, cudaFuncAttributeMaxDynamicSharedMemorySize, SM_STEP);

    vspn_prep<<<(12 * 16384 + 255) / 256, 256>>>(ggc, w_ih, w_hh, Wemb_b, Wemb_v, FB, FV);

    const int EB = (EE + 255) / 256;
    const int GB = (NPAD * 32 + 255) / 256;   // gather: 1 warp per padded node
    const int poolBlocks = (NN + 127) / 128;

    for (int graph = 0; graph < 2; graph++) {
        const float* x   = graph ? x_v   : x_b;
        const int*   ei  = graph ? ei_v  : ei_b;
        const int*   bat = graph ? bat_v : bat_b;
        const int    F   = graph ? FV    : FB;

        // CSR build for this graph (race-free chain)
        cudaMemsetAsync(p_ecnt, 0, sizeof(int) * NN);
        k_hist<<<EB, 256>>>(ei);
        k_blocksum<<<NB_SCAN, 512>>>();
        k_scanbsum<<<1, 256>>>();
        k_scanfinal<<<NB_SCAN, 512>>>();
        k_fill<<<EB, 256>>>(ei);

        // embed + step-0 messages
        vspn_emb<<<MT, 256, SM_EMB>>>(x, F, p_img + (size_t)(10 + graph) * TILE,
                                      p_img, p_h, p_ym, NN);
        // steps
        for (int s = 0; s < STEPS; s++) {
            vspn_gather<<<GB, 256>>>(p_ym, p_agg);
            int mstep = (s < STEPS - 1) ? (s + 1) : -1;
            vspn_step<<<MT, 256, SM_STEP>>>(p_agg, p_h, mstep, b_ih, b_hh, p_ym);
        }
        vspn_pool<<<poolBlocks, 128>>>(p_h, bat,
                                       p_pool + (size_t)graph * GG * HH,
                                       p_cnt + graph * GG, NN);
    }

    vspn_head<<<GG, 256>>>(W1, b1, W2, b2, out);
}

// round 12
// speedup vs baseline: 5.9250x; 1.1900x over previous
#include <cuda_runtime.h>
#include <cuda_fp16.h>
#include <cstdint>
#include <math.h>

#define NN 100000
#define EE 600000
#define GG 64
#define HH 128
#define STEPS 4
#define NB_SCAN 196   // ceil(NN/512)
#define TILE 32768    // fp16 128x128 tile bytes
#define MT 782        // ceil(NN/128)
#define NPAD (MT * 128)   // 100096

// ---------------- scratch (device globals; allocation-free) ----------------
__device__ __align__(256) __half d_ht [(size_t)MT * 16384];  // hidden h, fp16 swizzled tiles
__device__ __align__(256) __half d_ym [(size_t)NN * HH];     // messages fp16
__device__ __align__(256) __half d_agg[(size_t)MT * 16384];  // gathered msgs, swizzled tiles
// Pre-swizzled fp16 weight tiles, 32KB each:
//  t0..3 : W_s ; t4..6 : Whh r,z,n ; t7..9 : Wih r,z,n ; t10,11 : emb b,v
__device__ __align__(256) char  d_img[12 * TILE];
__device__ __align__(256) float d_pool[2 * GG * HH];
__device__ __align__(256) float d_cnt [2 * GG];
// CSR scratch
__device__ int d_ecnt[NN];
__device__ int d_ecur[NN];
__device__ int d_eoff[NN + 1];
__device__ int d_eidx[EE];

// ---------------- helpers ---------------------------------------------------
__device__ __forceinline__ uint32_t smem_u32(const void* p) {
    uint32_t a;
    asm("{ .reg .u64 t; cvta.to.shared.u64 t, %1; cvt.u32.u64 %0, t; }" : "=r"(a) : "l"(p));
    return a;
}
__host__ __device__ __forceinline__ uint32_t swz(int row, int k) {
    return (uint32_t)(row * 256 + ((((k >> 3) ^ (row & 7)) << 4) | ((k & 7) << 1)));
}
__device__ __forceinline__ float tanh_ap(float x) {
    float y;
    asm("tanh.approx.f32 %0, %1;" : "=f"(y) : "f"(x));
    return y;
}
__device__ __forceinline__ float sigm(float x) {
    return fmaf(tanh_ap(x * 0.5f), 0.5f, 0.5f);
}

#define LDSM4(R0, R1, R2, R3, ADDR) \
    asm volatile("ldmatrix.sync.aligned.m8n8.x4.shared.b16 {%0,%1,%2,%3}, [%4];" \
                 : "=r"(R0), "=r"(R1), "=r"(R2), "=r"(R3) : "r"(ADDR))

#define MMA16816(D, A0, A1, A2, A3, B0, B1) \
    asm volatile("mma.sync.aligned.m16n8k16.row.col.f32.f16.f16.f32 " \
                 "{%0,%1,%2,%3}, {%4,%5,%6,%7}, {%8,%9}, {%0,%1,%2,%3};" \
                 : "+f"((D)[0]), "+f"((D)[1]), "+f"((D)[2]), "+f"((D)[3]) \
                 : "r"(A0), "r"(A1), "r"(A2), "r"(A3), "r"(B0), "r"(B1))

// cp.async a 32KB tile (all 256 threads), one commit group
__device__ __forceinline__ void cp_tile(uint32_t dst, const char* __restrict__ src, int tid) {
#pragma unroll
    for (int i = 0; i < 8; i++) {
        uint32_t d = dst + tid * 16 + i * 4096;
        const char* s = src + tid * 16 + i * 4096;
        asm volatile("cp.async.cg.shared.global [%0], [%1], 16;" :: "r"(d), "l"(s));
    }
    asm volatile("cp.async.commit_group;");
}
#define CP_WAIT(n) asm volatile("cp.async.wait_group %0;" :: "n"(n))

// one 128x128x128 fp16 MMA pass accumulating into acc
__device__ __forceinline__ void mma_pass(uint32_t sA, uint32_t sB,
                                         int arow, int akl, int brow, int bkl,
                                         float (&acc)[2][8][4])
{
#pragma unroll
    for (int ks = 0; ks < 8; ks++) {
        const int kk = ks * 16;
        uint32_t a0[4], a1[4];
        LDSM4(a0[0], a0[1], a0[2], a0[3], sA + swz(arow,      kk + akl));
        LDSM4(a1[0], a1[1], a1[2], a1[3], sA + swz(arow + 16, kk + akl));
#pragma unroll
        for (int nb = 0; nb < 4; nb++) {
            uint32_t bh[4];
            LDSM4(bh[0], bh[1], bh[2], bh[3], sB + swz(brow + nb * 16, kk + bkl));
            int j0 = nb * 2;
            MMA16816(acc[0][j0],     a0[0], a0[1], a0[2], a0[3], bh[0], bh[1]);
            MMA16816(acc[1][j0],     a1[0], a1[1], a1[2], a1[3], bh[0], bh[1]);
            MMA16816(acc[0][j0 + 1], a0[0], a0[1], a0[2], a0[3], bh[2], bh[3]);
            MMA16816(acc[1][j0 + 1], a1[0], a1[1], a1[2], a1[3], bh[2], bh[3]);
        }
    }
}

__device__ __forceinline__ void zero_acc(float (&acc)[2][8][4]) {
#pragma unroll
    for (int i = 0; i < 2; i++)
#pragma unroll
        for (int j = 0; j < 8; j++)
#pragma unroll
            for (int q = 0; q < 4; q++) acc[i][j][q] = 0.f;
}

// stage fp32 A[rows at row0.., Kin<=128] -> fp16 swizzled smem tile
__device__ __forceinline__ void stage_A(const float* __restrict__ A, int Kin, int Mlim,
                                        int row0, char* dst, int tid)
{
    int r = tid >> 1;
    int hf = tid & 1;
    int row = row0 + r;
    bool valid = row < Mlim;
    const float* ap = A + (size_t)row * Kin;
#pragma unroll
    for (int i = 0; i < 8; i++) {
        int k0 = hf * 64 + i * 8;
        float v[8];
#pragma unroll
        for (int q = 0; q < 8; q++) {
            int k = k0 + q;
            v[q] = (valid && k < Kin) ? ap[k] : 0.f;
        }
        uint32_t p[4];
#pragma unroll
        for (int q = 0; q < 4; q++) {
            __half2 h2 = __floats2half2_rn(v[2 * q], v[2 * q + 1]);
            p[q] = *reinterpret_cast<uint32_t*>(&h2);
        }
        *reinterpret_cast<uint4*>(dst + swz(r, k0)) = make_uint4(p[0], p[1], p[2], p[3]);
    }
}

__device__ __forceinline__ void acc_row(float4& s, const __half* __restrict__ p) {
    uint2 v = *reinterpret_cast<const uint2*>(p);
    float2 a = __half22float2(*reinterpret_cast<__half2*>(&v.x));
    float2 b = __half22float2(*reinterpret_cast<__half2*>(&v.y));
    s.x += a.x; s.y += a.y; s.z += b.x; s.w += b.y;
}

// ---------------- prep: fp16 weight tiles + zero pool/cnt -------------------
__global__ void vspn_prep(const float* __restrict__ ggc,   // [4,128,128]
                          const float* __restrict__ wih,   // [384,128]
                          const float* __restrict__ whh,   // [384,128]
                          const float* __restrict__ wembB, // [FB,128]
                          const float* __restrict__ wembV, // [FV,128]
                          int FB, int FV)
{
    int idx = blockIdx.x * blockDim.x + threadIdx.x;
    if (idx < 2 * GG * HH) d_pool[idx] = 0.f;
    if (idx < 2 * GG) d_cnt[idx] = 0.f;
    if (idx >= 12 * 16384) return;
    int t = idx / 16384;
    int e = idx % 16384;
    int n = e >> 7;
    int k = e & 127;
    float v = 0.f;
    if (t < 4) {
        v = ggc[(t * 128 + k) * 128 + n];
    } else if (t < 7) {
        int g = t - 4;
        v = whh[(size_t)(g * 128 + n) * 128 + k];
    } else if (t < 10) {
        int g = t - 7;
        v = wih[(size_t)(g * 128 + n) * 128 + k];
    } else if (t == 10) {
        v = (k < FB) ? wembB[(size_t)k * 128 + n] : 0.f;
    } else {
        v = (k < FV) ? wembV[(size_t)k * 128 + n] : 0.f;
    }
    *(__half*)(d_img + (size_t)t * TILE + swz(n, k)) = __float2half_rn(v);
}

// ---------------- CSR build (per graph; memset->hist->scan->fill) -----------
__global__ void k_hist(const int* __restrict__ ei) {
    int e = blockIdx.x * blockDim.x + threadIdx.x;
    if (e < EE) atomicAdd(&d_ecnt[ei[EE + e]], 1);
}
// fused scan: per-block base by summing preceding counts (read-only on d_ecnt
// — race-free: nothing writes d_ecnt in this kernel), then intra-block scan.
__global__ void k_scan2() {
    __shared__ int sh[512];
    int t = threadIdx.x, bid = blockIdx.x;
    int i = bid * 512 + t;
    int base = 0;
    for (int j = t; j < bid * 512; j += 512) base += d_ecnt[j];
    sh[t] = base;
    __syncthreads();
    for (int s = 256; s > 0; s >>= 1) {
        if (t < s) sh[t] += sh[t + s];
        __syncthreads();
    }
    base = sh[0];
    __syncthreads();
    int v = (i < NN) ? d_ecnt[i] : 0;
    sh[t] = v;
    __syncthreads();
    for (int off = 1; off < 512; off <<= 1) {
        int x = (t >= off) ? sh[t - off] : 0;
        __syncthreads();
        sh[t] += x;
        __syncthreads();
    }
    if (i < NN) {
        int excl = base + sh[t] - v;
        d_eoff[i] = excl;
        d_ecur[i] = excl;
        if (i == NN - 1) d_eoff[NN] = excl + v;
    }
}
__global__ void k_fill(const int* __restrict__ ei) {
    int e = blockIdx.x * blockDim.x + threadIdx.x;
    if (e >= EE) return;
    int p = atomicAdd(&d_ecur[ei[EE + e]], 1);
    d_eidx[p] = ei[e];
}

// -------- gather: agg tile[row] = fp16(sum CSR ym rows), swizzled layout ----
__global__ void vspn_gather(const __half* __restrict__ ym,
                            __half* __restrict__ agg)
{
    int w = (blockIdx.x * blockDim.x + threadIdx.x) >> 5;   // padded node index
    if (w >= NPAD) return;
    int lane = threadIdx.x & 31;
    int lane4 = lane * 4;
    float4 s0 = make_float4(0.f, 0.f, 0.f, 0.f), s1 = s0, s2 = s0, s3 = s0;
    if (w < NN) {
        int e0 = d_eoff[w], e1 = d_eoff[w + 1];
        int e = e0;
        for (; e + 4 <= e1; e += 4) {
            int p0 = d_eidx[e], p1 = d_eidx[e + 1];
            int p2 = d_eidx[e + 2], p3 = d_eidx[e + 3];
            acc_row(s0, ym + (size_t)p0 * 128 + lane4);
            acc_row(s1, ym + (size_t)p1 * 128 + lane4);
            acc_row(s2, ym + (size_t)p2 * 128 + lane4);
            acc_row(s3, ym + (size_t)p3 * 128 + lane4);
        }
        for (; e < e1; e++)
            acc_row(s0, ym + (size_t)d_eidx[e] * 128 + lane4);
    }
    s0.x += s1.x + s2.x + s3.x;
    s0.y += s1.y + s2.y + s3.y;
    s0.z += s1.z + s2.z + s3.z;
    s0.w += s1.w + s2.w + s3.w;
    __half2 h0 = __floats2half2_rn(s0.x, s0.y);
    __half2 h1 = __floats2half2_rn(s0.z, s0.w);
    uint2 pk;
    pk.x = *reinterpret_cast<uint32_t*>(&h0);
    pk.y = *reinterpret_cast<uint32_t*>(&h1);
    char* dst = reinterpret_cast<char*>(agg) + (size_t)(w >> 7) * TILE + swz(w & 127, lane4);
    *reinterpret_cast<uint2*>(dst) = pk;
}

// ---------------- embed: ht = fp16tiles(relu(x@Wemb)); ym = fp16(h@W0) ------
#define SM_EMB (3 * TILE)
__global__ void __launch_bounds__(256, 1)
vspn_emb(const float* __restrict__ x, int Kin,
         const char* __restrict__ imgE, const char* __restrict__ imgM,
         __half* __restrict__ ht, __half* __restrict__ ym, int M)
{
    extern __shared__ char smem[];
    const int tid = threadIdx.x, lane = tid & 31, wid = tid >> 5;
    const int wr = wid & 3, wc = wid >> 2;
    const int arow = wr * 32 + (lane & 15), akl = (lane >> 4) << 3;
    const int brow = wc * 64 + ((lane >> 4) << 3) + (lane & 7), bkl = ((lane >> 3) & 1) << 3;
    const int rl0 = wr * 32 + (lane >> 2);
    const int cb  = wc * 64 + (lane & 3) * 2;
    const int node0 = blockIdx.x * 128;
    char* httile = reinterpret_cast<char*>(ht) + (size_t)blockIdx.x * TILE;

    uint32_t sA = smem_u32(smem), sB0 = sA + TILE, sB1 = sA + 2 * TILE;
    cp_tile(sB0, imgE, tid);
    cp_tile(sB1, imgM, tid);
    stage_A(x, Kin, M, node0, smem, tid);
    CP_WAIT(1);
    __syncthreads();

    float acc[2][8][4];
    zero_acc(acc);
    mma_pass(sA, sB0, arow, akl, brow, bkl, acc);
    __syncthreads();   // A consumed

    // h = relu(acc): write fp16 tile to gmem + restage into A slot
#pragma unroll
    for (int i = 0; i < 2; i++)
#pragma unroll
        for (int rr = 0; rr < 2; rr++) {
            int rl = rl0 + i * 16 + rr * 8;
            int node = node0 + rl;
            bool valid = node < M;
#pragma unroll
            for (int j = 0; j < 8; j++) {
                int c = cb + j * 8;
                float v0 = fmaxf(acc[i][j][rr * 2], 0.f);
                float v1 = fmaxf(acc[i][j][rr * 2 + 1], 0.f);
                __half2 h2 = __floats2half2_rn(v0, v1);
                uint32_t pk = *reinterpret_cast<uint32_t*>(&h2);
                *reinterpret_cast<uint32_t*>(smem + swz(rl, c)) = pk;
                if (valid)
                    *reinterpret_cast<uint32_t*>(httile + swz(rl, c)) = pk;
            }
        }
    CP_WAIT(0);
    __syncthreads();
    zero_acc(acc);
    mma_pass(sA, sB1, arow, akl, brow, bkl, acc);
#pragma unroll
    for (int i = 0; i < 2; i++)
#pragma unroll
        for (int rr = 0; rr < 2; rr++) {
            int node = node0 + rl0 + i * 16 + rr * 8;
            if (node >= M) continue;
#pragma unroll
            for (int j = 0; j < 8; j++) {
                int c = cb + j * 8;
                __half2 h2 = __floats2half2_rn(acc[i][j][rr * 2], acc[i][j][rr * 2 + 1]);
                *reinterpret_cast<uint32_t*>(ym + (size_t)node * 128 + c) =
                    *reinterpret_cast<uint32_t*>(&h2);
            }
        }
}

// ---------------- fused step: GRU(ht, agg) -> ht ; ym = fp16(h@W_next) ------
// Both agg AND h arrive as pre-swizzled fp16 tiles → pure cp.async staging.
// Combine reads h_old straight from sAh smem (no second gmem pass).
#define SM_STEP (4 * TILE)   // sA(agg) | sAh(h) | B0 | B1
__global__ void __launch_bounds__(256, 1)
vspn_step(const __half* __restrict__ agg, __half* __restrict__ ht,
          int mstep,
          const float* __restrict__ bih, const float* __restrict__ bhh,
          __half* __restrict__ ym)
{
    extern __shared__ char smem[];
    const int tid = threadIdx.x, lane = tid & 31, wid = tid >> 5;
    const int wr = wid & 3, wc = wid >> 2;
    const int arow = wr * 32 + (lane & 15), akl = (lane >> 4) << 3;
    const int brow = wc * 64 + ((lane >> 4) << 3) + (lane & 7), bkl = ((lane >> 3) & 1) << 3;
    const int rl0 = wr * 32 + (lane >> 2);
    const int cb  = wc * 64 + (lane & 3) * 2;
    const int node0 = blockIdx.x * 128;
    char* httile = reinterpret_cast<char*>(ht) + (size_t)blockIdx.x * TILE;

    uint32_t sA  = smem_u32(smem);
    uint32_t sAh = sA + TILE;
    uint32_t sB0 = sA + 2 * TILE;
    uint32_t sB1 = sA + 3 * TILE;

    cp_tile(sAh, httile, tid);                                                 // C1: h
    cp_tile(sB0, d_img + 4 * TILE, tid);                                       // C2: Whh_r
    cp_tile(sB1, d_img + 7 * TILE, tid);                                       // C3: Wih_r
    cp_tile(sA, reinterpret_cast<const char*>(agg) + (size_t)blockIdx.x * TILE, tid); // C4: agg

    float acc[2][8][4], rg[2][8][4], ng[2][8][4];

    // ---- P0: gh_r (needs C1, C2) ----
    CP_WAIT(2);
    __syncthreads();
    zero_acc(acc);
    mma_pass(sAh, sB0, arow, akl, brow, bkl, acc);
    __syncthreads();
    cp_tile(sB0, d_img + 6 * TILE, tid);   // C5: Whh_n
    // ---- P1: + gi_r -> r (needs C3, C4) ----
    CP_WAIT(1);
    __syncthreads();
    mma_pass(sA, sB1, arow, akl, brow, bkl, acc);
#pragma unroll
    for (int i = 0; i < 2; i++)
#pragma unroll
        for (int j = 0; j < 8; j++) {
            int c = cb + j * 8;
            float2 b1 = *reinterpret_cast<const float2*>(bih + c);
            float2 b2 = *reinterpret_cast<const float2*>(bhh + c);
#pragma unroll
            for (int rr = 0; rr < 2; rr++) {
                rg[i][j][rr * 2]     = sigm(acc[i][j][rr * 2]     + b1.x + b2.x);
                rg[i][j][rr * 2 + 1] = sigm(acc[i][j][rr * 2 + 1] + b1.y + b2.y);
            }
        }
    __syncthreads();
    cp_tile(sB1, d_img + 9 * TILE, tid);   // C6: Wih_n
    // ---- P2: gh_n (needs C5) ----
    CP_WAIT(1);
    __syncthreads();
    zero_acc(acc);
    mma_pass(sAh, sB0, arow, akl, brow, bkl, acc);
#pragma unroll
    for (int i = 0; i < 2; i++)
#pragma unroll
        for (int j = 0; j < 8; j++) {
            int c = cb + j * 8;
            float2 b1 = *reinterpret_cast<const float2*>(bih + 256 + c);
            float2 b2 = *reinterpret_cast<const float2*>(bhh + 256 + c);
#pragma unroll
            for (int rr = 0; rr < 2; rr++) {
                acc[i][j][rr * 2]     = rg[i][j][rr * 2]     * (acc[i][j][rr * 2]     + b2.x) + b1.x;
                acc[i][j][rr * 2 + 1] = rg[i][j][rr * 2 + 1] * (acc[i][j][rr * 2 + 1] + b2.y) + b1.y;
            }
        }
    __syncthreads();
    cp_tile(sB0, d_img + 5 * TILE, tid);   // C7: Whh_z
    // ---- P3: + gi_n -> n (needs C6) ----
    CP_WAIT(1);
    __syncthreads();
    mma_pass(sA, sB1, arow, akl, brow, bkl, acc);
#pragma unroll
    for (int i = 0; i < 2; i++)
#pragma unroll
        for (int j = 0; j < 8; j++)
#pragma unroll
            for (int q = 0; q < 4; q++) ng[i][j][q] = tanh_ap(acc[i][j][q]);
    __syncthreads();
    cp_tile(sB1, d_img + 8 * TILE, tid);   // C8: Wih_z
    // ---- P4: gh_z (needs C7) ----
    CP_WAIT(1);
    __syncthreads();
    zero_acc(acc);
    mma_pass(sAh, sB0, arow, akl, brow, bkl, acc);
    __syncthreads();
    if (mstep >= 0) cp_tile(sB0, d_img + (size_t)mstep * TILE, tid);   // C9: W_m
    // ---- P5: + gi_z -> z ; combine (h_old from sAh smem); restage into sA --
    if (mstep >= 0) { CP_WAIT(1); } else { CP_WAIT(0); }
    __syncthreads();
    mma_pass(sA, sB1, arow, akl, brow, bkl, acc);
    __syncthreads();   // all warps done reading sA
#pragma unroll
    for (int i = 0; i < 2; i++)
#pragma unroll
        for (int rr = 0; rr < 2; rr++) {
            int rl = rl0 + i * 16 + rr * 8;
            int node = node0 + rl;
            bool valid = node < NN;
#pragma unroll
            for (int j = 0; j < 8; j++) {
                int c = cb + j * 8;
                float2 b1 = *reinterpret_cast<const float2*>(bih + 128 + c);
                float2 b2 = *reinterpret_cast<const float2*>(bhh + 128 + c);
                float z0 = sigm(acc[i][j][rr * 2]     + b1.x + b2.x);
                float z1 = sigm(acc[i][j][rr * 2 + 1] + b1.y + b2.y);
                uint32_t hw = *reinterpret_cast<uint32_t*>(smem + TILE + swz(rl, c));
                float2 hp = __half22float2(*reinterpret_cast<__half2*>(&hw));
                float h0 = (1.f - z0) * ng[i][j][rr * 2]     + z0 * hp.x;
                float h1 = (1.f - z1) * ng[i][j][rr * 2 + 1] + z1 * hp.y;
                __half2 hh = __floats2half2_rn(h0, h1);
                uint32_t pk = *reinterpret_cast<uint32_t*>(&hh);
                *reinterpret_cast<uint32_t*>(smem + swz(rl, c)) = pk;
                if (valid)
                    *reinterpret_cast<uint32_t*>(httile + swz(rl, c)) = pk;
            }
        }

    // ---- P6: ym = fp16(h_new @ W[mstep]) (needs C9) ----
    if (mstep >= 0) {
        CP_WAIT(0);
        __syncthreads();
        zero_acc(acc);
        mma_pass(sA, sB0, arow, akl, brow, bkl, acc);
#pragma unroll
        for (int i = 0; i < 2; i++)
#pragma unroll
            for (int rr = 0; rr < 2; rr++) {
                int node = node0 + rl0 + i * 16 + rr * 8;
                if (node >= NN) continue;
#pragma unroll
                for (int j = 0; j < 8; j++) {
                    int c = cb + j * 8;
                    __half2 h2 = __floats2half2_rn(acc[i][j][rr * 2], acc[i][j][rr * 2 + 1]);
                    *reinterpret_cast<uint32_t*>(ym + (size_t)node * 128 + c) =
                        *reinterpret_cast<uint32_t*>(&h2);
                }
            }
    }
}

// ---------------- pool: pool[b] += relu(h[n]), cnt[b] += 1 (fp16 tiles) -----
__global__ void vspn_pool(const __half* __restrict__ ht, const int* __restrict__ batch,
                          float* __restrict__ pool, float* __restrict__ cnt, int Nn)
{
    __shared__ int sbh[128];
    int j  = threadIdx.x;
    int n0 = blockIdx.x * 128;
    int nend = min(n0 + 128, Nn);
    int cn = nend - n0;
    if (n0 + j < Nn) sbh[j] = batch[n0 + j];
    __syncthreads();
    const char* tb = reinterpret_cast<const char*>(ht) + (size_t)blockIdx.x * TILE;
    float sum = 0.f, rc = 0.f;
    int cur = sbh[0];
    for (int t = 0; t < cn; t++) {
        int b = sbh[t];
        if (b != cur) {
            atomicAdd(&pool[(size_t)cur * HH + j], sum);
            if (j == 0) atomicAdd(&cnt[cur], rc);
            sum = 0.f; rc = 0.f; cur = b;
        }
        float v = __half2float(*reinterpret_cast<const __half*>(tb + swz(t, j)));
        sum += fmaxf(v, 0.f);
        rc += 1.f;
    }
    atomicAdd(&pool[(size_t)cur * HH + j], sum);
    if (j == 0) atomicAdd(&cnt[cur], rc);
}

// ---------------- head ------------------------------------------------------
__global__ void vspn_head(const float* __restrict__ W1, const float* __restrict__ b1,
                          const float* __restrict__ W2, const float* __restrict__ b2,
                          float* __restrict__ out)
{
    int g = blockIdx.x;
    int k = threadIdx.x;
    __shared__ float gsh[256];
    __shared__ float tsh[256];
    float cb = fmaxf(d_cnt[g], 1.f);
    float cv = fmaxf(d_cnt[GG + g], 1.f);
    if (k < HH) gsh[k] = d_pool[(size_t)g * HH + k] / cb;
    else        gsh[k] = d_pool[(size_t)(GG + g) * HH + (k - HH)] / cv;
    __syncthreads();
    float acc = b1[k];
    for (int j = 0; j < 256; j++) acc += gsh[j] * W1[j * 256 + k];
    float t = fmaxf(acc, 0.f);
    tsh[k] = t * W2[k];
    __syncthreads();
    for (int s = 128; s > 0; s >>= 1) {
        if (k < s) tsh[k] += tsh[k + s];
        __syncthreads();
    }
    if (k == 0) {
        float x = tsh[0] + b2[0];
        out[g] = fmaxf(x, 0.f) + log1pf(expf(-fabsf(x)));
    }
}

// ---------------- launch ----------------------------------------------------
extern "C" void kernel_launch(void* const* d_in, const int* in_sizes, int n_in,
                              void* d_out, int out_size)
{
    const float* x_b   = (const float*)d_in[0];
    const int*   ei_b  = (const int*)  d_in[1];
    const int*   bat_b = (const int*)  d_in[2];
    const float* x_v   = (const float*)d_in[3];
    const int*   ei_v  = (const int*)  d_in[4];
    const int*   bat_v = (const int*)  d_in[5];
    const float* Wemb_b= (const float*)d_in[6];
    const float* Wemb_v= (const float*)d_in[7];
    const float* ggc   = (const float*)d_in[8];
    const float* w_ih  = (const float*)d_in[9];
    const float* w_hh  = (const float*)d_in[10];
    const float* b_ih  = (const float*)d_in[11];
    const float* b_hh  = (const float*)d_in[12];
    const float* W1    = (const float*)d_in[13];
    const float* b1    = (const float*)d_in[14];
    const float* W2    = (const float*)d_in[15];
    const float* b2    = (const float*)d_in[16];
    float* out = (float*)d_out;

    const int FB = in_sizes[0] / NN;
    const int FV = in_sizes[3] / NN;

    float *p_pool, *p_cnt;
    __half *p_ht, *p_ym, *p_agg;
    char* p_img;
    int* p_ecnt;
    cudaGetSymbolAddress((void**)&p_ht,   d_ht);
    cudaGetSymbolAddress((void**)&p_ym,   d_ym);
    cudaGetSymbolAddress((void**)&p_agg,  d_agg);
    cudaGetSymbolAddress((void**)&p_img,  d_img);
    cudaGetSymbolAddress((void**)&p_ecnt, d_ecnt);
    cudaGetSymbolAddress((void**)&p_pool, d_pool);
    cudaGetSymbolAddress((void**)&p_cnt,  d_cnt);

    cudaFuncSetAttribute(vspn_emb,  cudaFuncAttributeMaxDynamicSharedMemorySize, SM_EMB);
    cudaFuncSetAttribute(vspn_step, cudaFuncAttributeMaxDynamicSharedMemorySize, SM_STEP);

    vspn_prep<<<(12 * 16384 + 255) / 256, 256>>>(ggc, w_ih, w_hh, Wemb_b, Wemb_v, FB, FV);
    // zero last-tile pad rows of ht once (avoid NaN ingestion via cp.async)
    cudaMemsetAsync(p_ht + (size_t)(MT - 1) * 16384, 0, TILE);

    const int EB = (EE + 255) / 256;
    const int GB = (NPAD * 32 + 255) / 256;   // gather: 1 warp per padded node
    const int poolBlocks = (NN + 127) / 128;

    for (int graph = 0; graph < 2; graph++) {
        const float* x   = graph ? x_v   : x_b;
        const int*   ei  = graph ? ei_v  : ei_b;
        const int*   bat = graph ? bat_v : bat_b;
        const int    F   = graph ? FV    : FB;

        // CSR build for this graph
        cudaMemsetAsync(p_ecnt, 0, sizeof(int) * NN);
        k_hist<<<EB, 256>>>(ei);
        k_scan2<<<NB_SCAN, 512>>>();
        k_fill<<<EB, 256>>>(ei);

        // embed + step-0 messages
        vspn_emb<<<MT, 256, SM_EMB>>>(x, F, p_img + (size_t)(10 + graph) * TILE,
                                      p_img, p_ht, p_ym, NN);
        // steps
        for (int s = 0; s < STEPS; s++) {
            vspn_gather<<<GB, 256>>>(p_ym, p_agg);
            int mstep = (s < STEPS - 1) ? (s + 1) : -1;
            vspn_step<<<MT, 256, SM_STEP>>>(p_agg, p_ht, mstep, b_ih, b_hh, p_ym);
        }
        vspn_pool<<<poolBlocks, 128>>>(p_ht, bat,
                                       p_pool + (size_t)graph * GG * HH,
                                       p_cnt + graph * GG, NN);
    }

    vspn_head<<<GG, 256>>>(W1, b1, W2, b2, out);
}

// round 13
// speedup vs baseline: 6.0539x; 1.0218x over previous
#include <cuda_runtime.h>
#include <cuda_fp16.h>
#include <cstdint>
#include <math.h>

#define NN 100000
#define EE 600000
#define GG 64
#define HH 128
#define STEPS 4
#define NB_SCAN 196   // ceil(NN/512)
#define TILE 32768    // fp16 128x128 tile bytes
#define MT 782        // ceil(NN/128)
#define NPAD (MT * 128)   // 100096

// ---------------- scratch (device globals; allocation-free) ----------------
__device__ __align__(256) __half d_ht [(size_t)MT * 16384];  // hidden h, fp16 swizzled tiles
__device__ __align__(256) __half d_ym [(size_t)NN * HH];     // messages fp16
__device__ __align__(256) __half d_agg[(size_t)MT * 16384];  // gathered msgs, swizzled tiles
// Pre-swizzled fp16 weight tiles, 32KB each:
//  t0..3 : W_s ; t4..6 : Whh r,z,n ; t7..9 : Wih r,z,n ; t10,11 : emb b,v
__device__ __align__(256) char  d_img[12 * TILE];
__device__ __align__(256) float d_pool[2 * GG * HH];
__device__ __align__(256) float d_cnt [2 * GG];
// CSR scratch (d_ecnt: zeroed by prep for graph 0, by k_fill for graph 1)
__device__ int d_ecnt[NN];
__device__ int d_ecur[NN];
__device__ int d_eoff[NN + 1];
__device__ int d_eidx[EE];

// ---------------- helpers ---------------------------------------------------
__device__ __forceinline__ uint32_t smem_u32(const void* p) {
    uint32_t a;
    asm("{ .reg .u64 t; cvta.to.shared.u64 t, %1; cvt.u32.u64 %0, t; }" : "=r"(a) : "l"(p));
    return a;
}
__host__ __device__ __forceinline__ uint32_t swz(int row, int k) {
    return (uint32_t)(row * 256 + ((((k >> 3) ^ (row & 7)) << 4) | ((k & 7) << 1)));
}
__device__ __forceinline__ float tanh_ap(float x) {
    float y;
    asm("tanh.approx.f32 %0, %1;" : "=f"(y) : "f"(x));
    return y;
}
__device__ __forceinline__ float sigm(float x) {
    return fmaf(tanh_ap(x * 0.5f), 0.5f, 0.5f);
}

#define LDSM4(R0, R1, R2, R3, ADDR) \
    asm volatile("ldmatrix.sync.aligned.m8n8.x4.shared.b16 {%0,%1,%2,%3}, [%4];" \
                 : "=r"(R0), "=r"(R1), "=r"(R2), "=r"(R3) : "r"(ADDR))

#define MMA16816(D, A0, A1, A2, A3, B0, B1) \
    asm volatile("mma.sync.aligned.m16n8k16.row.col.f32.f16.f16.f32 " \
                 "{%0,%1,%2,%3}, {%4,%5,%6,%7}, {%8,%9}, {%0,%1,%2,%3};" \
                 : "+f"((D)[0]), "+f"((D)[1]), "+f"((D)[2]), "+f"((D)[3]) \
                 : "r"(A0), "r"(A1), "r"(A2), "r"(A3), "r"(B0), "r"(B1))

// cp.async a 32KB tile (all 256 threads), one commit group
__device__ __forceinline__ void cp_tile(uint32_t dst, const char* __restrict__ src, int tid) {
#pragma unroll
    for (int i = 0; i < 8; i++) {
        uint32_t d = dst + tid * 16 + i * 4096;
        const char* s = src + tid * 16 + i * 4096;
        asm volatile("cp.async.cg.shared.global [%0], [%1], 16;" :: "r"(d), "l"(s));
    }
    asm volatile("cp.async.commit_group;");
}
#define CP_WAIT(n) asm volatile("cp.async.wait_group %0;" :: "n"(n))

// one 128x128x128 fp16 MMA pass accumulating into acc
__device__ __forceinline__ void mma_pass(uint32_t sA, uint32_t sB,
                                         int arow, int akl, int brow, int bkl,
                                         float (&acc)[2][8][4])
{
#pragma unroll
    for (int ks = 0; ks < 8; ks++) {
        const int kk = ks * 16;
        uint32_t a0[4], a1[4];
        LDSM4(a0[0], a0[1], a0[2], a0[3], sA + swz(arow,      kk + akl));
        LDSM4(a1[0], a1[1], a1[2], a1[3], sA + swz(arow + 16, kk + akl));
#pragma unroll
        for (int nb = 0; nb < 4; nb++) {
            uint32_t bh[4];
            LDSM4(bh[0], bh[1], bh[2], bh[3], sB + swz(brow + nb * 16, kk + bkl));
            int j0 = nb * 2;
            MMA16816(acc[0][j0],     a0[0], a0[1], a0[2], a0[3], bh[0], bh[1]);
            MMA16816(acc[1][j0],     a1[0], a1[1], a1[2], a1[3], bh[0], bh[1]);
            MMA16816(acc[0][j0 + 1], a0[0], a0[1], a0[2], a0[3], bh[2], bh[3]);
            MMA16816(acc[1][j0 + 1], a1[0], a1[1], a1[2], a1[3], bh[2], bh[3]);
        }
    }
}

__device__ __forceinline__ void zero_acc(float (&acc)[2][8][4]) {
#pragma unroll
    for (int i = 0; i < 2; i++)
#pragma unroll
        for (int j = 0; j < 8; j++)
#pragma unroll
            for (int q = 0; q < 4; q++) acc[i][j][q] = 0.f;
}

// stage fp32 A[rows at row0.., Kin<=128] -> fp16 swizzled smem tile
__device__ __forceinline__ void stage_A(const float* __restrict__ A, int Kin, int Mlim,
                                        int row0, char* dst, int tid)
{
    int r = tid >> 1;
    int hf = tid & 1;
    int row = row0 + r;
    bool valid = row < Mlim;
    const float* ap = A + (size_t)row * Kin;
#pragma unroll
    for (int i = 0; i < 8; i++) {
        int k0 = hf * 64 + i * 8;
        float v[8];
#pragma unroll
        for (int q = 0; q < 8; q++) {
            int k = k0 + q;
            v[q] = (valid && k < Kin) ? ap[k] : 0.f;
        }
        uint32_t p[4];
#pragma unroll
        for (int q = 0; q < 4; q++) {
            __half2 h2 = __floats2half2_rn(v[2 * q], v[2 * q + 1]);
            p[q] = *reinterpret_cast<uint32_t*>(&h2);
        }
        *reinterpret_cast<uint4*>(dst + swz(r, k0)) = make_uint4(p[0], p[1], p[2], p[3]);
    }
}

__device__ __forceinline__ void acc_row(float4& s, const __half* __restrict__ p) {
    uint2 v = *reinterpret_cast<const uint2*>(p);
    float2 a = __half22float2(*reinterpret_cast<__half2*>(&v.x));
    float2 b = __half22float2(*reinterpret_cast<__half2*>(&v.y));
    s.x += a.x; s.y += a.y; s.z += b.x; s.w += b.y;
}

// ------- prep: fp16 weight tiles + zero pool/cnt/ecnt/ht-pad-tile ----------
__global__ void vspn_prep(const float* __restrict__ ggc,   // [4,128,128]
                          const float* __restrict__ wih,   // [384,128]
                          const float* __restrict__ whh,   // [384,128]
                          const float* __restrict__ wembB, // [FB,128]
                          const float* __restrict__ wembV, // [FV,128]
                          int FB, int FV)
{
    int idx = blockIdx.x * blockDim.x + threadIdx.x;
    if (idx < 2 * GG * HH) d_pool[idx] = 0.f;
    if (idx < 2 * GG) d_cnt[idx] = 0.f;
    if (idx < NN) d_ecnt[idx] = 0;
    if (idx < 16384) d_ht[(size_t)(MT - 1) * 16384 + idx] = __float2half(0.f);
    if (idx >= 12 * 16384) return;
    int t = idx / 16384;
    int e = idx % 16384;
    int n = e >> 7;
    int k = e & 127;
    float v = 0.f;
    if (t < 4) {
        v = ggc[(t * 128 + k) * 128 + n];
    } else if (t < 7) {
        int g = t - 4;
        v = whh[(size_t)(g * 128 + n) * 128 + k];
    } else if (t < 10) {
        int g = t - 7;
        v = wih[(size_t)(g * 128 + n) * 128 + k];
    } else if (t == 10) {
        v = (k < FB) ? wembB[(size_t)k * 128 + n] : 0.f;
    } else {
        v = (k < FV) ? wembV[(size_t)k * 128 + n] : 0.f;
    }
    *(__half*)(d_img + (size_t)t * TILE + swz(n, k)) = __float2half_rn(v);
}

// ---------------- CSR build (per graph; hist->scan->fill) -------------------
__global__ void k_hist(const int* __restrict__ ei) {
    int e = blockIdx.x * blockDim.x + threadIdx.x;
    if (e < EE) atomicAdd(&d_ecnt[ei[EE + e]], 1);
}
// fused scan: per-block base by summing preceding counts (read-only on d_ecnt)
__global__ void k_scan2() {
    __shared__ int sh[512];
    int t = threadIdx.x, bid = blockIdx.x;
    int i = bid * 512 + t;
    int base = 0;
    for (int j = t; j < bid * 512; j += 512) base += d_ecnt[j];
    sh[t] = base;
    __syncthreads();
    for (int s = 256; s > 0; s >>= 1) {
        if (t < s) sh[t] += sh[t + s];
        __syncthreads();
    }
    base = sh[0];
    __syncthreads();
    int v = (i < NN) ? d_ecnt[i] : 0;
    sh[t] = v;
    __syncthreads();
    for (int off = 1; off < 512; off <<= 1) {
        int x = (t >= off) ? sh[t - off] : 0;
        __syncthreads();
        sh[t] += x;
        __syncthreads();
    }
    if (i < NN) {
        int excl = base + sh[t] - v;
        d_eoff[i] = excl;
        d_ecur[i] = excl;
        if (i == NN - 1) d_eoff[NN] = excl + v;
    }
}
// fill; also re-zeroes d_ecnt for the NEXT graph's hist (safe: scan already ran)
__global__ void k_fill(const int* __restrict__ ei) {
    int e = blockIdx.x * blockDim.x + threadIdx.x;
    if (e < NN) d_ecnt[e] = 0;
    if (e >= EE) return;
    int p = atomicAdd(&d_ecur[ei[EE + e]], 1);
    d_eidx[p] = ei[e];
}

// -------- gather: agg tile[row] = fp16(sum CSR ym rows), swizzled layout ----
__global__ void vspn_gather(const __half* __restrict__ ym,
                            __half* __restrict__ agg)
{
    int w = (blockIdx.x * blockDim.x + threadIdx.x) >> 5;   // padded node index
    if (w >= NPAD) return;
    int lane = threadIdx.x & 31;
    int lane4 = lane * 4;
    float4 s0 = make_float4(0.f, 0.f, 0.f, 0.f), s1 = s0, s2 = s0, s3 = s0;
    if (w < NN) {
        int e0 = d_eoff[w], e1 = d_eoff[w + 1];
        int e = e0;
        for (; e + 4 <= e1; e += 4) {
            int p0 = d_eidx[e], p1 = d_eidx[e + 1];
            int p2 = d_eidx[e + 2], p3 = d_eidx[e + 3];
            acc_row(s0, ym + (size_t)p0 * 128 + lane4);
            acc_row(s1, ym + (size_t)p1 * 128 + lane4);
            acc_row(s2, ym + (size_t)p2 * 128 + lane4);
            acc_row(s3, ym + (size_t)p3 * 128 + lane4);
        }
        for (; e < e1; e++)
            acc_row(s0, ym + (size_t)d_eidx[e] * 128 + lane4);
    }
    s0.x += s1.x + s2.x + s3.x;
    s0.y += s1.y + s2.y + s3.y;
    s0.z += s1.z + s2.z + s3.z;
    s0.w += s1.w + s2.w + s3.w;
    __half2 h0 = __floats2half2_rn(s0.x, s0.y);
    __half2 h1 = __floats2half2_rn(s0.z, s0.w);
    uint2 pk;
    pk.x = *reinterpret_cast<uint32_t*>(&h0);
    pk.y = *reinterpret_cast<uint32_t*>(&h1);
    char* dst = reinterpret_cast<char*>(agg) + (size_t)(w >> 7) * TILE + swz(w & 127, lane4);
    *reinterpret_cast<uint2*>(dst) = pk;
}

// ---------------- embed: ht = fp16tiles(relu(x@Wemb)); ym = fp16(h@W0) ------
#define SM_EMB (3 * TILE)
__global__ void __launch_bounds__(256, 1)
vspn_emb(const float* __restrict__ x, int Kin,
         const char* __restrict__ imgE, const char* __restrict__ imgM,
         __half* __restrict__ ht, __half* __restrict__ ym, int M)
{
    extern __shared__ char smem[];
    const int tid = threadIdx.x, lane = tid & 31, wid = tid >> 5;
    const int wr = wid & 3, wc = wid >> 2;
    const int arow = wr * 32 + (lane & 15), akl = (lane >> 4) << 3;
    const int brow = wc * 64 + ((lane >> 4) << 3) + (lane & 7), bkl = ((lane >> 3) & 1) << 3;
    const int rl0 = wr * 32 + (lane >> 2);
    const int cb  = wc * 64 + (lane & 3) * 2;
    const int node0 = blockIdx.x * 128;
    char* httile = reinterpret_cast<char*>(ht) + (size_t)blockIdx.x * TILE;

    uint32_t sA = smem_u32(smem), sB0 = sA + TILE, sB1 = sA + 2 * TILE;
    cp_tile(sB0, imgE, tid);
    cp_tile(sB1, imgM, tid);
    stage_A(x, Kin, M, node0, smem, tid);
    CP_WAIT(1);
    __syncthreads();

    float acc[2][8][4];
    zero_acc(acc);
    mma_pass(sA, sB0, arow, akl, brow, bkl, acc);
    __syncthreads();   // A consumed

    // h = relu(acc): write fp16 tile to gmem + restage into A slot
#pragma unroll
    for (int i = 0; i < 2; i++)
#pragma unroll
        for (int rr = 0; rr < 2; rr++) {
            int rl = rl0 + i * 16 + rr * 8;
            int node = node0 + rl;
            bool valid = node < M;
#pragma unroll
            for (int j = 0; j < 8; j++) {
                int c = cb + j * 8;
                float v0 = fmaxf(acc[i][j][rr * 2], 0.f);
                float v1 = fmaxf(acc[i][j][rr * 2 + 1], 0.f);
                __half2 h2 = __floats2half2_rn(v0, v1);
                uint32_t pk = *reinterpret_cast<uint32_t*>(&h2);
                *reinterpret_cast<uint32_t*>(smem + swz(rl, c)) = pk;
                if (valid)
                    *reinterpret_cast<uint32_t*>(httile + swz(rl, c)) = pk;
            }
        }
    CP_WAIT(0);
    __syncthreads();
    zero_acc(acc);
    mma_pass(sA, sB1, arow, akl, brow, bkl, acc);
#pragma unroll
    for (int i = 0; i < 2; i++)
#pragma unroll
        for (int rr = 0; rr < 2; rr++) {
            int node = node0 + rl0 + i * 16 + rr * 8;
            if (node >= M) continue;
#pragma unroll
            for (int j = 0; j < 8; j++) {
                int c = cb + j * 8;
                __half2 h2 = __floats2half2_rn(acc[i][j][rr * 2], acc[i][j][rr * 2 + 1]);
                *reinterpret_cast<uint32_t*>(ym + (size_t)node * 128 + c) =
                    *reinterpret_cast<uint32_t*>(&h2);
            }
        }
}

// ---------------- fused step: GRU(ht, agg) -> ht ; ym = fp16(h@W_next) ------
// 7-tile smem: deep prefetch of h, agg and 5 weight tiles at entry; only two
// mid-kernel reloads (B0<-Wih_z, B1<-W_m).
// groups: g1 sAh(h), g2 sA(agg), g3 B0=Whh_r, g4 B1=Wih_r, g5 B2=Whh_n,
//         g6 B3=Wih_n, g7 B4=Whh_z, g8 B0=Wih_z, g9 B1=W_m(or t0 dummy)
#define SM_STEP (7 * TILE)   // 224KB
__global__ void __launch_bounds__(256, 1)
vspn_step(const __half* __restrict__ agg, __half* __restrict__ ht,
          int mstep,
          const float* __restrict__ bih, const float* __restrict__ bhh,
          __half* __restrict__ ym)
{
    extern __shared__ char smem[];
    const int tid = threadIdx.x, lane = tid & 31, wid = tid >> 5;
    const int wr = wid & 3, wc = wid >> 2;
    const int arow = wr * 32 + (lane & 15), akl = (lane >> 4) << 3;
    const int brow = wc * 64 + ((lane >> 4) << 3) + (lane & 7), bkl = ((lane >> 3) & 1) << 3;
    const int rl0 = wr * 32 + (lane >> 2);
    const int cb  = wc * 64 + (lane & 3) * 2;
    const int node0 = blockIdx.x * 128;
    char* httile = reinterpret_cast<char*>(ht) + (size_t)blockIdx.x * TILE;

    uint32_t sA  = smem_u32(smem);
    uint32_t sAh = sA + TILE;
    uint32_t sB0 = sA + 2 * TILE;
    uint32_t sB1 = sA + 3 * TILE;
    uint32_t sB2 = sA + 4 * TILE;
    uint32_t sB3 = sA + 5 * TILE;
    uint32_t sB4 = sA + 6 * TILE;

    cp_tile(sAh, httile, tid);                                                 // g1
    cp_tile(sA, reinterpret_cast<const char*>(agg) + (size_t)blockIdx.x * TILE, tid); // g2
    cp_tile(sB0, d_img + 4 * TILE, tid);   // g3: Whh_r
    cp_tile(sB1, d_img + 7 * TILE, tid);   // g4: Wih_r
    cp_tile(sB2, d_img + 6 * TILE, tid);   // g5: Whh_n
    cp_tile(sB3, d_img + 9 * TILE, tid);   // g6: Wih_n
    cp_tile(sB4, d_img + 5 * TILE, tid);   // g7: Whh_z

    float acc[2][8][4], rg[2][8][4], ng[2][8][4];

    // ---- P0: gh_r (needs g1,g2,g3) ----
    CP_WAIT(4);
    __syncthreads();
    zero_acc(acc);
    mma_pass(sAh, sB0, arow, akl, brow, bkl, acc);
    // ---- P1: + gi_r -> r (needs g4) ; reload B0<-Wih_z after sync ----
    CP_WAIT(3);
    __syncthreads();
    cp_tile(sB0, d_img + 8 * TILE, tid);   // g8: Wih_z
    mma_pass(sA, sB1, arow, akl, brow, bkl, acc);
#pragma unroll
    for (int i = 0; i < 2; i++)
#pragma unroll
        for (int j = 0; j < 8; j++) {
            int c = cb + j * 8;
            float2 b1 = *reinterpret_cast<const float2*>(bih + c);
            float2 b2 = *reinterpret_cast<const float2*>(bhh + c);
#pragma unroll
            for (int rr = 0; rr < 2; rr++) {
                rg[i][j][rr * 2]     = sigm(acc[i][j][rr * 2]     + b1.x + b2.x);
                rg[i][j][rr * 2 + 1] = sigm(acc[i][j][rr * 2 + 1] + b1.y + b2.y);
            }
        }
    // ---- P2: gh_n (needs g5) ; reload B1<-W_m after sync ----
    CP_WAIT(3);
    __syncthreads();
    cp_tile(sB1, d_img + (size_t)((mstep >= 0) ? mstep : 0) * TILE, tid);   // g9
    zero_acc(acc);
    mma_pass(sAh, sB2, arow, akl, brow, bkl, acc);
#pragma unroll
    for (int i = 0; i < 2; i++)
#pragma unroll
        for (int j = 0; j < 8; j++) {
            int c = cb + j * 8;
            float2 b1 = *reinterpret_cast<const float2*>(bih + 256 + c);
            float2 b2 = *reinterpret_cast<const float2*>(bhh + 256 + c);
#pragma unroll
            for (int rr = 0; rr < 2; rr++) {
                acc[i][j][rr * 2]     = rg[i][j][rr * 2]     * (acc[i][j][rr * 2]     + b2.x) + b1.x;
                acc[i][j][rr * 2 + 1] = rg[i][j][rr * 2 + 1] * (acc[i][j][rr * 2 + 1] + b2.y) + b1.y;
            }
        }
    // ---- P3: + gi_n -> n (needs g6) ----
    CP_WAIT(3);
    __syncthreads();
    mma_pass(sA, sB3, arow, akl, brow, bkl, acc);
#pragma unroll
    for (int i = 0; i < 2; i++)
#pragma unroll
        for (int j = 0; j < 8; j++)
#pragma unroll
            for (int q = 0; q < 4; q++) ng[i][j][q] = tanh_ap(acc[i][j][q]);
    // ---- P4: gh_z (needs g7) ----
    CP_WAIT(2);
    __syncthreads();
    zero_acc(acc);
    mma_pass(sAh, sB4, arow, akl, brow, bkl, acc);
    // ---- P5: + gi_z -> z (needs g8) ; combine; restage h_new into sA ----
    CP_WAIT(1);
    __syncthreads();
    mma_pass(sA, sB0, arow, akl, brow, bkl, acc);
    __syncthreads();   // all warps done reading sA
#pragma unroll
    for (int i = 0; i < 2; i++)
#pragma unroll
        for (int rr = 0; rr < 2; rr++) {
            int rl = rl0 + i * 16 + rr * 8;
            int node = node0 + rl;
            bool valid = node < NN;
#pragma unroll
            for (int j = 0; j < 8; j++) {
                int c = cb + j * 8;
                float2 b1 = *reinterpret_cast<const float2*>(bih + 128 + c);
                float2 b2 = *reinterpret_cast<const float2*>(bhh + 128 + c);
                float z0 = sigm(acc[i][j][rr * 2]     + b1.x + b2.x);
                float z1 = sigm(acc[i][j][rr * 2 + 1] + b1.y + b2.y);
                uint32_t hw = *reinterpret_cast<uint32_t*>(smem + TILE + swz(rl, c));
                float2 hp = __half22float2(*reinterpret_cast<__half2*>(&hw));
                float h0 = (1.f - z0) * ng[i][j][rr * 2]     + z0 * hp.x;
                float h1 = (1.f - z1) * ng[i][j][rr * 2 + 1] + z1 * hp.y;
                __half2 hh = __floats2half2_rn(h0, h1);
                uint32_t pk = *reinterpret_cast<uint32_t*>(&hh);
                *reinterpret_cast<uint32_t*>(smem + swz(rl, c)) = pk;
                if (valid)
                    *reinterpret_cast<uint32_t*>(httile + swz(rl, c)) = pk;
            }
        }

    // ---- P6: ym = fp16(h_new @ W[mstep]) (needs g9) ----
    if (mstep >= 0) {
        CP_WAIT(0);
        __syncthreads();
        zero_acc(acc);
        mma_pass(sA, sB1, arow, akl, brow, bkl, acc);
#pragma unroll
        for (int i = 0; i < 2; i++)
#pragma unroll
            for (int rr = 0; rr < 2; rr++) {
                int node = node0 + rl0 + i * 16 + rr * 8;
                if (node >= NN) continue;
#pragma unroll
                for (int j = 0; j < 8; j++) {
                    int c = cb + j * 8;
                    __half2 h2 = __floats2half2_rn(acc[i][j][rr * 2], acc[i][j][rr * 2 + 1]);
                    *reinterpret_cast<uint32_t*>(ym + (size_t)node * 128 + c) =
                        *reinterpret_cast<uint32_t*>(&h2);
                }
            }
    }
}

// ---------------- pool: pool[b] += relu(h[n]), cnt[b] += 1 (fp16 tiles) -----
__global__ void vspn_pool(const __half* __restrict__ ht, const int* __restrict__ batch,
                          float* __restrict__ pool, float* __restrict__ cnt, int Nn)
{
    __shared__ int sbh[128];
    int j  = threadIdx.x;
    int n0 = blockIdx.x * 128;
    int nend = min(n0 + 128, Nn);
    int cn = nend - n0;
    if (n0 + j < Nn) sbh[j] = batch[n0 + j];
    __syncthreads();
    const char* tb = reinterpret_cast<const char*>(ht) + (size_t)blockIdx.x * TILE;
    float sum = 0.f, rc = 0.f;
    int cur = sbh[0];
    for (int t = 0; t < cn; t++) {
        int b = sbh[t];
        if (b != cur) {
            atomicAdd(&pool[(size_t)cur * HH + j], sum);
            if (j == 0) atomicAdd(&cnt[cur], rc);
            sum = 0.f; rc = 0.f; cur = b;
        }
        float v = __half2float(*reinterpret_cast<const __half*>(tb + swz(t, j)));
        sum += fmaxf(v, 0.f);
        rc += 1.f;
    }
    atomicAdd(&pool[(size_t)cur * HH + j], sum);
    if (j == 0) atomicAdd(&cnt[cur], rc);
}

// ---------------- head ------------------------------------------------------
__global__ void vspn_head(const float* __restrict__ W1, const float* __restrict__ b1,
                          const float* __restrict__ W2, const float* __restrict__ b2,
                          float* __restrict__ out)
{
    int g = blockIdx.x;
    int k = threadIdx.x;
    __shared__ float gsh[256];
    __shared__ float tsh[256];
    float cb = fmaxf(d_cnt[g], 1.f);
    float cv = fmaxf(d_cnt[GG + g], 1.f);
    if (k < HH) gsh[k] = d_pool[(size_t)g * HH + k] / cb;
    else        gsh[k] = d_pool[(size_t)(GG + g) * HH + (k - HH)] / cv;
    __syncthreads();
    float acc = b1[k];
    for (int j = 0; j < 256; j++) acc += gsh[j] * W1[j * 256 + k];
    float t = fmaxf(acc, 0.f);
    tsh[k] = t * W2[k];
    __syncthreads();
    for (int s = 128; s > 0; s >>= 1) {
        if (k < s) tsh[k] += tsh[k + s];
        __syncthreads();
    }
    if (k == 0) {
        float x = tsh[0] + b2[0];
        out[g] = fmaxf(x, 0.f) + log1pf(expf(-fabsf(x)));
    }
}

// ---------------- launch ----------------------------------------------------
extern "C" void kernel_launch(void* const* d_in, const int* in_sizes, int n_in,
                              void* d_out, int out_size)
{
    const float* x_b   = (const float*)d_in[0];
    const int*   ei_b  = (const int*)  d_in[1];
    const int*   bat_b = (const int*)  d_in[2];
    const float* x_v   = (const float*)d_in[3];
    const int*   ei_v  = (const int*)  d_in[4];
    const int*   bat_v = (const int*)  d_in[5];
    const float* Wemb_b= (const float*)d_in[6];
    const float* Wemb_v= (const float*)d_in[7];
    const float* ggc   = (const float*)d_in[8];
    const float* w_ih  = (const float*)d_in[9];
    const float* w_hh  = (const float*)d_in[10];
    const float* b_ih  = (const float*)d_in[11];
    const float* b_hh  = (const float*)d_in[12];
    const float* W1    = (const float*)d_in[13];
    const float* b1    = (const float*)d_in[14];
    const float* W2    = (const float*)d_in[15];
    const float* b2    = (const float*)d_in[16];
    float* out = (float*)d_out;

    const int FB = in_sizes[0] / NN;
    const int FV = in_sizes[3] / NN;

    float *p_pool, *p_cnt;
    __half *p_ht, *p_ym, *p_agg;
    char* p_img;
    cudaGetSymbolAddress((void**)&p_ht,   d_ht);
    cudaGetSymbolAddress((void**)&p_ym,   d_ym);
    cudaGetSymbolAddress((void**)&p_agg,  d_agg);
    cudaGetSymbolAddress((void**)&p_img,  d_img);
    cudaGetSymbolAddress((void**)&p_pool, d_pool);
    cudaGetSymbolAddress((void**)&p_cnt,  d_cnt);

    cudaFuncSetAttribute(vspn_emb,  cudaFuncAttributeMaxDynamicSharedMemorySize, SM_EMB);
    cudaFuncSetAttribute(vspn_step, cudaFuncAttributeMaxDynamicSharedMemorySize, SM_STEP);

    // launch 0: weights + zero pool/cnt/ecnt/ht-pad
    vspn_prep<<<(12 * 16384 + 255) / 256, 256>>>(ggc, w_ih, w_hh, Wemb_b, Wemb_v, FB, FV);

    const int EB = (EE + 255) / 256;
    const int GB = (NPAD * 32 + 255) / 256;
    const int poolBlocks = (NN + 127) / 128;

    for (int graph = 0; graph < 2; graph++) {
        const float* x   = graph ? x_v   : x_b;
        const int*   ei  = graph ? ei_v  : ei_b;
        const int*   bat = graph ? bat_v : bat_b;
        const int    F   = graph ? FV    : FB;

        // CSR build (ecnt pre-zeroed by prep / previous k_fill)
        k_hist<<<EB, 256>>>(ei);
        k_scan2<<<NB_SCAN, 512>>>();
        k_fill<<<EB, 256>>>(ei);

        // embed + step-0 messages
        vspn_emb<<<MT, 256, SM_EMB>>>(x, F, p_img + (size_t)(10 + graph) * TILE,
                                      p_img, p_ht, p_ym, NN);
        // steps
        for (int s = 0; s < STEPS; s++) {
            vspn_gather<<<GB, 256>>>(p_ym, p_agg);
            int mstep = (s < STEPS - 1) ? (s + 1) : -1;
            vspn_step<<<MT, 256, SM_STEP>>>(p_agg, p_ht, mstep, b_ih, b_hh, p_ym);
        }
        vspn_pool<<<poolBlocks, 128>>>(p_ht, bat,
                                       p_pool + (size_t)graph * GG * HH,
                                       p_cnt + graph * GG, NN);
    }

    vspn_head<<<GG, 256>>>(W1, b1, W2, b2, out);
}

// round 14
// speedup vs baseline: 6.4435x; 1.0643x over previous
#include <cuda_runtime.h>
#include <cuda_fp16.h>
#include <cstdint>
#include <math.h>

#define NN 100000
#define EE 600000
#define GG 64
#define HH 128
#define STEPS 4
#define NB_SCAN 196   // ceil(NN/512)
#define TILE 32768    // fp16 128x128 tile bytes
#define MT 782        // ceil(NN/128)
#define NPAD (MT * 128)   // 100096

// ---------------- scratch (device globals; per-graph doubled) ---------------
__device__ __align__(256) __half d_ht [2 * (size_t)MT * 16384];  // hidden tiles
__device__ __align__(256) __half d_ym [2 * (size_t)NN * HH];     // messages
__device__ __align__(256) __half d_agg[2 * (size_t)MT * 16384];  // gathered tiles
// Pre-swizzled fp16 weight tiles, 32KB each:
//  t0..3 : W_s ; t4..6 : Whh r,z,n ; t7..9 : Wih r,z,n ; t10,11 : emb b,v
__device__ __align__(256) char  d_img[12 * TILE];
__device__ __align__(256) float d_pool[2 * GG * HH];
__device__ __align__(256) float d_cnt [2 * GG];
// CSR scratch (per-graph; d_ecnt zeroed by prep each launch)
__device__ int d_ecnt[2 * NN];
__device__ int d_ecur[2 * NN];
__device__ int d_eoff[2 * (NN + 1)];
__device__ int d_eidx[2 * EE];

// ---------------- helpers ---------------------------------------------------
__device__ __forceinline__ uint32_t smem_u32(const void* p) {
    uint32_t a;
    asm("{ .reg .u64 t; cvta.to.shared.u64 t, %1; cvt.u32.u64 %0, t; }" : "=r"(a) : "l"(p));
    return a;
}
__host__ __device__ __forceinline__ uint32_t swz(int row, int k) {
    return (uint32_t)(row * 256 + ((((k >> 3) ^ (row & 7)) << 4) | ((k & 7) << 1)));
}
__device__ __forceinline__ float tanh_ap(float x) {
    float y;
    asm("tanh.approx.f32 %0, %1;" : "=f"(y) : "f"(x));
    return y;
}
__device__ __forceinline__ float sigm(float x) {
    return fmaf(tanh_ap(x * 0.5f), 0.5f, 0.5f);
}

#define LDSM4(R0, R1, R2, R3, ADDR) \
    asm volatile("ldmatrix.sync.aligned.m8n8.x4.shared.b16 {%0,%1,%2,%3}, [%4];" \
                 : "=r"(R0), "=r"(R1), "=r"(R2), "=r"(R3) : "r"(ADDR))

#define MMA16816(D, A0, A1, A2, A3, B0, B1) \
    asm volatile("mma.sync.aligned.m16n8k16.row.col.f32.f16.f16.f32 " \
                 "{%0,%1,%2,%3}, {%4,%5,%6,%7}, {%8,%9}, {%0,%1,%2,%3};" \
                 : "+f"((D)[0]), "+f"((D)[1]), "+f"((D)[2]), "+f"((D)[3]) \
                 : "r"(A0), "r"(A1), "r"(A2), "r"(A3), "r"(B0), "r"(B1))

// cp.async a 32KB tile (all 256 threads), one commit group
__device__ __forceinline__ void cp_tile(uint32_t dst, const char* __restrict__ src, int tid) {
#pragma unroll
    for (int i = 0; i < 8; i++) {
        uint32_t d = dst + tid * 16 + i * 4096;
        const char* s = src + tid * 16 + i * 4096;
        asm volatile("cp.async.cg.shared.global [%0], [%1], 16;" :: "r"(d), "l"(s));
    }
    asm volatile("cp.async.commit_group;");
}
#define CP_WAIT(n) asm volatile("cp.async.wait_group %0;" :: "n"(n))

// one 128x128x128 fp16 MMA pass accumulating into acc
__device__ __forceinline__ void mma_pass(uint32_t sA, uint32_t sB,
                                         int arow, int akl, int brow, int bkl,
                                         float (&acc)[2][8][4])
{
#pragma unroll
    for (int ks = 0; ks < 8; ks++) {
        const int kk = ks * 16;
        uint32_t a0[4], a1[4];
        LDSM4(a0[0], a0[1], a0[2], a0[3], sA + swz(arow,      kk + akl));
        LDSM4(a1[0], a1[1], a1[2], a1[3], sA + swz(arow + 16, kk + akl));
#pragma unroll
        for (int nb = 0; nb < 4; nb++) {
            uint32_t bh[4];
            LDSM4(bh[0], bh[1], bh[2], bh[3], sB + swz(brow + nb * 16, kk + bkl));
            int j0 = nb * 2;
            MMA16816(acc[0][j0],     a0[0], a0[1], a0[2], a0[3], bh[0], bh[1]);
            MMA16816(acc[1][j0],     a1[0], a1[1], a1[2], a1[3], bh[0], bh[1]);
            MMA16816(acc[0][j0 + 1], a0[0], a0[1], a0[2], a0[3], bh[2], bh[3]);
            MMA16816(acc[1][j0 + 1], a1[0], a1[1], a1[2], a1[3], bh[2], bh[3]);
        }
    }
}

__device__ __forceinline__ void zero_acc(float (&acc)[2][8][4]) {
#pragma unroll
    for (int i = 0; i < 2; i++)
#pragma unroll
        for (int j = 0; j < 8; j++)
#pragma unroll
            for (int q = 0; q < 4; q++) acc[i][j][q] = 0.f;
}

// stage fp32 A[rows at row0.., Kin<=128] -> fp16 swizzled smem tile
__device__ __forceinline__ void stage_A(const float* __restrict__ A, int Kin, int Mlim,
                                        int row0, char* dst, int tid)
{
    int r = tid >> 1;
    int hf = tid & 1;
    int row = row0 + r;
    bool valid = row < Mlim;
    const float* ap = A + (size_t)row * Kin;
#pragma unroll
    for (int i = 0; i < 8; i++) {
        int k0 = hf * 64 + i * 8;
        float v[8];
#pragma unroll
        for (int q = 0; q < 8; q++) {
            int k = k0 + q;
            v[q] = (valid && k < Kin) ? ap[k] : 0.f;
        }
        uint32_t p[4];
#pragma unroll
        for (int q = 0; q < 4; q++) {
            __half2 h2 = __floats2half2_rn(v[2 * q], v[2 * q + 1]);
            p[q] = *reinterpret_cast<uint32_t*>(&h2);
        }
        *reinterpret_cast<uint4*>(dst + swz(r, k0)) = make_uint4(p[0], p[1], p[2], p[3]);
    }
}

__device__ __forceinline__ void acc_row(float4& s, const __half* __restrict__ p) {
    uint2 v = *reinterpret_cast<const uint2*>(p);
    float2 a = __half22float2(*reinterpret_cast<__half2*>(&v.x));
    float2 b = __half22float2(*reinterpret_cast<__half2*>(&v.y));
    s.x += a.x; s.y += a.y; s.z += b.x; s.w += b.y;
}

// ------- prep: fp16 weight tiles + zero pool/cnt/ecnt(x2)/ht-pad(x2) --------
__global__ void vspn_prep(const float* __restrict__ ggc,   // [4,128,128]
                          const float* __restrict__ wih,   // [384,128]
                          const float* __restrict__ whh,   // [384,128]
                          const float* __restrict__ wembB, // [FB,128]
                          const float* __restrict__ wembV, // [FV,128]
                          int FB, int FV)
{
    int idx = blockIdx.x * blockDim.x + threadIdx.x;
    if (idx < 2 * GG * HH) d_pool[idx] = 0.f;
    if (idx < 2 * GG) d_cnt[idx] = 0.f;
    if (idx < 2 * NN) d_ecnt[idx] = 0;
    if (idx < 2 * 16384) {
        int g = idx >> 14, off = idx & 16383;
        d_ht[(size_t)g * MT * 16384 + (size_t)(MT - 1) * 16384 + off] = __float2half(0.f);
    }
    if (idx >= 12 * 16384) return;
    int t = idx / 16384;
    int e = idx % 16384;
    int n = e >> 7;
    int k = e & 127;
    float v = 0.f;
    if (t < 4) {
        v = ggc[(t * 128 + k) * 128 + n];
    } else if (t < 7) {
        int g = t - 4;
        v = whh[(size_t)(g * 128 + n) * 128 + k];
    } else if (t < 10) {
        int g = t - 7;
        v = wih[(size_t)(g * 128 + n) * 128 + k];
    } else if (t == 10) {
        v = (k < FB) ? wembB[(size_t)k * 128 + n] : 0.f;
    } else {
        v = (k < FV) ? wembV[(size_t)k * 128 + n] : 0.f;
    }
    *(__half*)(d_img + (size_t)t * TILE + swz(n, k)) = __float2half_rn(v);
}

// ---------------- CSR build (per graph; hist->scan->fill) -------------------
__global__ void k_hist(const int* __restrict__ ei, int* __restrict__ ecnt) {
    int e = blockIdx.x * blockDim.x + threadIdx.x;
    if (e < EE) atomicAdd(&ecnt[ei[EE + e]], 1);
}
// fused scan: per-block base by summing preceding counts (read-only on ecnt)
__global__ void k_scan2(const int* __restrict__ ecnt,
                        int* __restrict__ eoff, int* __restrict__ ecur) {
    __shared__ int sh[512];
    int t = threadIdx.x, bid = blockIdx.x;
    int i = bid * 512 + t;
    int base = 0;
    for (int j = t; j < bid * 512; j += 512) base += ecnt[j];
    sh[t] = base;
    __syncthreads();
    for (int s = 256; s > 0; s >>= 1) {
        if (t < s) sh[t] += sh[t + s];
        __syncthreads();
    }
    base = sh[0];
    __syncthreads();
    int v = (i < NN) ? ecnt[i] : 0;
    sh[t] = v;
    __syncthreads();
    for (int off = 1; off < 512; off <<= 1) {
        int x = (t >= off) ? sh[t - off] : 0;
        __syncthreads();
        sh[t] += x;
        __syncthreads();
    }
    if (i < NN) {
        int excl = base + sh[t] - v;
        eoff[i] = excl;
        ecur[i] = excl;
        if (i == NN - 1) eoff[NN] = excl + v;
    }
}
__global__ void k_fill(const int* __restrict__ ei,
                       int* __restrict__ ecur, int* __restrict__ eidx) {
    int e = blockIdx.x * blockDim.x + threadIdx.x;
    if (e >= EE) return;
    int p = atomicAdd(&ecur[ei[EE + e]], 1);
    eidx[p] = ei[e];
}

// -------- gather: agg tile[row] = fp16(sum CSR ym rows), swizzled layout ----
__global__ void vspn_gather(const __half* __restrict__ ym,
                            __half* __restrict__ agg,
                            const int* __restrict__ eoff,
                            const int* __restrict__ eidx)
{
    int w = (blockIdx.x * blockDim.x + threadIdx.x) >> 5;   // padded node index
    if (w >= NPAD) return;
    int lane = threadIdx.x & 31;
    int lane4 = lane * 4;
    float4 s0 = make_float4(0.f, 0.f, 0.f, 0.f), s1 = s0, s2 = s0, s3 = s0;
    if (w < NN) {
        int e0 = eoff[w], e1 = eoff[w + 1];
        int e = e0;
        for (; e + 4 <= e1; e += 4) {
            int p0 = eidx[e], p1 = eidx[e + 1];
            int p2 = eidx[e + 2], p3 = eidx[e + 3];
            acc_row(s0, ym + (size_t)p0 * 128 + lane4);
            acc_row(s1, ym + (size_t)p1 * 128 + lane4);
            acc_row(s2, ym + (size_t)p2 * 128 + lane4);
            acc_row(s3, ym + (size_t)p3 * 128 + lane4);
        }
        for (; e < e1; e++)
            acc_row(s0, ym + (size_t)eidx[e] * 128 + lane4);
    }
    s0.x += s1.x + s2.x + s3.x;
    s0.y += s1.y + s2.y + s3.y;
    s0.z += s1.z + s2.z + s3.z;
    s0.w += s1.w + s2.w + s3.w;
    __half2 h0 = __floats2half2_rn(s0.x, s0.y);
    __half2 h1 = __floats2half2_rn(s0.z, s0.w);
    uint2 pk;
    pk.x = *reinterpret_cast<uint32_t*>(&h0);
    pk.y = *reinterpret_cast<uint32_t*>(&h1);
    char* dst = reinterpret_cast<char*>(agg) + (size_t)(w >> 7) * TILE + swz(w & 127, lane4);
    *reinterpret_cast<uint2*>(dst) = pk;
}

// ---------------- embed: ht = fp16tiles(relu(x@Wemb)); ym = fp16(h@W0) ------
#define SM_EMB (3 * TILE)
__global__ void __launch_bounds__(256, 1)
vspn_emb(const float* __restrict__ x, int Kin,
         const char* __restrict__ imgE, const char* __restrict__ imgM,
         __half* __restrict__ ht, __half* __restrict__ ym, int M)
{
    extern __shared__ char smem[];
    const int tid = threadIdx.x, lane = tid & 31, wid = tid >> 5;
    const int wr = wid & 3, wc = wid >> 2;
    const int arow = wr * 32 + (lane & 15), akl = (lane >> 4) << 3;
    const int brow = wc * 64 + ((lane >> 4) << 3) + (lane & 7), bkl = ((lane >> 3) & 1) << 3;
    const int rl0 = wr * 32 + (lane >> 2);
    const int cb  = wc * 64 + (lane & 3) * 2;
    const int node0 = blockIdx.x * 128;
    char* httile = reinterpret_cast<char*>(ht) + (size_t)blockIdx.x * TILE;

    uint32_t sA = smem_u32(smem), sB0 = sA + TILE, sB1 = sA + 2 * TILE;
    cp_tile(sB0, imgE, tid);
    cp_tile(sB1, imgM, tid);
    stage_A(x, Kin, M, node0, smem, tid);
    CP_WAIT(1);
    __syncthreads();

    float acc[2][8][4];
    zero_acc(acc);
    mma_pass(sA, sB0, arow, akl, brow, bkl, acc);
    __syncthreads();   // A consumed

    // h = relu(acc): write fp16 tile to gmem + restage into A slot
#pragma unroll
    for (int i = 0; i < 2; i++)
#pragma unroll
        for (int rr = 0; rr < 2; rr++) {
            int rl = rl0 + i * 16 + rr * 8;
            int node = node0 + rl;
            bool valid = node < M;
#pragma unroll
            for (int j = 0; j < 8; j++) {
                int c = cb + j * 8;
                float v0 = fmaxf(acc[i][j][rr * 2], 0.f);
                float v1 = fmaxf(acc[i][j][rr * 2 + 1], 0.f);
                __half2 h2 = __floats2half2_rn(v0, v1);
                uint32_t pk = *reinterpret_cast<uint32_t*>(&h2);
                *reinterpret_cast<uint32_t*>(smem + swz(rl, c)) = pk;
                if (valid)
                    *reinterpret_cast<uint32_t*>(httile + swz(rl, c)) = pk;
            }
        }
    CP_WAIT(0);
    __syncthreads();
    zero_acc(acc);
    mma_pass(sA, sB1, arow, akl, brow, bkl, acc);
#pragma unroll
    for (int i = 0; i < 2; i++)
#pragma unroll
        for (int rr = 0; rr < 2; rr++) {
            int node = node0 + rl0 + i * 16 + rr * 8;
            if (node >= M) continue;
#pragma unroll
            for (int j = 0; j < 8; j++) {
                int c = cb + j * 8;
                __half2 h2 = __floats2half2_rn(acc[i][j][rr * 2], acc[i][j][rr * 2 + 1]);
                *reinterpret_cast<uint32_t*>(ym + (size_t)node * 128 + c) =
                    *reinterpret_cast<uint32_t*>(&h2);
            }
        }
}

// ---------------- fused step: GRU(ht, agg) -> ht ; ym = fp16(h@W_next) ------
// 7-tile smem deep prefetch (identical to R13).
#define SM_STEP (7 * TILE)   // 224KB
__global__ void __launch_bounds__(256, 1)
vspn_step(const __half* __restrict__ agg, __half* __restrict__ ht,
          int mstep,
          const float* __restrict__ bih, const float* __restrict__ bhh,
          __half* __restrict__ ym)
{
    extern __shared__ char smem[];
    const int tid = threadIdx.x, lane = tid & 31, wid = tid >> 5;
    const int wr = wid & 3, wc = wid >> 2;
    const int arow = wr * 32 + (lane & 15), akl = (lane >> 4) << 3;
    const int brow = wc * 64 + ((lane >> 4) << 3) + (lane & 7), bkl = ((lane >> 3) & 1) << 3;
    const int rl0 = wr * 32 + (lane >> 2);
    const int cb  = wc * 64 + (lane & 3) * 2;
    const int node0 = blockIdx.x * 128;
    char* httile = reinterpret_cast<char*>(ht) + (size_t)blockIdx.x * TILE;

    uint32_t sA  = smem_u32(smem);
    uint32_t sAh = sA + TILE;
    uint32_t sB0 = sA + 2 * TILE;
    uint32_t sB1 = sA + 3 * TILE;
    uint32_t sB2 = sA + 4 * TILE;
    uint32_t sB3 = sA + 5 * TILE;
    uint32_t sB4 = sA + 6 * TILE;

    cp_tile(sAh, httile, tid);                                                 // g1
    cp_tile(sA, reinterpret_cast<const char*>(agg) + (size_t)blockIdx.x * TILE, tid); // g2
    cp_tile(sB0, d_img + 4 * TILE, tid);   // g3: Whh_r
    cp_tile(sB1, d_img + 7 * TILE, tid);   // g4: Wih_r
    cp_tile(sB2, d_img + 6 * TILE, tid);   // g5: Whh_n
    cp_tile(sB3, d_img + 9 * TILE, tid);   // g6: Wih_n
    cp_tile(sB4, d_img + 5 * TILE, tid);   // g7: Whh_z

    float acc[2][8][4], rg[2][8][4], ng[2][8][4];

    // ---- P0: gh_r (needs g1,g2,g3) ----
    CP_WAIT(4);
    __syncthreads();
    zero_acc(acc);
    mma_pass(sAh, sB0, arow, akl, brow, bkl, acc);
    // ---- P1: + gi_r -> r (needs g4) ; reload B0<-Wih_z after sync ----
    CP_WAIT(3);
    __syncthreads();
    cp_tile(sB0, d_img + 8 * TILE, tid);   // g8: Wih_z
    mma_pass(sA, sB1, arow, akl, brow, bkl, acc);
#pragma unroll
    for (int i = 0; i < 2; i++)
#pragma unroll
        for (int j = 0; j < 8; j++) {
            int c = cb + j * 8;
            float2 b1 = *reinterpret_cast<const float2*>(bih + c);
            float2 b2 = *reinterpret_cast<const float2*>(bhh + c);
#pragma unroll
            for (int rr = 0; rr < 2; rr++) {
                rg[i][j][rr * 2]     = sigm(acc[i][j][rr * 2]     + b1.x + b2.x);
                rg[i][j][rr * 2 + 1] = sigm(acc[i][j][rr * 2 + 1] + b1.y + b2.y);
            }
        }
    // ---- P2: gh_n (needs g5) ; reload B1<-W_m after sync ----
    CP_WAIT(3);
    __syncthreads();
    cp_tile(sB1, d_img + (size_t)((mstep >= 0) ? mstep : 0) * TILE, tid);   // g9
    zero_acc(acc);
    mma_pass(sAh, sB2, arow, akl, brow, bkl, acc);
#pragma unroll
    for (int i = 0; i < 2; i++)
#pragma unroll
        for (int j = 0; j < 8; j++) {
            int c = cb + j * 8;
            float2 b1 = *reinterpret_cast<const float2*>(bih + 256 + c);
            float2 b2 = *reinterpret_cast<const float2*>(bhh + 256 + c);
#pragma unroll
            for (int rr = 0; rr < 2; rr++) {
                acc[i][j][rr * 2]     = rg[i][j][rr * 2]     * (acc[i][j][rr * 2]     + b2.x) + b1.x;
                acc[i][j][rr * 2 + 1] = rg[i][j][rr * 2 + 1] * (acc[i][j][rr * 2 + 1] + b2.y) + b1.y;
            }
        }
    // ---- P3: + gi_n -> n (needs g6) ----
    CP_WAIT(3);
    __syncthreads();
    mma_pass(sA, sB3, arow, akl, brow, bkl, acc);
#pragma unroll
    for (int i = 0; i < 2; i++)
#pragma unroll
        for (int j = 0; j < 8; j++)
#pragma unroll
            for (int q = 0; q < 4; q++) ng[i][j][q] = tanh_ap(acc[i][j][q]);
    // ---- P4: gh_z (needs g7) ----
    CP_WAIT(2);
    __syncthreads();
    zero_acc(acc);
    mma_pass(sAh, sB4, arow, akl, brow, bkl, acc);
    // ---- P5: + gi_z -> z (needs g8) ; combine; restage h_new into sA ----
    CP_WAIT(1);
    __syncthreads();
    mma_pass(sA, sB0, arow, akl, brow, bkl, acc);
    __syncthreads();   // all warps done reading sA
#pragma unroll
    for (int i = 0; i < 2; i++)
#pragma unroll
        for (int rr = 0; rr < 2; rr++) {
            int rl = rl0 + i * 16 + rr * 8;
            int node = node0 + rl;
            bool valid = node < NN;
#pragma unroll
            for (int j = 0; j < 8; j++) {
                int c = cb + j * 8;
                float2 b1 = *reinterpret_cast<const float2*>(bih + 128 + c);
                float2 b2 = *reinterpret_cast<const float2*>(bhh + 128 + c);
                float z0 = sigm(acc[i][j][rr * 2]     + b1.x + b2.x);
                float z1 = sigm(acc[i][j][rr * 2 + 1] + b1.y + b2.y);
                uint32_t hw = *reinterpret_cast<uint32_t*>(smem + TILE + swz(rl, c));
                float2 hp = __half22float2(*reinterpret_cast<__half2*>(&hw));
                float h0 = (1.f - z0) * ng[i][j][rr * 2]     + z0 * hp.x;
                float h1 = (1.f - z1) * ng[i][j][rr * 2 + 1] + z1 * hp.y;
                __half2 hh = __floats2half2_rn(h0, h1);
                uint32_t pk = *reinterpret_cast<uint32_t*>(&hh);
                *reinterpret_cast<uint32_t*>(smem + swz(rl, c)) = pk;
                if (valid)
                    *reinterpret_cast<uint32_t*>(httile + swz(rl, c)) = pk;
            }
        }

    // ---- P6: ym = fp16(h_new @ W[mstep]) (needs g9) ----
    if (mstep >= 0) {
        CP_WAIT(0);
        __syncthreads();
        zero_acc(acc);
        mma_pass(sA, sB1, arow, akl, brow, bkl, acc);
#pragma unroll
        for (int i = 0; i < 2; i++)
#pragma unroll
            for (int rr = 0; rr < 2; rr++) {
                int node = node0 + rl0 + i * 16 + rr * 8;
                if (node >= NN) continue;
#pragma unroll
                for (int j = 0; j < 8; j++) {
                    int c = cb + j * 8;
                    __half2 h2 = __floats2half2_rn(acc[i][j][rr * 2], acc[i][j][rr * 2 + 1]);
                    *reinterpret_cast<uint32_t*>(ym + (size_t)node * 128 + c) =
                        *reinterpret_cast<uint32_t*>(&h2);
                }
            }
    }
}

// ---------------- pool: pool[b] += relu(h[n]), cnt[b] += 1 (fp16 tiles) -----
__global__ void vspn_pool(const __half* __restrict__ ht, const int* __restrict__ batch,
                          float* __restrict__ pool, float* __restrict__ cnt, int Nn)
{
    __shared__ int sbh[128];
    int j  = threadIdx.x;
    int n0 = blockIdx.x * 128;
    int nend = min(n0 + 128, Nn);
    int cn = nend - n0;
    if (n0 + j < Nn) sbh[j] = batch[n0 + j];
    __syncthreads();
    const char* tb = reinterpret_cast<const char*>(ht) + (size_t)blockIdx.x * TILE;
    float sum = 0.f, rc = 0.f;
    int cur = sbh[0];
    for (int t = 0; t < cn; t++) {
        int b = sbh[t];
        if (b != cur) {
            atomicAdd(&pool[(size_t)cur * HH + j], sum);
            if (j == 0) atomicAdd(&cnt[cur], rc);
            sum = 0.f; rc = 0.f; cur = b;
        }
        float v = __half2float(*reinterpret_cast<const __half*>(tb + swz(t, j)));
        sum += fmaxf(v, 0.f);
        rc += 1.f;
    }
    atomicAdd(&pool[(size_t)cur * HH + j], sum);
    if (j == 0) atomicAdd(&cnt[cur], rc);
}

// ---------------- head ------------------------------------------------------
__global__ void vspn_head(const float* __restrict__ W1, const float* __restrict__ b1,
                          const float* __restrict__ W2, const float* __restrict__ b2,
                          float* __restrict__ out)
{
    int g = blockIdx.x;
    int k = threadIdx.x;
    __shared__ float gsh[256];
    __shared__ float tsh[256];
    float cb = fmaxf(d_cnt[g], 1.f);
    float cv = fmaxf(d_cnt[GG + g], 1.f);
    if (k < HH) gsh[k] = d_pool[(size_t)g * HH + k] / cb;
    else        gsh[k] = d_pool[(size_t)(GG + g) * HH + (k - HH)] / cv;
    __syncthreads();
    float acc = b1[k];
    for (int j = 0; j < 256; j++) acc += gsh[j] * W1[j * 256 + k];
    float t = fmaxf(acc, 0.f);
    tsh[k] = t * W2[k];
    __syncthreads();
    for (int s = 128; s > 0; s >>= 1) {
        if (k < s) tsh[k] += tsh[k + s];
        __syncthreads();
    }
    if (k == 0) {
        float x = tsh[0] + b2[0];
        out[g] = fmaxf(x, 0.f) + log1pf(expf(-fabsf(x)));
    }
}

// ---------------- launch ----------------------------------------------------
extern "C" void kernel_launch(void* const* d_in, const int* in_sizes, int n_in,
                              void* d_out, int out_size)
{
    const float* x_b   = (const float*)d_in[0];
    const int*   ei_b  = (const int*)  d_in[1];
    const int*   bat_b = (const int*)  d_in[2];
    const float* x_v   = (const float*)d_in[3];
    const int*   ei_v  = (const int*)  d_in[4];
    const int*   bat_v = (const int*)  d_in[5];
    const float* Wemb_b= (const float*)d_in[6];
    const float* Wemb_v= (const float*)d_in[7];
    const float* ggc   = (const float*)d_in[8];
    const float* w_ih  = (const float*)d_in[9];
    const float* w_hh  = (const float*)d_in[10];
    const float* b_ih  = (const float*)d_in[11];
    const float* b_hh  = (const float*)d_in[12];
    const float* W1    = (const float*)d_in[13];
    const float* b1    = (const float*)d_in[14];
    const float* W2    = (const float*)d_in[15];
    const float* b2    = (const float*)d_in[16];
    float* out = (float*)d_out;

    const int FB = in_sizes[0] / NN;
    const int FV = in_sizes[3] / NN;

    float *p_pool, *p_cnt;
    __half *p_ht, *p_ym, *p_agg;
    char* p_img;
    int *p_ecnt, *p_ecur, *p_eoff, *p_eidx;
    cudaGetSymbolAddress((void**)&p_ht,   d_ht);
    cudaGetSymbolAddress((void**)&p_ym,   d_ym);
    cudaGetSymbolAddress((void**)&p_agg,  d_agg);
    cudaGetSymbolAddress((void**)&p_img,  d_img);
    cudaGetSymbolAddress((void**)&p_pool, d_pool);
    cudaGetSymbolAddress((void**)&p_cnt,  d_cnt);
    cudaGetSymbolAddress((void**)&p_ecnt, d_ecnt);
    cudaGetSymbolAddress((void**)&p_ecur, d_ecur);
    cudaGetSymbolAddress((void**)&p_eoff, d_eoff);
    cudaGetSymbolAddress((void**)&p_eidx, d_eidx);

    // one-time host-side resources (streams/events; no device memory)
    static cudaStream_t s2 = nullptr;
    static cudaEvent_t evA = nullptr, evB = nullptr;
    if (s2 == nullptr) {
        cudaStreamCreateWithFlags(&s2, cudaStreamNonBlocking);
        cudaEventCreateWithFlags(&evA, cudaEventDisableTiming);
        cudaEventCreateWithFlags(&evB, cudaEventDisableTiming);
        cudaFuncSetAttribute(vspn_emb,  cudaFuncAttributeMaxDynamicSharedMemorySize, SM_EMB);
        cudaFuncSetAttribute(vspn_step, cudaFuncAttributeMaxDynamicSharedMemorySize, SM_STEP);
    }

    // launch 0 (stream 0): weights + zero pool/cnt/ecnt/ht-pads
    vspn_prep<<<784, 256>>>(ggc, w_ih, w_hh, Wemb_b, Wemb_v, FB, FV);

    // fork second stream off the capture stream
    cudaEventRecord(evA, 0);
    cudaStreamWaitEvent(s2, evA, 0);

    const int EB = (EE + 255) / 256;
    const int GB = (NPAD * 32 + 255) / 256;
    const int poolBlocks = (NN + 127) / 128;

    for (int graph = 0; graph < 2; graph++) {
        cudaStream_t st = graph ? s2 : (cudaStream_t)0;
        const float* x   = graph ? x_v   : x_b;
        const int*   ei  = graph ? ei_v  : ei_b;
        const int*   bat = graph ? bat_v : bat_b;
        const int    F   = graph ? FV    : FB;
        __half* ht  = p_ht  + (size_t)graph * MT * 16384;
        __half* ym  = p_ym  + (size_t)graph * NN * HH;
        __half* agg = p_agg + (size_t)graph * MT * 16384;
        int* ecnt = p_ecnt + graph * NN;
        int* ecur = p_ecur + graph * NN;
        int* eoff = p_eoff + graph * (NN + 1);
        int* eidx = p_eidx + graph * EE;

        // CSR build
        k_hist<<<EB, 256, 0, st>>>(ei, ecnt);
        k_scan2<<<NB_SCAN, 512, 0, st>>>(ecnt, eoff, ecur);
        k_fill<<<EB, 256, 0, st>>>(ei, ecur, eidx);

        // embed + step-0 messages
        vspn_emb<<<MT, 256, SM_EMB, st>>>(x, F, p_img + (size_t)(10 + graph) * TILE,
                                          p_img, ht, ym, NN);
        // steps
        for (int s = 0; s < STEPS; s++) {
            vspn_gather<<<GB, 256, 0, st>>>(ym, agg, eoff, eidx);
            int mstep = (s < STEPS - 1) ? (s + 1) : -1;
            vspn_step<<<MT, 256, SM_STEP, st>>>(agg, ht, mstep, b_ih, b_hh, ym);
        }
        vspn_pool<<<poolBlocks, 128, 0, st>>>(ht, bat,
                                              p_pool + (size_t)graph * GG * HH,
                                              p_cnt + graph * GG, NN);
    }

    // join and run head on stream 0
    cudaEventRecord(evB, s2);
    cudaStreamWaitEvent((cudaStream_t)0, evB, 0);
    vspn_head<<<GG, 256>>>(W1, b1, W2, b2, out);
}

// round 16
// speedup vs baseline: 6.6507x; 1.0322x over previous
#include <cuda_runtime.h>
#include <cuda_fp16.h>
#include <cstdint>
#include <math.h>

#define NN 100000
#define EE 600000
#define GG 64
#define HH 128
#define STEPS 4
#define NB_SCAN 196   // ceil(NN/512)
#define TILE 32768    // fp16 128x128 tile bytes
#define MT 782        // ceil(NN/128)
#define NPAD (MT * 128)   // 100096

// ---------------- scratch (device globals; per-graph doubled) ---------------
__device__ __align__(256) __half d_ht  [2 * (size_t)MT * 16384];  // hidden tiles
__device__ __align__(256) __half d_hsum[2 * (size_t)MT * 16384];  // gathered-h tiles
// Pre-swizzled fp16 weight tiles, 32KB each:
//  t0..11 : C[s][gate] = W_s @ Wih_gate^T   (t = s*3 + g, g: 0=r 1=z 2=n)
//  t12..14: Whh r,z,n ;  t15,16: emb bond, voro
__device__ __align__(256) char  d_img[17 * TILE];
__device__ __align__(256) float d_pool[2 * GG * HH];
__device__ __align__(256) float d_cnt [2 * GG];
// CSR scratch (per-graph; d_ecnt zeroed by prep)
__device__ int d_ecnt[2 * NN];
__device__ int d_ecur[2 * NN];
__device__ int d_eoff[2 * (NN + 1)];
__device__ int d_eidx[2 * EE];

// ---------------- helpers ---------------------------------------------------
__device__ __forceinline__ uint32_t smem_u32(const void* p) {
    uint32_t a;
    asm("{ .reg .u64 t; cvta.to.shared.u64 t, %1; cvt.u32.u64 %0, t; }" : "=r"(a) : "l"(p));
    return a;
}
__host__ __device__ __forceinline__ uint32_t swz(int row, int k) {
    return (uint32_t)(row * 256 + ((((k >> 3) ^ (row & 7)) << 4) | ((k & 7) << 1)));
}
__device__ __forceinline__ float tanh_ap(float x) {
    float y;
    asm("tanh.approx.f32 %0, %1;" : "=f"(y) : "f"(x));
    return y;
}
__device__ __forceinline__ float sigm(float x) {
    return fmaf(tanh_ap(x * 0.5f), 0.5f, 0.5f);
}

#define LDSM4(R0, R1, R2, R3, ADDR) \
    asm volatile("ldmatrix.sync.aligned.m8n8.x4.shared.b16 {%0,%1,%2,%3}, [%4];" \
                 : "=r"(R0), "=r"(R1), "=r"(R2), "=r"(R3) : "r"(ADDR))

#define MMA16816(D, A0, A1, A2, A3, B0, B1) \
    asm volatile("mma.sync.aligned.m16n8k16.row.col.f32.f16.f16.f32 " \
                 "{%0,%1,%2,%3}, {%4,%5,%6,%7}, {%8,%9}, {%0,%1,%2,%3};" \
                 : "+f"((D)[0]), "+f"((D)[1]), "+f"((D)[2]), "+f"((D)[3]) \
                 : "r"(A0), "r"(A1), "r"(A2), "r"(A3), "r"(B0), "r"(B1))

// cp.async a 32KB tile (all 256 threads), one commit group
__device__ __forceinline__ void cp_tile(uint32_t dst, const char* __restrict__ src, int tid) {
#pragma unroll
    for (int i = 0; i < 8; i++) {
        uint32_t d = dst + tid * 16 + i * 4096;
        const char* s = src + tid * 16 + i * 4096;
        asm volatile("cp.async.cg.shared.global [%0], [%1], 16;" :: "r"(d), "l"(s));
    }
    asm volatile("cp.async.commit_group;");
}
#define CP_WAIT(n) asm volatile("cp.async.wait_group %0;" :: "n"(n))

// one 128x128x128 fp16 MMA pass accumulating into acc
__device__ __forceinline__ void mma_pass(uint32_t sA, uint32_t sB,
                                         int arow, int akl, int brow, int bkl,
                                         float (&acc)[2][8][4])
{
#pragma unroll
    for (int ks = 0; ks < 8; ks++) {
        const int kk = ks * 16;
        uint32_t a0[4], a1[4];
        LDSM4(a0[0], a0[1], a0[2], a0[3], sA + swz(arow,      kk + akl));
        LDSM4(a1[0], a1[1], a1[2], a1[3], sA + swz(arow + 16, kk + akl));
#pragma unroll
        for (int nb = 0; nb < 4; nb++) {
            uint32_t bh[4];
            LDSM4(bh[0], bh[1], bh[2], bh[3], sB + swz(brow + nb * 16, kk + bkl));
            int j0 = nb * 2;
            MMA16816(acc[0][j0],     a0[0], a0[1], a0[2], a0[3], bh[0], bh[1]);
            MMA16816(acc[1][j0],     a1[0], a1[1], a1[2], a1[3], bh[0], bh[1]);
            MMA16816(acc[0][j0 + 1], a0[0], a0[1], a0[2], a0[3], bh[2], bh[3]);
            MMA16816(acc[1][j0 + 1], a1[0], a1[1], a1[2], a1[3], bh[2], bh[3]);
        }
    }
}

__device__ __forceinline__ void zero_acc(float (&acc)[2][8][4]) {
#pragma unroll
    for (int i = 0; i < 2; i++)
#pragma unroll
        for (int j = 0; j < 8; j++)
#pragma unroll
            for (int q = 0; q < 4; q++) acc[i][j][q] = 0.f;
}

// stage fp32 A[rows at row0.., Kin<=128] -> fp16 swizzled smem tile
__device__ __forceinline__ void stage_A(const float* __restrict__ A, int Kin, int Mlim,
                                        int row0, char* dst, int tid)
{
    int r = tid >> 1;
    int hf = tid & 1;
    int row = row0 + r;
    bool valid = row < Mlim;
    const float* ap = A + (size_t)row * Kin;
#pragma unroll
    for (int i = 0; i < 8; i++) {
        int k0 = hf * 64 + i * 8;
        float v[8];
#pragma unroll
        for (int q = 0; q < 8; q++) {
            int k = k0 + q;
            v[q] = (valid && k < Kin) ? ap[k] : 0.f;
        }
        uint32_t p[4];
#pragma unroll
        for (int q = 0; q < 4; q++) {
            __half2 h2 = __floats2half2_rn(v[2 * q], v[2 * q + 1]);
            p[q] = *reinterpret_cast<uint32_t*>(&h2);
        }
        *reinterpret_cast<uint4*>(dst + swz(r, k0)) = make_uint4(p[0], p[1], p[2], p[3]);
    }
}

__device__ __forceinline__ void acc_row(float4& s, const char* __restrict__ p) {
    uint2 v = *reinterpret_cast<const uint2*>(p);
    float2 a = __half22float2(*reinterpret_cast<__half2*>(&v.x));
    float2 b = __half22float2(*reinterpret_cast<__half2*>(&v.y));
    s.x += a.x; s.y += a.y; s.z += b.x; s.w += b.y;
}

// ------- prep: weight tiles (incl. combined C = W_s @ Wih^T) + zeroing ------
__global__ void vspn_prep(const float* __restrict__ ggc,   // [4,128,128]
                          const float* __restrict__ wih,   // [384,128]
                          const float* __restrict__ whh,   // [384,128]
                          const float* __restrict__ wembB, // [FB,128]
                          const float* __restrict__ wembV, // [FV,128]
                          int FB, int FV)
{
    int idx = blockIdx.x * blockDim.x + threadIdx.x;
    if (idx < 2 * GG * HH) d_pool[idx] = 0.f;
    if (idx < 2 * GG) d_cnt[idx] = 0.f;
    if (idx < 2 * NN) d_ecnt[idx] = 0;
    if (idx < 2 * 16384) {
        int g = idx >> 14, off = idx & 16383;
        d_ht[(size_t)g * MT * 16384 + (size_t)(MT - 1) * 16384 + off] = __float2half(0.f);
    }
    if (idx >= 17 * 16384) return;
    int t = idx / 16384;
    int e = idx % 16384;
    int n = e >> 7;
    int k = e & 127;
    float v = 0.f;
    if (t < 12) {
        // C[s][g][k][n] = sum_c ggc[s][k][c] * wih[g*128+n][c]   (fp32, rounded once)
        int s = t / 3, g = t % 3;
        const float* wr = ggc + (size_t)(s * 128 + k) * 128;
        const float* vr = wih + (size_t)(g * 128 + n) * 128;
        float a0 = 0.f, a1 = 0.f, a2 = 0.f, a3 = 0.f;
#pragma unroll 4
        for (int c = 0; c < 128; c += 4) {
            a0 = fmaf(wr[c],     vr[c],     a0);
            a1 = fmaf(wr[c + 1], vr[c + 1], a1);
            a2 = fmaf(wr[c + 2], vr[c + 2], a2);
            a3 = fmaf(wr[c + 3], vr[c + 3], a3);
        }
        v = (a0 + a1) + (a2 + a3);
    } else if (t < 15) {
        int g = t - 12;
        v = whh[(size_t)(g * 128 + n) * 128 + k];
    } else if (t == 15) {
        v = (k < FB) ? wembB[(size_t)k * 128 + n] : 0.f;
    } else {
        v = (k < FV) ? wembV[(size_t)k * 128 + n] : 0.f;
    }
    *(__half*)(d_img + (size_t)t * TILE + swz(n, k)) = __float2half_rn(v);
}

// ---------------- CSR build (per graph; hist->scan->fill) -------------------
__global__ void k_hist(const int* __restrict__ ei, int* __restrict__ ecnt) {
    int e = blockIdx.x * blockDim.x + threadIdx.x;
    if (e < EE) atomicAdd(&ecnt[ei[EE + e]], 1);
}
__global__ void k_scan2(const int* __restrict__ ecnt,
                        int* __restrict__ eoff, int* __restrict__ ecur) {
    __shared__ int sh[512];
    int t = threadIdx.x, bid = blockIdx.x;
    int i = bid * 512 + t;
    int base = 0;
    for (int j = t; j < bid * 512; j += 512) base += ecnt[j];
    sh[t] = base;
    __syncthreads();
    for (int s = 256; s > 0; s >>= 1) {
        if (t < s) sh[t] += sh[t + s];
        __syncthreads();
    }
    base = sh[0];
    __syncthreads();
    int v = (i < NN) ? ecnt[i] : 0;
    sh[t] = v;
    __syncthreads();
    for (int off = 1; off < 512; off <<= 1) {
        int x = (t >= off) ? sh[t - off] : 0;
        __syncthreads();
        sh[t] += x;
        __syncthreads();
    }
    if (i < NN) {
        int excl = base + sh[t] - v;
        eoff[i] = excl;
        ecur[i] = excl;
        if (i == NN - 1) eoff[NN] = excl + v;
    }
}
__global__ void k_fill(const int* __restrict__ ei,
                       int* __restrict__ ecur, int* __restrict__ eidx) {
    int e = blockIdx.x * blockDim.x + threadIdx.x;
    if (e >= EE) return;
    int p = atomicAdd(&ecur[ei[EE + e]], 1);
    eidx[p] = ei[e];
}

// ---- gather: hsum tile[row] = fp16(sum CSR h-tile rows), swizzled ----------
__global__ void vspn_gather(const __half* __restrict__ ht,
                            __half* __restrict__ hsum,
                            const int* __restrict__ eoff,
                            const int* __restrict__ eidx)
{
    int w = (blockIdx.x * blockDim.x + threadIdx.x) >> 5;   // padded node index
    if (w >= NPAD) return;
    int lane = threadIdx.x & 31;
    int lane4 = lane * 4;
    const char* base = reinterpret_cast<const char*>(ht);
    float4 s0 = make_float4(0.f, 0.f, 0.f, 0.f), s1 = s0, s2 = s0, s3 = s0;
    if (w < NN) {
        int e0 = eoff[w], e1 = eoff[w + 1];
        int e = e0;
        for (; e + 4 <= e1; e += 4) {
            int p0 = eidx[e], p1 = eidx[e + 1];
            int p2 = eidx[e + 2], p3 = eidx[e + 3];
            acc_row(s0, base + (size_t)(p0 >> 7) * TILE + swz(p0 & 127, lane4));
            acc_row(s1, base + (size_t)(p1 >> 7) * TILE + swz(p1 & 127, lane4));
            acc_row(s2, base + (size_t)(p2 >> 7) * TILE + swz(p2 & 127, lane4));
            acc_row(s3, base + (size_t)(p3 >> 7) * TILE + swz(p3 & 127, lane4));
        }
        for (; e < e1; e++) {
            int p0 = eidx[e];
            acc_row(s0, base + (size_t)(p0 >> 7) * TILE + swz(p0 & 127, lane4));
        }
    }
    s0.x += s1.x + s2.x + s3.x;
    s0.y += s1.y + s2.y + s3.y;
    s0.z += s1.z + s2.z + s3.z;
    s0.w += s1.w + s2.w + s3.w;
    __half2 h0 = __floats2half2_rn(s0.x, s0.y);
    __half2 h1 = __floats2half2_rn(s0.z, s0.w);
    uint2 pk;
    pk.x = *reinterpret_cast<uint32_t*>(&h0);
    pk.y = *reinterpret_cast<uint32_t*>(&h1);
    char* dst = reinterpret_cast<char*>(hsum) + (size_t)(w >> 7) * TILE + swz(w & 127, lane4);
    *reinterpret_cast<uint2*>(dst) = pk;
}

// ---------------- embed: ht = fp16tiles(relu(x@Wemb)) -----------------------
#define SM_EMB (2 * TILE)
__global__ void __launch_bounds__(256, 1)
vspn_emb(const float* __restrict__ x, int Kin,
         const char* __restrict__ imgE,
         __half* __restrict__ ht, int M)
{
    extern __shared__ char smem[];
    const int tid = threadIdx.x, lane = tid & 31, wid = tid >> 5;
    const int wr = wid & 3, wc = wid >> 2;
    const int arow = wr * 32 + (lane & 15), akl = (lane >> 4) << 3;
    const int brow = wc * 64 + ((lane >> 4) << 3) + (lane & 7), bkl = ((lane >> 3) & 1) << 3;
    const int rl0 = wr * 32 + (lane >> 2);
    const int cb  = wc * 64 + (lane & 3) * 2;
    const int node0 = blockIdx.x * 128;
    char* httile = reinterpret_cast<char*>(ht) + (size_t)blockIdx.x * TILE;

    uint32_t sA = smem_u32(smem), sB0 = sA + TILE;
    cp_tile(sB0, imgE, tid);
    stage_A(x, Kin, M, node0, smem, tid);
    CP_WAIT(0);
    __syncthreads();

    float acc[2][8][4];
    zero_acc(acc);
    mma_pass(sA, sB0, arow, akl, brow, bkl, acc);

#pragma unroll
    for (int i = 0; i < 2; i++)
#pragma unroll
        for (int rr = 0; rr < 2; rr++) {
            int rl = rl0 + i * 16 + rr * 8;
            int node = node0 + rl;
            if (node >= M) continue;
#pragma unroll
            for (int j = 0; j < 8; j++) {
                int c = cb + j * 8;
                float v0 = fmaxf(acc[i][j][rr * 2], 0.f);
                float v1 = fmaxf(acc[i][j][rr * 2 + 1], 0.f);
                __half2 h2 = __floats2half2_rn(v0, v1);
                *reinterpret_cast<uint32_t*>(httile + swz(rl, c)) =
                    *reinterpret_cast<uint32_t*>(&h2);
            }
        }
}

// --------- fused step: GRU(ht, hsum) -> ht  (6 MMA passes, no ym) -----------
// gi_gate = hsum @ C[s][gate]  (C precomputed = W_s @ Wih^T)
// groups: g1 sAh(h), g2 sA(hsum), g3 B0=Whh_r, g4 B1=C_sr, g5 B2=Whh_n,
//         g6 B3=C_sn, g7 B4=Whh_z, g8 B0=C_sz (mid reload)
#define SM_STEP (7 * TILE)   // 224KB
__global__ void __launch_bounds__(256, 1)
vspn_step(const __half* __restrict__ hsum, __half* __restrict__ ht,
          const char* __restrict__ imgC,   // 3 tiles: C_sr | C_sz | C_sn
          const float* __restrict__ bih, const float* __restrict__ bhh)
{
    extern __shared__ char smem[];
    const int tid = threadIdx.x, lane = tid & 31, wid = tid >> 5;
    const int wr = wid & 3, wc = wid >> 2;
    const int arow = wr * 32 + (lane & 15), akl = (lane >> 4) << 3;
    const int brow = wc * 64 + ((lane >> 4) << 3) + (lane & 7), bkl = ((lane >> 3) & 1) << 3;
    const int rl0 = wr * 32 + (lane >> 2);
    const int cb  = wc * 64 + (lane & 3) * 2;
    const int node0 = blockIdx.x * 128;
    char* httile = reinterpret_cast<char*>(ht) + (size_t)blockIdx.x * TILE;

    uint32_t sA  = smem_u32(smem);
    uint32_t sAh = sA + TILE;
    uint32_t sB0 = sA + 2 * TILE;
    uint32_t sB1 = sA + 3 * TILE;
    uint32_t sB2 = sA + 4 * TILE;
    uint32_t sB3 = sA + 5 * TILE;
    uint32_t sB4 = sA + 6 * TILE;

    cp_tile(sAh, httile, tid);                                                    // g1
    cp_tile(sA, reinterpret_cast<const char*>(hsum) + (size_t)blockIdx.x * TILE, tid); // g2
    cp_tile(sB0, d_img + 12 * TILE, tid);   // g3: Whh_r
    cp_tile(sB1, imgC, tid);                // g4: C_sr
    cp_tile(sB2, d_img + 14 * TILE, tid);   // g5: Whh_n
    cp_tile(sB3, imgC + 2 * TILE, tid);     // g6: C_sn
    cp_tile(sB4, d_img + 13 * TILE, tid);   // g7: Whh_z

    float acc[2][8][4], rg[2][8][4], ng[2][8][4];

    // ---- P0: gh_r (needs g1..g3) ----
    CP_WAIT(4);
    __syncthreads();
    zero_acc(acc);
    mma_pass(sAh, sB0, arow, akl, brow, bkl, acc);
    // ---- P1: + gi_r -> r (needs g4) ; reload B0<-C_sz after sync ----
    CP_WAIT(3);
    __syncthreads();
    cp_tile(sB0, imgC + TILE, tid);         // g8: C_sz
    mma_pass(sA, sB1, arow, akl, brow, bkl, acc);
#pragma unroll
    for (int i = 0; i < 2; i++)
#pragma unroll
        for (int j = 0; j < 8; j++) {
            int c = cb + j * 8;
            float2 b1 = *reinterpret_cast<const float2*>(bih + c);
            float2 b2 = *reinterpret_cast<const float2*>(bhh + c);
#pragma unroll
            for (int rr = 0; rr < 2; rr++) {
                rg[i][j][rr * 2]     = sigm(acc[i][j][rr * 2]     + b1.x + b2.x);
                rg[i][j][rr * 2 + 1] = sigm(acc[i][j][rr * 2 + 1] + b1.y + b2.y);
            }
        }
    // ---- P2: gh_n (needs g5; pending g6,g7,g8) ----
    CP_WAIT(3);
    __syncthreads();
    zero_acc(acc);
    mma_pass(sAh, sB2, arow, akl, brow, bkl, acc);
#pragma unroll
    for (int i = 0; i < 2; i++)
#pragma unroll
        for (int j = 0; j < 8; j++) {
            int c = cb + j * 8;
            float2 b1 = *reinterpret_cast<const float2*>(bih + 256 + c);
            float2 b2 = *reinterpret_cast<const float2*>(bhh + 256 + c);
#pragma unroll
            for (int rr = 0; rr < 2; rr++) {
                acc[i][j][rr * 2]     = rg[i][j][rr * 2]     * (acc[i][j][rr * 2]     + b2.x) + b1.x;
                acc[i][j][rr * 2 + 1] = rg[i][j][rr * 2 + 1] * (acc[i][j][rr * 2 + 1] + b2.y) + b1.y;
            }
        }
    // ---- P3: + gi_n -> n (needs g6; pending g7,g8) ----
    CP_WAIT(2);
    __syncthreads();
    mma_pass(sA, sB3, arow, akl, brow, bkl, acc);
#pragma unroll
    for (int i = 0; i < 2; i++)
#pragma unroll
        for (int j = 0; j < 8; j++)
#pragma unroll
            for (int q = 0; q < 4; q++) ng[i][j][q] = tanh_ap(acc[i][j][q]);
    // ---- P4: gh_z (needs g7; pending g8) ----
    CP_WAIT(1);
    __syncthreads();
    zero_acc(acc);
    mma_pass(sAh, sB4, arow, akl, brow, bkl, acc);
    // ---- P5: + gi_z -> z (needs g8) ; combine; write ht tile ----
    CP_WAIT(0);
    __syncthreads();
    mma_pass(sA, sB0, arow, akl, brow, bkl, acc);
#pragma unroll
    for (int i = 0; i < 2; i++)
#pragma unroll
        for (int rr = 0; rr < 2; rr++) {
            int rl = rl0 + i * 16 + rr * 8;
            int node = node0 + rl;
            bool valid = node < NN;
#pragma unroll
            for (int j = 0; j < 8; j++) {
                int c = cb + j * 8;
                float2 b1 = *reinterpret_cast<const float2*>(bih + 128 + c);
                float2 b2 = *reinterpret_cast<const float2*>(bhh + 128 + c);
                float z0 = sigm(acc[i][j][rr * 2]     + b1.x + b2.x);
                float z1 = sigm(acc[i][j][rr * 2 + 1] + b1.y + b2.y);
                uint32_t hw = *reinterpret_cast<uint32_t*>(smem + TILE + swz(rl, c));
                float2 hp = __half22float2(*reinterpret_cast<__half2*>(&hw));
                float h0 = (1.f - z0) * ng[i][j][rr * 2]     + z0 * hp.x;
                float h1 = (1.f - z1) * ng[i][j][rr * 2 + 1] + z1 * hp.y;
                __half2 hh = __floats2half2_rn(h0, h1);
                if (valid)
                    *reinterpret_cast<uint32_t*>(httile + swz(rl, c)) =
                        *reinterpret_cast<uint32_t*>(&hh);
            }
        }
}

// ---------------- pool: pool[b] += relu(h[n]), cnt[b] += 1 (fp16 tiles) -----
__global__ void vspn_pool(const __half* __restrict__ ht, const int* __restrict__ batch,
                          float* __restrict__ pool, float* __restrict__ cnt, int Nn)
{
    __shared__ int sbh[128];
    int j  = threadIdx.x;
    int n0 = blockIdx.x * 128;
    int nend = min(n0 + 128, Nn);
    int cn = nend - n0;
    if (n0 + j < Nn) sbh[j] = batch[n0 + j];
    __syncthreads();
    const char* tb = reinterpret_cast<const char*>(ht) + (size_t)blockIdx.x * TILE;
    float sum = 0.f, rc = 0.f;
    int cur = sbh[0];
    for (int t = 0; t < cn; t++) {
        int b = sbh[t];
        if (b != cur) {
            atomicAdd(&pool[(size_t)cur * HH + j], sum);
            if (j == 0) atomicAdd(&cnt[cur], rc);
            sum = 0.f; rc = 0.f; cur = b;
        }
        float v = __half2float(*reinterpret_cast<const __half*>(tb + swz(t, j)));
        sum += fmaxf(v, 0.f);
        rc += 1.f;
    }
    atomicAdd(&pool[(size_t)cur * HH + j], sum);
    if (j == 0) atomicAdd(&cnt[cur], rc);
}

// ---------------- head ------------------------------------------------------
__global__ void vspn_head(const float* __restrict__ W1, const float* __restrict__ b1,
                          const float* __restrict__ W2, const float* __restrict__ b2,
                          float* __restrict__ out)
{
    int g = blockIdx.x;
    int k = threadIdx.x;
    __shared__ float gsh[256];
    __shared__ float tsh[256];
    float cb = fmaxf(d_cnt[g], 1.f);
    float cv = fmaxf(d_cnt[GG + g], 1.f);
    if (k < HH) gsh[k] = d_pool[(size_t)g * HH + k] / cb;
    else        gsh[k] = d_pool[(size_t)(GG + g) * HH + (k - HH)] / cv;
    __syncthreads();
    float acc = b1[k];
    for (int j = 0; j < 256; j++) acc += gsh[j] * W1[j * 256 + k];
    float t = fmaxf(acc, 0.f);
    tsh[k] = t * W2[k];
    __syncthreads();
    for (int s = 128; s > 0; s >>= 1) {
        if (k < s) tsh[k] += tsh[k + s];
        __syncthreads();
    }
    if (k == 0) {
        float x = tsh[0] + b2[0];
        out[g] = fmaxf(x, 0.f) + log1pf(expf(-fabsf(x)));
    }
}

// ---------------- launch ----------------------------------------------------
extern "C" void kernel_launch(void* const* d_in, const int* in_sizes, int n_in,
                              void* d_out, int out_size)
{
    const float* x_b   = (const float*)d_in[0];
    const int*   ei_b  = (const int*)  d_in[1];
    const int*   bat_b = (const int*)  d_in[2];
    const float* x_v   = (const float*)d_in[3];
    const int*   ei_v  = (const int*)  d_in[4];
    const int*   bat_v = (const int*)  d_in[5];
    const float* Wemb_b= (const float*)d_in[6];
    const float* Wemb_v= (const float*)d_in[7];
    const float* ggc   = (const float*)d_in[8];
    const float* w_ih  = (const float*)d_in[9];
    const float* w_hh  = (const float*)d_in[10];
    const float* b_ih  = (const float*)d_in[11];
    const float* b_hh  = (const float*)d_in[12];
    const float* W1    = (const float*)d_in[13];
    const float* b1    = (const float*)d_in[14];
    const float* W2    = (const float*)d_in[15];
    const float* b2    = (const float*)d_in[16];
    float* out = (float*)d_out;

    const int FB = in_sizes[0] / NN;
    const int FV = in_sizes[3] / NN;

    float *p_pool, *p_cnt;
    __half *p_ht, *p_hsum;
    char* p_img;
    int *p_ecnt, *p_ecur, *p_eoff, *p_eidx;
    cudaGetSymbolAddress((void**)&p_ht,   d_ht);
    cudaGetSymbolAddress((void**)&p_hsum, d_hsum);
    cudaGetSymbolAddress((void**)&p_img,  d_img);
    cudaGetSymbolAddress((void**)&p_pool, d_pool);
    cudaGetSymbolAddress((void**)&p_cnt,  d_cnt);
    cudaGetSymbolAddress((void**)&p_ecnt, d_ecnt);
    cudaGetSymbolAddress((void**)&p_ecur, d_ecur);
    cudaGetSymbolAddress((void**)&p_eoff, d_eoff);
    cudaGetSymbolAddress((void**)&p_eidx, d_eidx);

    // one-time host-side resources (streams/events; no device memory)
    static cudaStream_t s2 = nullptr;
    static cudaEvent_t evA = nullptr, evB = nullptr;
    if (s2 == nullptr) {
        cudaStreamCreateWithFlags(&s2, cudaStreamNonBlocking);
        cudaEventCreateWithFlags(&evA, cudaEventDisableTiming);
        cudaEventCreateWithFlags(&evB, cudaEventDisableTiming);
        cudaFuncSetAttribute(vspn_emb,  cudaFuncAttributeMaxDynamicSharedMemorySize, SM_EMB);
        cudaFuncSetAttribute(vspn_step, cudaFuncAttributeMaxDynamicSharedMemorySize, SM_STEP);
    }

    // launch 0 (stream 0): weight tiles (incl. combined C) + zeroing
    vspn_prep<<<(17 * 16384 + 255) / 256, 256>>>(ggc, w_ih, w_hh, Wemb_b, Wemb_v, FB, FV);

    // fork second stream off the capture stream
    cudaEventRecord(evA, 0);
    cudaStreamWaitEvent(s2, evA, 0);

    const int EB = (EE + 255) / 256;
    const int GB = (NPAD * 32 + 255) / 256;
    const int poolBlocks = (NN + 127) / 128;

    for (int graph = 0; graph < 2; graph++) {
        cudaStream_t st = graph ? s2 : (cudaStream_t)0;
        const float* x   = graph ? x_v   : x_b;
        const int*   ei  = graph ? ei_v  : ei_b;
        const int*   bat = graph ? bat_v : bat_b;
        const int    F   = graph ? FV    : FB;
        __half* ht   = p_ht   + (size_t)graph * MT * 16384;
        __half* hsum = p_hsum + (size_t)graph * MT * 16384;
        int* ecnt = p_ecnt + graph * NN;
        int* ecur = p_ecur + graph * NN;
        int* eoff = p_eoff + graph * (NN + 1);
        int* eidx = p_eidx + graph * EE;

        // CSR build
        k_hist<<<EB, 256, 0, st>>>(ei, ecnt);
        k_scan2<<<NB_SCAN, 512, 0, st>>>(ecnt, eoff, ecur);
        k_fill<<<EB, 256, 0, st>>>(ei, ecur, eidx);

        // embed
        vspn_emb<<<MT, 256, SM_EMB, st>>>(x, F, p_img + (size_t)(15 + graph) * TILE,
                                          ht, NN);
        // steps
        for (int s = 0; s < STEPS; s++) {
            vspn_gather<<<GB, 256, 0, st>>>(ht, hsum, eoff, eidx);
            vspn_step<<<MT, 256, SM_STEP, st>>>(hsum, ht,
                                                p_img + (size_t)s * 3 * TILE,
                                                b_ih, b_hh);
        }
        vspn_pool<<<poolBlocks, 128, 0, st>>>(ht, bat,
                                              p_pool + (size_t)graph * GG * HH,
                                              p_cnt + graph * GG, NN);
    }

    // join and run head on stream 0
    cudaEventRecord(evB, s2);
    cudaStreamWaitEvent((cudaStream_t)0, evB, 0);
    vspn_head<<<GG, 256>>>(W1, b1, W2, b2, out);
}